// round 1
// baseline (speedup 1.0000x reference)
#include <cuda_runtime.h>
#include <math.h>
#include <stdint.h>

#define B_   16384
#define D_   256
#define ML_  10
#define M2_  (B_*9)   // GRU rows actually needed (m = 1..9)

// ---------------- scratch (static __device__, no allocation) ----------------
__device__ float g_X     [(size_t)B_*512];   // [O_prev, O_t*W_t]
__device__ float g_gates [(size_t)B_*768];   // i,g,o raw
__device__ float g_OTP   [(size_t)B_*256];   // O_t'
__device__ float g_Q     [(size_t)B_*256];
__device__ float g_QK    [(size_t)B_*256];   // Q @ k_W
__device__ float g_WM    [(size_t)B_*256];   // attn-weighted memory row
__device__ float g_OUP   [(size_t)B_*256];   // O_up
__device__ float g_Zr    [(size_t)M2_*256];  // z raw
__device__ float g_Rr    [(size_t)M2_*256];  // r raw
__device__ float g_MTr   [(size_t)M2_*256];  // m_tilde raw
__device__ float g_Wigo  [768*512];          // LSTM weights, f-gate dropped
__device__ float g_bigo  [768];
__device__ float g_kWT   [256*256];          // k_W transposed

__device__ __forceinline__ float sigf(float x){ return 1.f/(1.f+expf(-x)); }

// ---------------- prep: LSTM weight repack + k_W transpose ----------------
__global__ void k_prep(const float* __restrict__ Wih, const float* __restrict__ bih,
                       const float* __restrict__ bhh, const float* __restrict__ kW)
{
    int i = blockIdx.x*blockDim.x + threadIdx.x;
    if (i < 768*512){
        int n = i >> 9, k = i & 511;
        int src = (n < 256) ? n : n + 256;      // i:0..255  g:512..767  o:768..1023
        g_Wigo[i] = Wih[src*512 + k];
        if (k == 0) g_bigo[n] = bih[src] + bhh[src];
    }
    if (i < 256*256){
        int j = i >> 8, d = i & 255;
        g_kWT[i] = kW[d*256 + j];               // g_kWT[j][d] = k_W[d][j]
    }
}

// ---------------- frame weighting: norms, W_t, x = [O_prev, O_t*W_t] ----------------
__global__ void k_frame(const float* __restrict__ O_t, const float* __restrict__ O_prev,
                        const float* __restrict__ wW, const float* __restrict__ wb,
                        float* __restrict__ out_Wt)
{
    int b = blockIdx.x, t = threadIdx.x;
    float ot = O_t[(size_t)b*256 + t];
    float op = O_prev[(size_t)b*256 + t];
    float dl = ot - op;
    float s0 = ot*ot, s1 = op*op, s2 = dl*dl, s3 = ot*op;
    #pragma unroll
    for (int off = 16; off; off >>= 1){
        s0 += __shfl_xor_sync(0xffffffffu, s0, off);
        s1 += __shfl_xor_sync(0xffffffffu, s1, off);
        s2 += __shfl_xor_sync(0xffffffffu, s2, off);
        s3 += __shfl_xor_sync(0xffffffffu, s3, off);
    }
    __shared__ float4 ws[8];
    __shared__ float4 tot;
    int w = t >> 5;
    if ((t & 31) == 0) ws[w] = make_float4(s0, s1, s2, s3);
    __syncthreads();
    if (t == 0){
        float4 r = ws[0];
        #pragma unroll
        for (int i = 1; i < 8; i++){ r.x += ws[i].x; r.y += ws[i].y; r.z += ws[i].z; r.w += ws[i].w; }
        tot = r;
    }
    __syncthreads();
    float n_t = sqrtf(tot.x), n_p = sqrtf(tot.y), rd = sqrtf(tot.z);
    float ra  = tot.w / (n_t*n_p + 1e-6f);
    float wt  = 0.5f*(tanhf(n_t*wW[t*3+0] + rd*wW[t*3+1] + ra*wW[t*3+2] + wb[t]) + 1.f);
    out_Wt[(size_t)b*256 + t] = wt;
    g_X[(size_t)b*512 + t]       = op;
    g_X[(size_t)b*512 + 256 + t] = ot * wt;
}

// ---------------- generic tiled SGEMM: C[M,N] = A[M,K] @ W[N,K]^T + bias ----------------
// AMODE 0: A is a plain [M,K] pointer
// AMODE 1: A row r -> (b=r/9, m=r%9+1): cols [0,256)=memory[b,m,:], [256,512)=O_up[b,:]
// AMODE 2: like 1 but cols [0,256) multiplied by sigmoid(rraw[r,:])
template<int AMODE>
__global__ void __launch_bounds__(256) k_gemm(
    const float* __restrict__ A,
    const float* __restrict__ memory,
    const float* __restrict__ oup,
    const float* __restrict__ rraw,
    const float* __restrict__ W,
    const float* __restrict__ bias,
    float* __restrict__ C,
    int M, int N, int K)
{
    __shared__ float As[8][128];
    __shared__ float Bs[8][128];
    const int tid = threadIdx.x;
    const int m0  = blockIdx.y * 128;
    const int n0  = blockIdx.x * 128;
    const int lr  = tid >> 1;            // 0..127
    const int lk4 = (tid & 1) << 2;      // 0 or 4
    const int ty  = tid >> 4;            // 0..15  (M dir)
    const int tx  = tid & 15;            // 0..15  (N dir)

    float acc[8][8];
    #pragma unroll
    for (int i = 0; i < 8; i++)
        #pragma unroll
        for (int j = 0; j < 8; j++) acc[i][j] = 0.f;

    const int arow = m0 + lr;
    const float* aptr = nullptr;
    size_t a_bm = 0, a_ob = 0;
    if (AMODE == 0){
        aptr = A + (size_t)arow * K;
    } else {
        int bb = arow / 9;
        int mm = arow % 9 + 1;
        a_bm = ((size_t)bb*10 + mm) * 256;
        a_ob = (size_t)bb * 256;
    }
    const float* wrow = W + (size_t)(n0 + lr) * K;

    for (int kk = 0; kk < K; kk += 8){
        const int gk = kk + lk4;
        float4 av;
        if (AMODE == 0){
            av = *reinterpret_cast<const float4*>(aptr + gk);
        } else {
            if (gk < 256){
                av = *reinterpret_cast<const float4*>(memory + a_bm + gk);
                if (AMODE == 2){
                    float4 rv = *reinterpret_cast<const float4*>(rraw + (size_t)arow*256 + gk);
                    av.x *= sigf(rv.x); av.y *= sigf(rv.y);
                    av.z *= sigf(rv.z); av.w *= sigf(rv.w);
                }
            } else {
                av = *reinterpret_cast<const float4*>(oup + a_ob + (gk - 256));
            }
        }
        float4 wv = *reinterpret_cast<const float4*>(wrow + gk);

        As[lk4+0][lr] = av.x; As[lk4+1][lr] = av.y; As[lk4+2][lr] = av.z; As[lk4+3][lr] = av.w;
        Bs[lk4+0][lr] = wv.x; Bs[lk4+1][lr] = wv.y; Bs[lk4+2][lr] = wv.z; Bs[lk4+3][lr] = wv.w;
        __syncthreads();

        #pragma unroll
        for (int k = 0; k < 8; k++){
            float a[8], bb[8];
            *reinterpret_cast<float4*>(a)    = *reinterpret_cast<const float4*>(&As[k][ty*8]);
            *reinterpret_cast<float4*>(a+4)  = *reinterpret_cast<const float4*>(&As[k][ty*8+4]);
            *reinterpret_cast<float4*>(bb)   = *reinterpret_cast<const float4*>(&Bs[k][tx*8]);
            *reinterpret_cast<float4*>(bb+4) = *reinterpret_cast<const float4*>(&Bs[k][tx*8+4]);
            #pragma unroll
            for (int i = 0; i < 8; i++)
                #pragma unroll
                for (int j = 0; j < 8; j++)
                    acc[i][j] = fmaf(a[i], bb[j], acc[i][j]);
        }
        __syncthreads();
    }

    float bv[8];
    #pragma unroll
    for (int j = 0; j < 8; j++) bv[j] = bias ? bias[n0 + tx*8 + j] : 0.f;
    #pragma unroll
    for (int i = 0; i < 8; i++){
        int row = m0 + ty*8 + i;
        float* cp = C + (size_t)row*N + n0 + tx*8;
        float4 o0 = make_float4(acc[i][0]+bv[0], acc[i][1]+bv[1], acc[i][2]+bv[2], acc[i][3]+bv[3]);
        float4 o1 = make_float4(acc[i][4]+bv[4], acc[i][5]+bv[5], acc[i][6]+bv[6], acc[i][7]+bv[7]);
        *reinterpret_cast<float4*>(cp)     = o0;
        *reinterpret_cast<float4*>(cp + 4) = o1;
    }
}

// ---------------- LSTM activations ----------------
__global__ void k_lstm_act()
{
    size_t i = (size_t)blockIdx.x*256 + threadIdx.x;   // over B*256
    size_t b = i >> 8; int d = (int)(i & 255);
    float ig = g_gates[b*768 + d];
    float gg = g_gates[b*768 + 256 + d];
    float og = g_gates[b*768 + 512 + d];
    float c  = sigf(ig) * tanhf(gg);
    g_OTP[i] = sigf(og) * tanhf(c);
}

// ---------------- attention: scores via Qk.mem, softmax, weighted memory row ----------------
__global__ void k_attn(const float* __restrict__ memory)
{
    int b = blockIdx.x, t = threadIdx.x;
    float qk = g_QK[(size_t)b*256 + t];
    const float* mb = memory + (size_t)b*ML_*256;
    float mv[ML_];
    __shared__ float sc[ML_];
    __shared__ float attn[ML_];
    if (t < ML_) sc[t] = 0.f;
    __syncthreads();
    #pragma unroll
    for (int m = 0; m < ML_; m++){
        mv[m] = mb[m*256 + t];
        float v = qk * mv[m];
        #pragma unroll
        for (int off = 16; off; off >>= 1) v += __shfl_xor_sync(0xffffffffu, v, off);
        if ((t & 31) == 0) atomicAdd(&sc[m], v);
    }
    __syncthreads();
    if (t == 0){
        float mx = -1e30f;
        #pragma unroll
        for (int m = 0; m < ML_; m++){ sc[m] *= 0.0625f; mx = fmaxf(mx, sc[m]); }
        float e[ML_], s = 0.f;
        #pragma unroll
        for (int m = 0; m < ML_; m++){ e[m] = expf(sc[m] - mx); s += e[m]; }
        float inv = 1.f / s;
        #pragma unroll
        for (int m = 0; m < ML_; m++) attn[m] = e[m] * inv;
    }
    __syncthreads();
    float wm = 0.f;
    #pragma unroll
    for (int m = 0; m < ML_; m++) wm += attn[m] * mv[m];
    g_WM[(size_t)b*256 + t] = wm;
}

// ---------------- scatter O_up to out[0], out[2], memory_new last slot ----------------
__global__ void k_scatter(float* __restrict__ out0, float* __restrict__ out_mem,
                          float* __restrict__ out2)
{
    size_t i = (size_t)blockIdx.x*256 + threadIdx.x;   // over B*256
    float v = g_OUP[i];
    out0[i] = v;
    out2[i] = v;
    size_t b = i >> 8; int d = (int)(i & 255);
    out_mem[b*(ML_*256) + 9*256 + d] = v;
}

// ---------------- GRU combine + shift ----------------
__global__ void k_final(const float* __restrict__ memory, float* __restrict__ out_mem)
{
    size_t i  = (size_t)blockIdx.x*256 + threadIdx.x;  // over M2_*256
    size_t rr = i >> 8; int d = (int)(i & 255);
    size_t b  = rr / 9; int m = (int)(rr % 9) + 1;
    float z   = sigf(g_Zr[i]);
    float mt  = tanhf(g_MTr[i]);
    float mem = memory[(b*ML_ + m)*256 + d];
    out_mem[b*(ML_*256) + (size_t)(m-1)*256 + d] = z*mem + (1.f - z)*mt;
}

// ---------------- launcher ----------------
extern "C" void kernel_launch(void* const* d_in, const int* in_sizes, int n_in,
                              void* d_out, int out_size)
{
    const float* O_t     = (const float*)d_in[0];
    const float* O_prev  = (const float*)d_in[1];
    const float* memory  = (const float*)d_in[2];
    const float* w_mlp_W = (const float*)d_in[3];
    const float* w_mlp_b = (const float*)d_in[4];
    const float* lstm_Wih= (const float*)d_in[5];
    // d_in[6] lstm_Whh unused (h0 = 0)
    const float* lstm_bih= (const float*)d_in[7];
    const float* lstm_bhh= (const float*)d_in[8];
    const float* q_W = (const float*)d_in[9];   const float* q_b = (const float*)d_in[10];
    const float* k_W = (const float*)d_in[11];  // k_b (d_in[12]) cancels in softmax
    const float* v_W = (const float*)d_in[13];  const float* v_b = (const float*)d_in[14];
    const float* z_W = (const float*)d_in[15];  const float* z_b = (const float*)d_in[16];
    const float* r_W = (const float*)d_in[17];  const float* r_b = (const float*)d_in[18];
    const float* h_W = (const float*)d_in[19];  const float* h_b = (const float*)d_in[20];

    float* out      = (float*)d_out;
    float* out0     = out;                                   // O_up            [B,D]
    float* out_mem  = out0 + (size_t)B_*D_;                  // memory_new      [B,ML,D]
    float* out2     = out_mem + (size_t)B_*ML_*D_;           // O_up (again)    [B,D]
    float* out3     = out2 + (size_t)B_*D_;                  // W_t             [B,D]

    float *pX, *pGates, *pOTP, *pQ, *pQK, *pWM, *pOUP, *pZ, *pR, *pMT, *pWigo, *pbigo, *pkWT;
    cudaGetSymbolAddress((void**)&pX,    g_X);
    cudaGetSymbolAddress((void**)&pGates,g_gates);
    cudaGetSymbolAddress((void**)&pOTP,  g_OTP);
    cudaGetSymbolAddress((void**)&pQ,    g_Q);
    cudaGetSymbolAddress((void**)&pQK,   g_QK);
    cudaGetSymbolAddress((void**)&pWM,   g_WM);
    cudaGetSymbolAddress((void**)&pOUP,  g_OUP);
    cudaGetSymbolAddress((void**)&pZ,    g_Zr);
    cudaGetSymbolAddress((void**)&pR,    g_Rr);
    cudaGetSymbolAddress((void**)&pMT,   g_MTr);
    cudaGetSymbolAddress((void**)&pWigo, g_Wigo);
    cudaGetSymbolAddress((void**)&pbigo, g_bigo);
    cudaGetSymbolAddress((void**)&pkWT,  g_kWT);

    // prep (repack LSTM weights, transpose k_W) + frame weighting
    k_prep <<<(768*512)/256, 256>>>(lstm_Wih, lstm_bih, lstm_bhh, k_W);
    k_frame<<<B_, 256>>>(O_t, O_prev, w_mlp_W, w_mlp_b, out3);

    // LSTM gates: [B,768] = g_X[B,512] @ Wigo^T
    {
        dim3 g(768/128, B_/128);
        k_gemm<0><<<g, 256>>>(pX, nullptr, nullptr, nullptr, pWigo, pbigo, pGates, B_, 768, 512);
    }
    k_lstm_act<<<B_, 256>>>();

    // Q = OTP @ q_W^T + q_b ; Qk = Q @ k_W (via transposed copy)
    {
        dim3 g(256/128, B_/128);
        k_gemm<0><<<g, 256>>>(pOTP, nullptr, nullptr, nullptr, q_W,  q_b,    pQ,  B_, 256, 256);
        k_gemm<0><<<g, 256>>>(pQ,   nullptr, nullptr, nullptr, pkWT, nullptr,pQK, B_, 256, 256);
    }

    // attention -> weighted memory row; O_up = WM @ v_W^T + v_b
    k_attn<<<B_, 256>>>(memory);
    {
        dim3 g(256/128, B_/128);
        k_gemm<0><<<g, 256>>>(pWM, nullptr, nullptr, nullptr, v_W, v_b, pOUP, B_, 256, 256);
    }
    k_scatter<<<B_, 256>>>(out0, out_mem, out2);

    // GRU (only m = 1..9 survive the shift)
    {
        dim3 g(256/128, M2_/128);
        k_gemm<1><<<g, 256>>>(nullptr, memory, pOUP, nullptr, z_W, z_b, pZ,  M2_, 256, 512);
        k_gemm<1><<<g, 256>>>(nullptr, memory, pOUP, nullptr, r_W, r_b, pR,  M2_, 256, 512);
        k_gemm<2><<<g, 256>>>(nullptr, memory, pOUP, pR,      h_W, h_b, pMT, M2_, 256, 512);
    }
    k_final<<<M2_, 256>>>(memory, out_mem);
}

// round 3
// speedup vs baseline: 1.5861x; 1.5861x over previous
#include <cuda_runtime.h>
#include <cuda_bf16.h>
#include <math.h>
#include <stdint.h>

#define B_   16384
#define D_   256
#define ML_  10
#define M2_  (B_*9)

typedef __nv_bfloat16 bf16;

// ---------------- scratch (static __device__) ----------------
__device__ __align__(256) float g_X    [(size_t)B_*512];   // [O_prev, O_t*W_t]
__device__ __align__(256) float g_gates[(size_t)B_*768];   // i,g,o raw
__device__ __align__(256) float g_OTP  [(size_t)B_*256];
__device__ __align__(256) float g_Q    [(size_t)B_*256];
__device__ __align__(256) float g_QK   [(size_t)B_*256];
__device__ __align__(256) float g_WM   [(size_t)B_*256];
__device__ __align__(256) float g_OUP  [(size_t)B_*256];
__device__ __align__(256) float g_Zr   [(size_t)M2_*512];  // z | r raw
__device__ __align__(256) float g_Hr   [(size_t)M2_*256];  // m_tilde raw
__device__ __align__(256) float g_kWT  [256*256];          // k_W transposed (fp32)

__device__ __forceinline__ float sigf(float x){ return 1.f/(1.f+expf(-x)); }

// ---------------- mma helpers (base ISA: sm_75/sm_80 features only) ----------------
__device__ __forceinline__ uint32_t smem_u32(const void* p){
    uint32_t a; asm("{ .reg .u64 t; cvta.to.shared.u64 t, %1; cvt.u32.u64 %0, t; }" : "=r"(a) : "l"(p));
    return a;
}
__device__ __forceinline__ void ldsm4(uint32_t* r, uint32_t addr){
    asm volatile("ldmatrix.sync.aligned.m8n8.x4.shared.b16 {%0,%1,%2,%3}, [%4];"
        : "=r"(r[0]),"=r"(r[1]),"=r"(r[2]),"=r"(r[3]) : "r"(addr));
}
__device__ __forceinline__ void mma16816(float* c, const uint32_t* a, const uint32_t* b){
    asm volatile("mma.sync.aligned.m16n8k16.row.col.f32.bf16.bf16.f32 "
        "{%0,%1,%2,%3}, {%4,%5,%6,%7}, {%8,%9}, {%0,%1,%2,%3};"
        : "+f"(c[0]),"+f"(c[1]),"+f"(c[2]),"+f"(c[3])
        : "r"(a[0]),"r"(a[1]),"r"(a[2]),"r"(a[3]), "r"(b[0]),"r"(b[1]));
}
__device__ __forceinline__ uint32_t packbf(bf16 a, bf16 b){
    return (uint32_t)__bfloat16_as_ushort(a) | ((uint32_t)__bfloat16_as_ushort(b) << 16);
}
__device__ __forceinline__ void cvt_split(float4 v, uint2& hi, uint2& lo){
    bf16 hx=__float2bfloat16(v.x), hy=__float2bfloat16(v.y);
    bf16 hz=__float2bfloat16(v.z), hw=__float2bfloat16(v.w);
    bf16 lx=__float2bfloat16(v.x-__bfloat162float(hx));
    bf16 ly=__float2bfloat16(v.y-__bfloat162float(hy));
    bf16 lz=__float2bfloat16(v.z-__bfloat162float(hz));
    bf16 lw=__float2bfloat16(v.w-__bfloat162float(hw));
    hi.x = packbf(hx,hy); hi.y = packbf(hz,hw);
    lo.x = packbf(lx,ly); lo.y = packbf(lz,lw);
}

// SMEM stage layout (row stride 80B; 128 rows per matrix):
//   Ahi @ 0, Alo @ 10240, Whi @ 20480, Wlo @ 30720 ; stage size 40960, x2 stages
#define STAGE_SZ 40960
#define SMEM_TOTAL (2*STAGE_SZ)

// ================== HMMA GEMM: C[M,N] = A[M,K] @ W[N,K]^T + bias ==================
// AMODE 0: A plain fp32 [M,K]
// AMODE 1: row r -> (b=r/9, m=r%9+1): k<256 = memory[b,m,k], k>=256 = oup[b,k-256]
// AMODE 2: like 1 but k<256 multiplied by sigmoid(zr_raw[r,256+k])
// WMODE 0: W plain [N,K].  WMODE 1: LSTM remap (row n -> n<256?n:n+256 of Wih)
// WMODE 2: two-pointer concat: row n<256 -> W[n], else W2[n-256]
// BMODE 0: bias1[col] (or 0 if null). BMODE 1: bih[src]+bhh[src] LSTM remap. BMODE 2: z|r concat
template<int AMODE,int WMODE,int BMODE>
__global__ void __launch_bounds__(256) k_mma(
    const float* __restrict__ A, const float* __restrict__ memory,
    const float* __restrict__ oup, const float* __restrict__ zr_raw,
    const float* __restrict__ W, const float* __restrict__ W2,
    const float* __restrict__ bias1, const float* __restrict__ bias2,
    float* __restrict__ C, int M, int N, int K)
{
    extern __shared__ char smem[];
    const int tid = threadIdx.x, lane = tid & 31, w = tid >> 5;
    const int wm = w >> 2, wn = w & 3;           // 2 x 4 warp grid
    const int m0 = blockIdx.y * 128, n0 = blockIdx.x * 128;

    float acc[4][4][4];
    #pragma unroll
    for (int i=0;i<4;i++)
        #pragma unroll
        for (int j=0;j<4;j++)
            #pragma unroll
            for (int k=0;k<4;k++) acc[i][j][k]=0.f;

    float4 av[4], wv[4];

    auto ldg = [&](int c){
        #pragma unroll
        for (int j=0;j<4;j++){
            int u = tid + j*256;
            int r = u >> 3, seg = u & 7;
            int gk = c*32 + seg*4;
            // A side
            if (AMODE == 0){
                av[j] = *reinterpret_cast<const float4*>(A + (size_t)(m0+r)*K + gk);
            } else {
                int row = m0 + r;
                int b = row/9, m = row%9 + 1;
                if (gk < 256){
                    float4 t = *reinterpret_cast<const float4*>(memory + ((size_t)b*ML_ + m)*256 + gk);
                    if (AMODE == 2){
                        float4 z = *reinterpret_cast<const float4*>(zr_raw + (size_t)row*512 + 256 + gk);
                        t.x *= sigf(z.x); t.y *= sigf(z.y); t.z *= sigf(z.z); t.w *= sigf(z.w);
                    }
                    av[j] = t;
                } else {
                    av[j] = *reinterpret_cast<const float4*>(oup + (size_t)b*256 + (gk-256));
                }
            }
            // W side
            int n = n0 + r;
            if (WMODE == 0){
                wv[j] = *reinterpret_cast<const float4*>(W + (size_t)n*K + gk);
            } else if (WMODE == 1){
                int src = (n < 256) ? n : n + 256;
                wv[j] = *reinterpret_cast<const float4*>(W + (size_t)src*K + gk);
            } else {
                const float* p = (n < 256) ? (W + (size_t)n*K) : (W2 + (size_t)(n-256)*K);
                wv[j] = *reinterpret_cast<const float4*>(p + gk);
            }
        }
    };
    auto sts = [&](char* base){
        #pragma unroll
        for (int j=0;j<4;j++){
            int u = tid + j*256;
            int r = u >> 3, seg = u & 7;
            uint32_t off = (uint32_t)(r*80 + seg*8);
            uint2 hv, lv;
            cvt_split(av[j], hv, lv);
            *reinterpret_cast<uint2*>(base + off)         = hv;
            *reinterpret_cast<uint2*>(base + 10240 + off) = lv;
            cvt_split(wv[j], hv, lv);
            *reinterpret_cast<uint2*>(base + 20480 + off) = hv;
            *reinterpret_cast<uint2*>(base + 30720 + off) = lv;
        }
    };

    const int nch = K >> 5;
    ldg(0);
    sts(smem);
    __syncthreads();

    for (int c = 0; c < nch; c++){
        int bsel = c & 1;
        if (c + 1 < nch) ldg(c + 1);

        // ---- MMA on stage bsel ----
        uint32_t sA = smem_u32(smem + bsel*STAGE_SZ);
        uint32_t sW = sA + 20480;
        #pragma unroll
        for (int kk = 0; kk < 2; kk++){
            uint32_t ah[4][4], al[4][4];
            #pragma unroll
            for (int i = 0; i < 4; i++){
                int rl = wm*64 + i*16 + (lane & 7) + ((lane & 8) ? 8 : 0);
                uint32_t col = kk*32 + ((lane & 16) ? 16 : 0);
                ldsm4(ah[i], sA + rl*80 + col);
                ldsm4(al[i], sA + 10240 + rl*80 + col);
            }
            uint32_t bh[4][2], bl[4][2];
            #pragma unroll
            for (int jp = 0; jp < 2; jp++){
                int nl = wn*32 + jp*16 + (lane & 7) + ((lane & 16) ? 8 : 0);
                uint32_t col = kk*32 + ((lane & 8) ? 16 : 0);
                uint32_t t[4];
                ldsm4(t, sW + nl*80 + col);
                bh[2*jp][0]=t[0]; bh[2*jp][1]=t[1]; bh[2*jp+1][0]=t[2]; bh[2*jp+1][1]=t[3];
                ldsm4(t, sW + 10240 + nl*80 + col);
                bl[2*jp][0]=t[0]; bl[2*jp][1]=t[1]; bl[2*jp+1][0]=t[2]; bl[2*jp+1][1]=t[3];
            }
            #pragma unroll
            for (int i=0;i<4;i++)
                #pragma unroll
                for (int j=0;j<4;j++) mma16816(acc[i][j], ah[i], bh[j]);
            #pragma unroll
            for (int i=0;i<4;i++)
                #pragma unroll
                for (int j=0;j<4;j++) mma16816(acc[i][j], ah[i], bl[j]);
            #pragma unroll
            for (int i=0;i<4;i++)
                #pragma unroll
                for (int j=0;j<4;j++) mma16816(acc[i][j], al[i], bh[j]);
        }

        if (c + 1 < nch) sts(smem + (bsel^1)*STAGE_SZ);
        __syncthreads();
    }

    // ---- epilogue: direct STG (32B contiguous per 4 lanes) ----
    #pragma unroll
    for (int j = 0; j < 4; j++){
        int col = n0 + wn*32 + j*8 + (lane & 3)*2;
        float b0 = 0.f, b1 = 0.f;
        if (BMODE == 0){
            if (bias1){ b0 = bias1[col]; b1 = bias1[col+1]; }
        } else if (BMODE == 1){
            int s0 = (col   < 256) ? col   : col+256;
            int s1 = (col+1 < 256) ? col+1 : col+257;
            b0 = bias1[s0] + bias2[s0];
            b1 = bias1[s1] + bias2[s1];
        } else {
            b0 = (col   < 256) ? bias1[col]   : bias2[col-256];
            b1 = (col+1 < 256) ? bias1[col+1] : bias2[col+1-256];
        }
        #pragma unroll
        for (int i = 0; i < 4; i++){
            int row = m0 + wm*64 + i*16 + (lane >> 2);
            float2 v0 = make_float2(acc[i][j][0]+b0, acc[i][j][1]+b1);
            float2 v1 = make_float2(acc[i][j][2]+b0, acc[i][j][3]+b1);
            *reinterpret_cast<float2*>(C + (size_t)row*N + col)     = v0;
            *reinterpret_cast<float2*>(C + (size_t)(row+8)*N + col) = v1;
        }
    }
}

// ---------------- k_W transpose (fp32) ----------------
__global__ void k_prep_kwt(const float* __restrict__ kW){
    int i = blockIdx.x*256 + threadIdx.x;
    if (i >= 65536) return;
    int j = i >> 8, d = i & 255;
    g_kWT[i] = kW[d*256 + j];
}

// ---------------- frame weighting ----------------
__global__ void k_frame(const float* __restrict__ O_t, const float* __restrict__ O_prev,
                        const float* __restrict__ wW, const float* __restrict__ wb,
                        float* __restrict__ out_Wt)
{
    int b = blockIdx.x, t = threadIdx.x;
    float ot = O_t[(size_t)b*256 + t];
    float op = O_prev[(size_t)b*256 + t];
    float dl = ot - op;
    float s0 = ot*ot, s1 = op*op, s2 = dl*dl, s3 = ot*op;
    #pragma unroll
    for (int off = 16; off; off >>= 1){
        s0 += __shfl_xor_sync(0xffffffffu, s0, off);
        s1 += __shfl_xor_sync(0xffffffffu, s1, off);
        s2 += __shfl_xor_sync(0xffffffffu, s2, off);
        s3 += __shfl_xor_sync(0xffffffffu, s3, off);
    }
    __shared__ float4 ws[8];
    __shared__ float4 tot;
    int w = t >> 5;
    if ((t & 31) == 0) ws[w] = make_float4(s0, s1, s2, s3);
    __syncthreads();
    if (t == 0){
        float4 r = ws[0];
        #pragma unroll
        for (int i = 1; i < 8; i++){ r.x += ws[i].x; r.y += ws[i].y; r.z += ws[i].z; r.w += ws[i].w; }
        tot = r;
    }
    __syncthreads();
    float n_t = sqrtf(tot.x), n_p = sqrtf(tot.y), rd = sqrtf(tot.z);
    float ra  = tot.w / (n_t*n_p + 1e-6f);
    float wt  = 0.5f*(tanhf(n_t*wW[t*3+0] + rd*wW[t*3+1] + ra*wW[t*3+2] + wb[t]) + 1.f);
    out_Wt[(size_t)b*256 + t] = wt;
    g_X[(size_t)b*512 + t]       = op;
    g_X[(size_t)b*512 + 256 + t] = ot * wt;
}

// ---------------- LSTM activations ----------------
__global__ void k_lstm_act(){
    size_t i = (size_t)blockIdx.x*256 + threadIdx.x;
    size_t b = i >> 8; int d = (int)(i & 255);
    float ig = g_gates[b*768 + d];
    float gg = g_gates[b*768 + 256 + d];
    float og = g_gates[b*768 + 512 + d];
    float c  = sigf(ig) * tanhf(gg);
    g_OTP[i] = sigf(og) * tanhf(c);
}

// ---------------- attention ----------------
__global__ void k_attn(const float* __restrict__ memory){
    int b = blockIdx.x, t = threadIdx.x;
    float qk = g_QK[(size_t)b*256 + t];
    const float* mb = memory + (size_t)b*ML_*256;
    float mv[ML_];
    __shared__ float sc[ML_];
    __shared__ float attn[ML_];
    if (t < ML_) sc[t] = 0.f;
    __syncthreads();
    #pragma unroll
    for (int m = 0; m < ML_; m++){
        mv[m] = mb[m*256 + t];
        float v = qk * mv[m];
        #pragma unroll
        for (int off = 16; off; off >>= 1) v += __shfl_xor_sync(0xffffffffu, v, off);
        if ((t & 31) == 0) atomicAdd(&sc[m], v);
    }
    __syncthreads();
    if (t == 0){
        float mx = -1e30f;
        #pragma unroll
        for (int m = 0; m < ML_; m++){ sc[m] *= 0.0625f; mx = fmaxf(mx, sc[m]); }
        float e[ML_], s = 0.f;
        #pragma unroll
        for (int m = 0; m < ML_; m++){ e[m] = expf(sc[m] - mx); s += e[m]; }
        float inv = 1.f / s;
        #pragma unroll
        for (int m = 0; m < ML_; m++) attn[m] = e[m] * inv;
    }
    __syncthreads();
    float wm = 0.f;
    #pragma unroll
    for (int m = 0; m < ML_; m++) wm += attn[m] * mv[m];
    g_WM[(size_t)b*256 + t] = wm;
}

// ---------------- scatter O_up ----------------
__global__ void k_scatter(float* __restrict__ out0, float* __restrict__ out_mem,
                          float* __restrict__ out2){
    size_t i = (size_t)blockIdx.x*256 + threadIdx.x;
    float v = g_OUP[i];
    out0[i] = v; out2[i] = v;
    size_t b = i >> 8; int d = (int)(i & 255);
    out_mem[b*(ML_*256) + 9*256 + d] = v;
}

// ---------------- GRU combine + shift ----------------
__global__ void k_final(const float* __restrict__ memory, float* __restrict__ out_mem){
    size_t i  = (size_t)blockIdx.x*256 + threadIdx.x;
    size_t rr = i >> 8; int d = (int)(i & 255);
    size_t b  = rr / 9; int m = (int)(rr % 9) + 1;
    float z   = sigf(g_Zr[rr*512 + d]);
    float mt  = tanhf(g_Hr[i]);
    float mem = memory[(b*ML_ + m)*256 + d];
    out_mem[b*(ML_*256) + (size_t)(m-1)*256 + d] = z*mem + (1.f - z)*mt;
}

// ---------------- launcher ----------------
extern "C" void kernel_launch(void* const* d_in, const int* in_sizes, int n_in,
                              void* d_out, int out_size)
{
    const float* O_t     = (const float*)d_in[0];
    const float* O_prev  = (const float*)d_in[1];
    const float* memory  = (const float*)d_in[2];
    const float* w_mlp_W = (const float*)d_in[3];
    const float* w_mlp_b = (const float*)d_in[4];
    const float* lstm_Wih= (const float*)d_in[5];
    const float* lstm_bih= (const float*)d_in[7];
    const float* lstm_bhh= (const float*)d_in[8];
    const float* q_W = (const float*)d_in[9];   const float* q_b = (const float*)d_in[10];
    const float* k_W = (const float*)d_in[11];  // k_b cancels in softmax
    const float* v_W = (const float*)d_in[13];  const float* v_b = (const float*)d_in[14];
    const float* z_W = (const float*)d_in[15];  const float* z_b = (const float*)d_in[16];
    const float* r_W = (const float*)d_in[17];  const float* r_b = (const float*)d_in[18];
    const float* h_W = (const float*)d_in[19];  const float* h_b = (const float*)d_in[20];

    float* out      = (float*)d_out;
    float* out0     = out;
    float* out_mem  = out0 + (size_t)B_*D_;
    float* out2     = out_mem + (size_t)B_*ML_*D_;
    float* out3     = out2 + (size_t)B_*D_;

    cudaFuncSetAttribute(k_mma<0,1,1>, cudaFuncAttributeMaxDynamicSharedMemorySize, SMEM_TOTAL);
    cudaFuncSetAttribute(k_mma<0,0,0>, cudaFuncAttributeMaxDynamicSharedMemorySize, SMEM_TOTAL);
    cudaFuncSetAttribute(k_mma<1,2,2>, cudaFuncAttributeMaxDynamicSharedMemorySize, SMEM_TOTAL);
    cudaFuncSetAttribute(k_mma<2,0,0>, cudaFuncAttributeMaxDynamicSharedMemorySize, SMEM_TOTAL);

    float *pX, *pGates, *pOTP, *pQ, *pQK, *pWM, *pOUP, *pZr, *pHr, *pkWT;
    cudaGetSymbolAddress((void**)&pX,    g_X);
    cudaGetSymbolAddress((void**)&pGates,g_gates);
    cudaGetSymbolAddress((void**)&pOTP,  g_OTP);
    cudaGetSymbolAddress((void**)&pQ,    g_Q);
    cudaGetSymbolAddress((void**)&pQK,   g_QK);
    cudaGetSymbolAddress((void**)&pWM,   g_WM);
    cudaGetSymbolAddress((void**)&pOUP,  g_OUP);
    cudaGetSymbolAddress((void**)&pZr,   g_Zr);
    cudaGetSymbolAddress((void**)&pHr,   g_Hr);
    cudaGetSymbolAddress((void**)&pkWT,  g_kWT);

    // prep + frame weighting
    k_prep_kwt<<<256, 256>>>(k_W);
    k_frame<<<B_, 256>>>(O_t, O_prev, w_mlp_W, w_mlp_b, out3);

    // LSTM gates: [B,768] = X[B,512] @ Wih(remap)^T + (bih+bhh)(remap)
    {
        dim3 g(6, B_/128);
        k_mma<0,1,1><<<g, 256, SMEM_TOTAL>>>(pX, nullptr, nullptr, nullptr,
                                             lstm_Wih, nullptr, lstm_bih, lstm_bhh,
                                             pGates, B_, 768, 512);
    }
    k_lstm_act<<<B_, 256>>>();

    // Q = OTP @ q_W^T + q_b ; QK = Q @ kWT^T
    {
        dim3 g(2, B_/128);
        k_mma<0,0,0><<<g, 256, SMEM_TOTAL>>>(pOTP, nullptr, nullptr, nullptr,
                                             q_W, nullptr, q_b, nullptr,
                                             pQ, B_, 256, 256);
        k_mma<0,0,0><<<g, 256, SMEM_TOTAL>>>(pQ, nullptr, nullptr, nullptr,
                                             pkWT, nullptr, nullptr, nullptr,
                                             pQK, B_, 256, 256);
    }

    // attention -> WM ; O_up = WM @ v_W^T + v_b
    k_attn<<<B_, 256>>>(memory);
    {
        dim3 g(2, B_/128);
        k_mma<0,0,0><<<g, 256, SMEM_TOTAL>>>(pWM, nullptr, nullptr, nullptr,
                                             v_W, nullptr, v_b, nullptr,
                                             pOUP, B_, 256, 256);
    }
    k_scatter<<<B_, 256>>>(out0, out_mem, out2);

    // GRU z|r: [M2,512] = [mem,O_up] @ [z_W;r_W]^T + [z_b;r_b]
    {
        dim3 g(4, M2_/128);
        k_mma<1,2,2><<<g, 256, SMEM_TOTAL>>>(nullptr, memory, pOUP, nullptr,
                                             z_W, r_W, z_b, r_b,
                                             pZr, M2_, 512, 512);
    }
    // GRU h: [M2,256] = [sig(r)*mem, O_up] @ h_W^T + h_b
    {
        dim3 g(2, M2_/128);
        k_mma<2,0,0><<<g, 256, SMEM_TOTAL>>>(nullptr, memory, pOUP, pZr,
                                             h_W, nullptr, h_b, nullptr,
                                             pHr, M2_, 256, 512);
    }
    k_final<<<M2_, 256>>>(memory, out_mem);
}

// round 4
// speedup vs baseline: 1.9781x; 1.2472x over previous
#include <cuda_runtime.h>
#include <cuda_bf16.h>
#include <math.h>
#include <stdint.h>

#define B_   16384
#define D_   256
#define ML_  10
#define M2_  (B_*9)

typedef __nv_bfloat16 bf16;

// ---------------- fp32 scratch ----------------
__device__ __align__(256) float g_gates[(size_t)B_*768];
__device__ __align__(256) float g_QK   [(size_t)B_*256];
__device__ __align__(256) float g_Zr   [(size_t)M2_*512];   // z | r raw

// ---------------- bf16 hi/lo activation scratch ----------------
__device__ __align__(256) bf16 g_Xhi [(size_t)B_*512],    g_Xlo [(size_t)B_*512];
__device__ __align__(256) bf16 g_OTPhi[(size_t)B_*256],   g_OTPlo[(size_t)B_*256];
__device__ __align__(256) bf16 g_Qhi [(size_t)B_*256],    g_Qlo [(size_t)B_*256];
__device__ __align__(256) bf16 g_WMhi[(size_t)B_*256],    g_WMlo[(size_t)B_*256];
__device__ __align__(256) bf16 g_OUPhi[(size_t)B_*256],   g_OUPlo[(size_t)B_*256];
__device__ __align__(256) bf16 g_MEMhi[(size_t)B_*ML_*256], g_MEMlo[(size_t)B_*ML_*256];
__device__ __align__(256) bf16 g_RMhi[(size_t)M2_*256],   g_RMlo[(size_t)M2_*256];

// ---------------- bf16 hi/lo weights ----------------
__device__ __align__(256) bf16 g_Wigo_hi[768*512], g_Wigo_lo[768*512];
__device__ __align__(256) bf16 g_Wq_hi [65536],    g_Wq_lo [65536];
__device__ __align__(256) bf16 g_WkT_hi[65536],    g_WkT_lo[65536];
__device__ __align__(256) bf16 g_Wv_hi [65536],    g_Wv_lo [65536];
__device__ __align__(256) bf16 g_Wzr_hi[512*512],  g_Wzr_lo[512*512];
__device__ __align__(256) bf16 g_Wh_hi [256*512],  g_Wh_lo [256*512];
__device__ __align__(256) float g_bigo[768];
__device__ __align__(256) float g_bzr [512];

__device__ __forceinline__ float sigf(float x){ return 1.f/(1.f+expf(-x)); }
__device__ __forceinline__ void splitf(float v, bf16* hi, bf16* lo){
    bf16 h = __float2bfloat16(v);
    *hi = h; *lo = __float2bfloat16(v - __bfloat162float(h));
}
__device__ __forceinline__ uint32_t packbf(bf16 a, bf16 b){
    return (uint32_t)__bfloat16_as_ushort(a) | ((uint32_t)__bfloat16_as_ushort(b) << 16);
}

// ---------------- PTX helpers (base ISA only) ----------------
__device__ __forceinline__ uint32_t smem_u32(const void* p){
    uint32_t a; asm("{ .reg .u64 t; cvta.to.shared.u64 t, %1; cvt.u32.u64 %0, t; }" : "=r"(a) : "l"(p));
    return a;
}
__device__ __forceinline__ void ldsm4(uint32_t* r, uint32_t addr){
    asm volatile("ldmatrix.sync.aligned.m8n8.x4.shared.b16 {%0,%1,%2,%3}, [%4];"
        : "=r"(r[0]),"=r"(r[1]),"=r"(r[2]),"=r"(r[3]) : "r"(addr));
}
__device__ __forceinline__ void mma16816(float* c, const uint32_t* a, const uint32_t* b){
    asm volatile("mma.sync.aligned.m16n8k16.row.col.f32.bf16.bf16.f32 "
        "{%0,%1,%2,%3}, {%4,%5,%6,%7}, {%8,%9}, {%0,%1,%2,%3};"
        : "+f"(c[0]),"+f"(c[1]),"+f"(c[2]),"+f"(c[3])
        : "r"(a[0]),"r"(a[1]),"r"(a[2]),"r"(a[3]), "r"(b[0]),"r"(b[1]));
}
__device__ __forceinline__ void cpa16(uint32_t dst, const void* src){
    asm volatile("cp.async.cg.shared.global [%0], [%1], 16;" :: "r"(dst), "l"(src));
}
#define CP_COMMIT() asm volatile("cp.async.commit_group;" ::: "memory")
#define CP_WAIT1()  asm volatile("cp.async.wait_group 1;"  ::: "memory")

// SMEM: per stage: Ahi@0 (128x80B), Alo@10240, Whi@20480 (256x80B), Wlo@40960 ; 61440 B
#define STAGE_SZ 61440
#define SMEM_TOTAL (3*STAGE_SZ)

// ================== HMMA GEMM: C[M,N] = (Ahi+Alo) @ (Whi+Wlo)^T + bias ==================
// CTA 128x256, 8 warps (2x4) of 64x64. K-chunk 32, 3-stage cp.async pipeline.
// AMODE 0: A row r -> Ahi + r*K
// AMODE 1: row r -> b=r/9, m=r%9+1: k<256 -> MEMsplit[(b*10+m)*256+k], else OUPsplit[b*256+k-256]
// AMODE 2: row r -> k<256 -> Ahi[r*256+k] (RM), else OUPsplit[b*256+k-256]
// EPI 0: fp32 C (+bias)
// EPI 1: bf16 split Chi/Clo (+bias)
// EPI 2: V-mode: O_up split + out0 + out2 + out_mem slot 9 (+bias)
// EPI 3: h-mode: mt=tanh(v+bias); z=sig(zraw); out_mem shifted = z*mem+(1-z)*mt
template<int AMODE,int EPI>
__global__ void __launch_bounds__(256,1) k_mma(
    const bf16* __restrict__ Ahi, const bf16* __restrict__ Alo,
    const bf16* __restrict__ A2hi, const bf16* __restrict__ A2lo,
    const bf16* __restrict__ Whi, const bf16* __restrict__ Wlo,
    const float* __restrict__ bias,
    float* __restrict__ C, bf16* __restrict__ Chi, bf16* __restrict__ Clo,
    float* __restrict__ out0, float* __restrict__ out_mem, float* __restrict__ out2,
    const float* __restrict__ zraw, const float* __restrict__ memory,
    int M, int N, int K)
{
    extern __shared__ char smem[];
    uint32_t sb = smem_u32(smem);
    const int tid = threadIdx.x, lane = tid & 31, w = tid >> 5;
    const int wm = w >> 2, wn = w & 3;
    const int m0 = blockIdx.y * 128, n0 = blockIdx.x * 256;
    const int nch = K >> 5;

    float acc[4][8][4];
    #pragma unroll
    for (int i=0;i<4;i++)
        #pragma unroll
        for (int j=0;j<8;j++)
            #pragma unroll
            for (int k=0;k<4;k++) acc[i][j][k]=0.f;

    auto load_chunk = [&](int c, int s){
        uint32_t st = sb + s*STAGE_SZ;
        // A: 1024 units of 16B (hi+lo)
        #pragma unroll
        for (int t=0;t<4;t++){
            int u = tid + t*256;
            int q = u & 3, row = (u>>2)&127, hl = u>>9;
            int gk = c*32 + q*8;
            const bf16* src;
            if (AMODE == 0){
                src = (hl ? Alo : Ahi) + (size_t)(m0+row)*K + gk;
            } else {
                int rr = m0 + row, b = rr/9;
                if (gk < 256){
                    if (AMODE == 1){
                        int m = rr - b*9 + 1;
                        src = (hl ? Alo : Ahi) + ((size_t)b*10 + m)*256 + gk;
                    } else {
                        src = (hl ? Alo : Ahi) + (size_t)rr*256 + gk;
                    }
                } else {
                    src = (hl ? A2lo : A2hi) + (size_t)b*256 + (gk - 256);
                }
            }
            cpa16(st + hl*10240 + row*80 + q*16, src);
        }
        // W: 2048 units
        #pragma unroll
        for (int t=0;t<8;t++){
            int u = tid + t*256;
            int q = u & 3, row = (u>>2)&255, hl = u>>10;
            int gk = c*32 + q*8;
            const bf16* src = (hl ? Wlo : Whi) + (size_t)(n0+row)*K + gk;
            cpa16(st + 20480 + hl*20480 + row*80 + q*16, src);
        }
        CP_COMMIT();
    };

    load_chunk(0, 0);
    load_chunk(1, 1);

    for (int c = 0; c < nch; c++){
        CP_WAIT1();
        __syncthreads();
        if (c + 2 < nch) load_chunk(c + 2, (c + 2) % 3);

        uint32_t sA = sb + (c % 3)*STAGE_SZ;
        uint32_t sW = sA + 20480;
        #pragma unroll
        for (int kk = 0; kk < 2; kk++){
            uint32_t ah[4][4], al[4][4];
            #pragma unroll
            for (int i = 0; i < 4; i++){
                int rl = wm*64 + i*16 + (lane & 7) + ((lane & 8) ? 8 : 0);
                uint32_t colb = kk*32 + ((lane & 16) ? 16 : 0);
                ldsm4(ah[i], sA + rl*80 + colb);
                ldsm4(al[i], sA + 10240 + rl*80 + colb);
            }
            uint32_t bh[8][2], bl[8][2];
            #pragma unroll
            for (int jp = 0; jp < 4; jp++){
                int nl = wn*64 + jp*16 + (lane & 7) + ((lane & 16) ? 8 : 0);
                uint32_t colb = kk*32 + ((lane & 8) ? 16 : 0);
                uint32_t t4[4];
                ldsm4(t4, sW + nl*80 + colb);
                bh[2*jp][0]=t4[0]; bh[2*jp][1]=t4[1]; bh[2*jp+1][0]=t4[2]; bh[2*jp+1][1]=t4[3];
                ldsm4(t4, sW + 20480 + nl*80 + colb);
                bl[2*jp][0]=t4[0]; bl[2*jp][1]=t4[1]; bl[2*jp+1][0]=t4[2]; bl[2*jp+1][1]=t4[3];
            }
            #pragma unroll
            for (int i=0;i<4;i++)
                #pragma unroll
                for (int j=0;j<8;j++) mma16816(acc[i][j], ah[i], bh[j]);
            #pragma unroll
            for (int i=0;i<4;i++)
                #pragma unroll
                for (int j=0;j<8;j++) mma16816(acc[i][j], ah[i], bl[j]);
            #pragma unroll
            for (int i=0;i<4;i++)
                #pragma unroll
                for (int j=0;j<8;j++) mma16816(acc[i][j], al[i], bh[j]);
        }
        __syncthreads();
    }

    // ---- epilogue ----
    #pragma unroll
    for (int j = 0; j < 8; j++){
        int col = n0 + wn*64 + j*8 + (lane & 3)*2;
        float b0 = bias ? bias[col] : 0.f;
        float b1 = bias ? bias[col+1] : 0.f;
        #pragma unroll
        for (int i = 0; i < 4; i++){
            int row = m0 + wm*64 + i*16 + (lane >> 2);
            #pragma unroll
            for (int h = 0; h < 2; h++){
                int rr = row + h*8;
                float v0 = acc[i][j][2*h+0] + b0;
                float v1 = acc[i][j][2*h+1] + b1;
                if (EPI == 0){
                    *reinterpret_cast<float2*>(C + (size_t)rr*N + col) = make_float2(v0, v1);
                } else if (EPI == 1){
                    bf16 h0,l0,h1,l1;
                    splitf(v0,&h0,&l0); splitf(v1,&h1,&l1);
                    size_t o = (size_t)rr*N + col;
                    *reinterpret_cast<uint32_t*>(Chi + o) = packbf(h0,h1);
                    *reinterpret_cast<uint32_t*>(Clo + o) = packbf(l0,l1);
                } else if (EPI == 2){
                    size_t o = (size_t)rr*256 + col;
                    bf16 h0,l0,h1,l1;
                    splitf(v0,&h0,&l0); splitf(v1,&h1,&l1);
                    *reinterpret_cast<uint32_t*>(Chi + o) = packbf(h0,h1);
                    *reinterpret_cast<uint32_t*>(Clo + o) = packbf(l0,l1);
                    float2 fv = make_float2(v0, v1);
                    *reinterpret_cast<float2*>(out0 + o) = fv;
                    *reinterpret_cast<float2*>(out2 + o) = fv;
                    *reinterpret_cast<float2*>(out_mem + (size_t)rr*(ML_*256) + 9*256 + col) = fv;
                } else {
                    int b = rr/9, m = rr - b*9 + 1;
                    float mt0 = tanhf(v0), mt1 = tanhf(v1);
                    float z0 = sigf(zraw[(size_t)rr*512 + col]);
                    float z1 = sigf(zraw[(size_t)rr*512 + col + 1]);
                    float2 mv = *reinterpret_cast<const float2*>(memory + ((size_t)b*ML_ + m)*256 + col);
                    float r0 = z0*mv.x + (1.f - z0)*mt0;
                    float r1 = z1*mv.y + (1.f - z1)*mt1;
                    *reinterpret_cast<float2*>(out_mem + (size_t)b*(ML_*256) + (size_t)(m-1)*256 + col) = make_float2(r0, r1);
                }
            }
        }
    }
}

// ---------------- one fused prep kernel (weights + memory split) ----------------
#define PB_WIGO 1536
#define PB_BIAS 5
#define PB_WQ   256
#define PB_WKT  256
#define PB_WV   256
#define PB_WZR  1024
#define PB_WH   512
#define PB_MEM  163840
#define PB_TOTAL (PB_WIGO+PB_BIAS+PB_WQ+PB_WKT+PB_WV+PB_WZR+PB_WH+PB_MEM)

__global__ void k_prep_all(const float* __restrict__ Wih, const float* __restrict__ bih,
                           const float* __restrict__ bhh,
                           const float* __restrict__ qW, const float* __restrict__ kW,
                           const float* __restrict__ vW,
                           const float* __restrict__ zW, const float* __restrict__ rW,
                           const float* __restrict__ hW,
                           const float* __restrict__ zb, const float* __restrict__ rb,
                           const float* __restrict__ memory)
{
    int blk = blockIdx.x;
    if (blk < PB_WIGO){
        int i = blk*256 + threadIdx.x;                     // 768*512
        int n = i >> 9, k = i & 511;
        int src = (n < 256) ? n : n + 256;
        splitf(Wih[(size_t)src*512 + k], g_Wigo_hi + i, g_Wigo_lo + i);
        return;
    } blk -= PB_WIGO;
    if (blk < PB_BIAS){
        int i = blk*256 + threadIdx.x;
        if (i < 768){
            int src = (i < 256) ? i : i + 256;
            g_bigo[i] = bih[src] + bhh[src];
        } else if (i < 1280){
            int n = i - 768;
            g_bzr[n] = (n < 256) ? zb[n] : rb[n-256];
        }
        return;
    } blk -= PB_BIAS;
    if (blk < PB_WQ){
        int i = blk*256 + threadIdx.x;
        splitf(qW[i], g_Wq_hi + i, g_Wq_lo + i);
        return;
    } blk -= PB_WQ;
    if (blk < PB_WKT){
        int i = blk*256 + threadIdx.x;                     // transposed
        int j = i >> 8, d = i & 255;
        splitf(kW[d*256 + j], g_WkT_hi + i, g_WkT_lo + i);
        return;
    } blk -= PB_WKT;
    if (blk < PB_WV){
        int i = blk*256 + threadIdx.x;
        splitf(vW[i], g_Wv_hi + i, g_Wv_lo + i);
        return;
    } blk -= PB_WV;
    if (blk < PB_WZR){
        int i = blk*256 + threadIdx.x;                     // 512*512
        int n = i >> 9, k = i & 511;
        float v = (n < 256) ? zW[(size_t)n*512 + k] : rW[(size_t)(n-256)*512 + k];
        splitf(v, g_Wzr_hi + i, g_Wzr_lo + i);
        return;
    } blk -= PB_WZR;
    if (blk < PB_WH){
        int i = blk*256 + threadIdx.x;                     // 256*512
        splitf(hW[i], g_Wh_hi + i, g_Wh_lo + i);
        return;
    } blk -= PB_WH;
    {
        size_t i = (size_t)blk*256 + threadIdx.x;          // B*ML*256
        splitf(memory[i], g_MEMhi + i, g_MEMlo + i);
    }
}

// ---------------- frame weighting ----------------
__global__ void k_frame(const float* __restrict__ O_t, const float* __restrict__ O_prev,
                        const float* __restrict__ wW, const float* __restrict__ wb,
                        float* __restrict__ out_Wt)
{
    int b = blockIdx.x, t = threadIdx.x;
    float ot = O_t[(size_t)b*256 + t];
    float op = O_prev[(size_t)b*256 + t];
    float dl = ot - op;
    float s0 = ot*ot, s1 = op*op, s2 = dl*dl, s3 = ot*op;
    #pragma unroll
    for (int off = 16; off; off >>= 1){
        s0 += __shfl_xor_sync(0xffffffffu, s0, off);
        s1 += __shfl_xor_sync(0xffffffffu, s1, off);
        s2 += __shfl_xor_sync(0xffffffffu, s2, off);
        s3 += __shfl_xor_sync(0xffffffffu, s3, off);
    }
    __shared__ float4 ws[8];
    __shared__ float4 tot;
    int w = t >> 5;
    if ((t & 31) == 0) ws[w] = make_float4(s0, s1, s2, s3);
    __syncthreads();
    if (t == 0){
        float4 r = ws[0];
        #pragma unroll
        for (int i = 1; i < 8; i++){ r.x += ws[i].x; r.y += ws[i].y; r.z += ws[i].z; r.w += ws[i].w; }
        tot = r;
    }
    __syncthreads();
    float n_t = sqrtf(tot.x), n_p = sqrtf(tot.y), rd = sqrtf(tot.z);
    float ra  = tot.w / (n_t*n_p + 1e-6f);
    float wt  = 0.5f*(tanhf(n_t*wW[t*3+0] + rd*wW[t*3+1] + ra*wW[t*3+2] + wb[t]) + 1.f);
    out_Wt[(size_t)b*256 + t] = wt;
    splitf(op,      g_Xhi + (size_t)b*512 + t,       g_Xlo + (size_t)b*512 + t);
    splitf(ot * wt, g_Xhi + (size_t)b*512 + 256 + t, g_Xlo + (size_t)b*512 + 256 + t);
}

// ---------------- LSTM activations ----------------
__global__ void k_lstm_act(){
    size_t i = (size_t)blockIdx.x*256 + threadIdx.x;
    size_t b = i >> 8; int d = (int)(i & 255);
    float ig = g_gates[b*768 + d];
    float gg = g_gates[b*768 + 256 + d];
    float og = g_gates[b*768 + 512 + d];
    float c  = sigf(ig) * tanhf(gg);
    splitf(sigf(og) * tanhf(c), g_OTPhi + i, g_OTPlo + i);
}

// ---------------- attention ----------------
__global__ void k_attn(const float* __restrict__ memory){
    int b = blockIdx.x, t = threadIdx.x;
    float qk = g_QK[(size_t)b*256 + t];
    const float* mb = memory + (size_t)b*ML_*256;
    float mv[ML_];
    __shared__ float sc[ML_];
    __shared__ float attn[ML_];
    if (t < ML_) sc[t] = 0.f;
    __syncthreads();
    #pragma unroll
    for (int m = 0; m < ML_; m++){
        mv[m] = mb[m*256 + t];
        float v = qk * mv[m];
        #pragma unroll
        for (int off = 16; off; off >>= 1) v += __shfl_xor_sync(0xffffffffu, v, off);
        if ((t & 31) == 0) atomicAdd(&sc[m], v);
    }
    __syncthreads();
    if (t == 0){
        float mx = -1e30f;
        #pragma unroll
        for (int m = 0; m < ML_; m++){ sc[m] *= 0.0625f; mx = fmaxf(mx, sc[m]); }
        float e[ML_], s = 0.f;
        #pragma unroll
        for (int m = 0; m < ML_; m++){ e[m] = expf(sc[m] - mx); s += e[m]; }
        float inv = 1.f / s;
        #pragma unroll
        for (int m = 0; m < ML_; m++) attn[m] = e[m] * inv;
    }
    __syncthreads();
    float wm = 0.f;
    #pragma unroll
    for (int m = 0; m < ML_; m++) wm += attn[m] * mv[m];
    splitf(wm, g_WMhi + (size_t)b*256 + t, g_WMlo + (size_t)b*256 + t);
}

// ---------------- build r*mem (split) for h GEMM ----------------
__global__ void k_build_rm(const float* __restrict__ memory){
    size_t i = (size_t)blockIdx.x*256 + threadIdx.x;   // over M2_*256
    size_t rr = i >> 8; int d = (int)(i & 255);
    size_t b = rr / 9; int m = (int)(rr % 9) + 1;
    float v = sigf(g_Zr[rr*512 + 256 + d]) * memory[(b*ML_ + m)*256 + d];
    splitf(v, g_RMhi + i, g_RMlo + i);
}

// ---------------- launcher ----------------
extern "C" void kernel_launch(void* const* d_in, const int* in_sizes, int n_in,
                              void* d_out, int out_size)
{
    const float* O_t     = (const float*)d_in[0];
    const float* O_prev  = (const float*)d_in[1];
    const float* memory  = (const float*)d_in[2];
    const float* w_mlp_W = (const float*)d_in[3];
    const float* w_mlp_b = (const float*)d_in[4];
    const float* lstm_Wih= (const float*)d_in[5];
    const float* lstm_bih= (const float*)d_in[7];
    const float* lstm_bhh= (const float*)d_in[8];
    const float* q_W = (const float*)d_in[9];   const float* q_b = (const float*)d_in[10];
    const float* k_W = (const float*)d_in[11];  // k_b cancels in softmax
    const float* v_W = (const float*)d_in[13];  const float* v_b = (const float*)d_in[14];
    const float* z_W = (const float*)d_in[15];  const float* z_b = (const float*)d_in[16];
    const float* r_W = (const float*)d_in[17];  const float* r_b = (const float*)d_in[18];
    const float* h_W = (const float*)d_in[19];  const float* h_b = (const float*)d_in[20];

    float* out      = (float*)d_out;
    float* out0     = out;
    float* out_mem  = out0 + (size_t)B_*D_;
    float* out2     = out_mem + (size_t)B_*ML_*D_;
    float* out3     = out2 + (size_t)B_*D_;

    cudaFuncSetAttribute(k_mma<0,0>, cudaFuncAttributeMaxDynamicSharedMemorySize, SMEM_TOTAL);
    cudaFuncSetAttribute(k_mma<0,1>, cudaFuncAttributeMaxDynamicSharedMemorySize, SMEM_TOTAL);
    cudaFuncSetAttribute(k_mma<0,2>, cudaFuncAttributeMaxDynamicSharedMemorySize, SMEM_TOTAL);
    cudaFuncSetAttribute(k_mma<1,0>, cudaFuncAttributeMaxDynamicSharedMemorySize, SMEM_TOTAL);
    cudaFuncSetAttribute(k_mma<2,3>, cudaFuncAttributeMaxDynamicSharedMemorySize, SMEM_TOTAL);

    float *pGates, *pQK, *pZr, *pbigo, *pbzr;
    cudaGetSymbolAddress((void**)&pGates, g_gates);
    cudaGetSymbolAddress((void**)&pQK,    g_QK);
    cudaGetSymbolAddress((void**)&pZr,    g_Zr);
    cudaGetSymbolAddress((void**)&pbigo,  g_bigo);
    cudaGetSymbolAddress((void**)&pbzr,   g_bzr);
    bf16 *pXhi,*pXlo,*pOTPhi,*pOTPlo,*pQhi,*pQlo,*pWMhi,*pWMlo,*pOUPhi,*pOUPlo;
    bf16 *pMEMhi,*pMEMlo,*pRMhi,*pRMlo;
    bf16 *pWigoH,*pWigoL,*pWqH,*pWqL,*pWkH,*pWkL,*pWvH,*pWvL,*pWzrH,*pWzrL,*pWhH,*pWhL;
    cudaGetSymbolAddress((void**)&pXhi, g_Xhi);     cudaGetSymbolAddress((void**)&pXlo, g_Xlo);
    cudaGetSymbolAddress((void**)&pOTPhi, g_OTPhi); cudaGetSymbolAddress((void**)&pOTPlo, g_OTPlo);
    cudaGetSymbolAddress((void**)&pQhi, g_Qhi);     cudaGetSymbolAddress((void**)&pQlo, g_Qlo);
    cudaGetSymbolAddress((void**)&pWMhi, g_WMhi);   cudaGetSymbolAddress((void**)&pWMlo, g_WMlo);
    cudaGetSymbolAddress((void**)&pOUPhi, g_OUPhi); cudaGetSymbolAddress((void**)&pOUPlo, g_OUPlo);
    cudaGetSymbolAddress((void**)&pMEMhi, g_MEMhi); cudaGetSymbolAddress((void**)&pMEMlo, g_MEMlo);
    cudaGetSymbolAddress((void**)&pRMhi, g_RMhi);   cudaGetSymbolAddress((void**)&pRMlo, g_RMlo);
    cudaGetSymbolAddress((void**)&pWigoH, g_Wigo_hi); cudaGetSymbolAddress((void**)&pWigoL, g_Wigo_lo);
    cudaGetSymbolAddress((void**)&pWqH, g_Wq_hi);     cudaGetSymbolAddress((void**)&pWqL, g_Wq_lo);
    cudaGetSymbolAddress((void**)&pWkH, g_WkT_hi);    cudaGetSymbolAddress((void**)&pWkL, g_WkT_lo);
    cudaGetSymbolAddress((void**)&pWvH, g_Wv_hi);     cudaGetSymbolAddress((void**)&pWvL, g_Wv_lo);
    cudaGetSymbolAddress((void**)&pWzrH, g_Wzr_hi);   cudaGetSymbolAddress((void**)&pWzrL, g_Wzr_lo);
    cudaGetSymbolAddress((void**)&pWhH, g_Wh_hi);     cudaGetSymbolAddress((void**)&pWhL, g_Wh_lo);

    // 1: fused prep (weights + memory split)
    k_prep_all<<<PB_TOTAL, 256>>>(lstm_Wih, lstm_bih, lstm_bhh, q_W, k_W, v_W,
                                  z_W, r_W, h_W, z_b, r_b, memory);
    // 2: frame weighting -> X split + W_t out
    k_frame<<<B_, 256>>>(O_t, O_prev, w_mlp_W, w_mlp_b, out3);
    // 3: LSTM gates [B,768]
    k_mma<0,0><<<dim3(3, B_/128), 256, SMEM_TOTAL>>>(
        pXhi, pXlo, nullptr, nullptr, pWigoH, pWigoL, pbigo,
        pGates, nullptr, nullptr, nullptr, nullptr, nullptr, nullptr, nullptr,
        B_, 768, 512);
    // 4: LSTM activations -> OTP split
    k_lstm_act<<<B_, 256>>>();
    // 5: Q [B,256] -> split
    k_mma<0,1><<<dim3(1, B_/128), 256, SMEM_TOTAL>>>(
        pOTPhi, pOTPlo, nullptr, nullptr, pWqH, pWqL, q_b,
        nullptr, pQhi, pQlo, nullptr, nullptr, nullptr, nullptr, nullptr,
        B_, 256, 256);
    // 6: QK [B,256] fp32   <-- ncu capture slot
    k_mma<0,0><<<dim3(1, B_/128), 256, SMEM_TOTAL>>>(
        pQhi, pQlo, nullptr, nullptr, pWkH, pWkL, nullptr,
        pQK, nullptr, nullptr, nullptr, nullptr, nullptr, nullptr, nullptr,
        B_, 256, 256);
    // 7: attention -> WM split
    k_attn<<<B_, 256>>>(memory);
    // 8: V [B,256] -> O_up split + out0/out2/mem slot (fused scatter)
    k_mma<0,2><<<dim3(1, B_/128), 256, SMEM_TOTAL>>>(
        pWMhi, pWMlo, nullptr, nullptr, pWvH, pWvL, v_b,
        nullptr, pOUPhi, pOUPlo, out0, out_mem, out2, nullptr, nullptr,
        B_, 256, 256);
    // 9: GRU z|r [M2,512] fp32
    k_mma<1,0><<<dim3(2, M2_/128), 256, SMEM_TOTAL>>>(
        pMEMhi, pMEMlo, pOUPhi, pOUPlo, pWzrH, pWzrL, pbzr,
        pZr, nullptr, nullptr, nullptr, nullptr, nullptr, nullptr, nullptr,
        M2_, 512, 512);
    // 10: build sig(r)*mem split
    k_build_rm<<<(int)(((size_t)M2_*256)/256), 256>>>(memory);
    // 11: GRU h [M2,256] + fused final combine/shift
    k_mma<2,3><<<dim3(1, M2_/128), 256, SMEM_TOTAL>>>(
        pRMhi, pRMlo, pOUPhi, pOUPlo, pWhH, pWhL, h_b,
        nullptr, nullptr, nullptr, nullptr, out_mem, nullptr, pZr, memory,
        M2_, 256, 512);
}

// round 5
// speedup vs baseline: 2.3006x; 1.1630x over previous
#include <cuda_runtime.h>
#include <cuda_bf16.h>
#include <math.h>
#include <stdint.h>

#define B_   16384
#define D_   256
#define ML_  10
#define M2_  (B_*9)

typedef __nv_bfloat16 bf16;

// ---------------- fp32 scratch ----------------
__device__ __align__(256) float g_gates[(size_t)B_*768];
__device__ __align__(256) float g_QK   [(size_t)B_*256];
__device__ __align__(256) float g_OZH  [(size_t)B_*768];    // O_up @ [zW|rW|hW][:,256:512]^T + bias
__device__ __align__(256) float g_Zs   [(size_t)M2_*256];   // sigmoid(z)

// ---------------- bf16 hi/lo activation scratch ----------------
__device__ __align__(256) bf16 g_Xhi [(size_t)B_*512],    g_Xlo [(size_t)B_*512];
__device__ __align__(256) bf16 g_OTPhi[(size_t)B_*256],   g_OTPlo[(size_t)B_*256];
__device__ __align__(256) bf16 g_WMhi[(size_t)B_*256],    g_WMlo[(size_t)B_*256];
__device__ __align__(256) bf16 g_OUPhi[(size_t)B_*256],   g_OUPlo[(size_t)B_*256];
__device__ __align__(256) bf16 g_MEMhi[(size_t)B_*ML_*256], g_MEMlo[(size_t)B_*ML_*256];
__device__ __align__(256) bf16 g_RMhi[(size_t)M2_*256],   g_RMlo[(size_t)M2_*256];

// ---------------- bf16 hi/lo weights ----------------
__device__ __align__(256) bf16 g_Wigo_hi[768*512], g_Wigo_lo[768*512];
__device__ __align__(256) bf16 g_Wqk_hi [65536],   g_Wqk_lo [65536];   // (q_W^T @ k_W)^T layout [j,e]
__device__ __align__(256) bf16 g_Wv_hi  [65536],   g_Wv_lo  [65536];
__device__ __align__(256) bf16 g_Wzrm_hi[512*256], g_Wzrm_lo[512*256]; // z|r weights, mem half
__device__ __align__(256) bf16 g_Whm_hi [256*256], g_Whm_lo [256*256]; // h weights, mem half
__device__ __align__(256) bf16 g_Wozh_hi[768*256], g_Wozh_lo[768*256]; // z|r|h weights, O_up half
__device__ __align__(256) float g_bigo[768];
__device__ __align__(256) float g_bozh[768];
__device__ __align__(256) float g_bqk [256];

__device__ __forceinline__ float sigf(float x){ return 1.f/(1.f+expf(-x)); }
__device__ __forceinline__ void splitf(float v, bf16* hi, bf16* lo){
    bf16 h = __float2bfloat16(v);
    *hi = h; *lo = __float2bfloat16(v - __bfloat162float(h));
}
__device__ __forceinline__ uint32_t packbf(bf16 a, bf16 b){
    return (uint32_t)__bfloat16_as_ushort(a) | ((uint32_t)__bfloat16_as_ushort(b) << 16);
}

// ---------------- PTX helpers (base ISA only) ----------------
__device__ __forceinline__ uint32_t smem_u32(const void* p){
    uint32_t a; asm("{ .reg .u64 t; cvta.to.shared.u64 t, %1; cvt.u32.u64 %0, t; }" : "=r"(a) : "l"(p));
    return a;
}
__device__ __forceinline__ void ldsm4(uint32_t* r, uint32_t addr){
    asm volatile("ldmatrix.sync.aligned.m8n8.x4.shared.b16 {%0,%1,%2,%3}, [%4];"
        : "=r"(r[0]),"=r"(r[1]),"=r"(r[2]),"=r"(r[3]) : "r"(addr));
}
__device__ __forceinline__ void mma16816(float* c, const uint32_t* a, const uint32_t* b){
    asm volatile("mma.sync.aligned.m16n8k16.row.col.f32.bf16.bf16.f32 "
        "{%0,%1,%2,%3}, {%4,%5,%6,%7}, {%8,%9}, {%0,%1,%2,%3};"
        : "+f"(c[0]),"+f"(c[1]),"+f"(c[2]),"+f"(c[3])
        : "r"(a[0]),"r"(a[1]),"r"(a[2]),"r"(a[3]), "r"(b[0]),"r"(b[1]));
}
__device__ __forceinline__ void cpa16(uint32_t dst, const void* src){
    asm volatile("cp.async.cg.shared.global [%0], [%1], 16;" :: "r"(dst), "l"(src));
}
#define CP_COMMIT() asm volatile("cp.async.commit_group;" ::: "memory")
#define CP_WAIT1()  asm volatile("cp.async.wait_group 1;"  ::: "memory")

// SMEM per stage: Ahi@0 (128x80B), Alo@10240, Whi@20480 (256x80B), Wlo@40960 ; 61440 B
#define STAGE_SZ 61440
#define SMEM_TOTAL (3*STAGE_SZ)

// ================== HMMA GEMM: C[M,N] = (Ahi+Alo) @ (Whi+Wlo)^T (3-pass) ==================
// CTA 128x256, 8 warps (2x4) of 64x64. K-chunk 32, 3-stage cp.async pipeline.
// AMODE 0: A row r -> Ahi/Alo + r*K
// AMODE 1: A row r -> b=r/9, m=r%9+1 -> Ahi/Alo (= MEM split) at ((b*10+m)*256 + k)
// EPI 0: fp32 C = v + bias[col]
// EPI 2: V-mode: v+=bias; O_up split -> Chi/Clo; v -> out0, out2, out_mem slot 9
// EPI 3: h-mode: v += ozh[b*768+512+col]; mt=tanh(v); z=zs[rr*256+col];
//        out_mem[b, m-1, col] = z*memory[b,m,col] + (1-z)*mt
// EPI 4: zr-mode: v += ozh[b*768+col]; col<256 -> zs[rr*256+col]=sig(v);
//        col>=256 -> rm=sig(v)*memory[b,m,col-256]; split -> rmhi/rmlo
template<int AMODE,int EPI>
__global__ void __launch_bounds__(256,1) k_mma(
    const bf16* __restrict__ Ahi, const bf16* __restrict__ Alo,
    const bf16* __restrict__ Whi, const bf16* __restrict__ Wlo,
    const float* __restrict__ bias,
    float* __restrict__ C, bf16* __restrict__ Chi, bf16* __restrict__ Clo,
    float* __restrict__ out0, float* __restrict__ out_mem, float* __restrict__ out2,
    const float* __restrict__ ozh, float* __restrict__ zs,
    bf16* __restrict__ rmhi, bf16* __restrict__ rmlo,
    const float* __restrict__ memory,
    int M, int N, int K)
{
    extern __shared__ char smem[];
    uint32_t sb = smem_u32(smem);
    const int tid = threadIdx.x, lane = tid & 31, w = tid >> 5;
    const int wm = w >> 2, wn = w & 3;
    const int m0 = blockIdx.y * 128, n0 = blockIdx.x * 256;
    const int nch = K >> 5;

    float acc[4][8][4];
    #pragma unroll
    for (int i=0;i<4;i++)
        #pragma unroll
        for (int j=0;j<8;j++)
            #pragma unroll
            for (int k=0;k<4;k++) acc[i][j][k]=0.f;

    auto load_chunk = [&](int c, int s){
        uint32_t st = sb + s*STAGE_SZ;
        #pragma unroll
        for (int t=0;t<4;t++){
            int u = tid + t*256;
            int q = u & 3, row = (u>>2)&127, hl = u>>9;
            int gk = c*32 + q*8;
            const bf16* src;
            if (AMODE == 0){
                src = (hl ? Alo : Ahi) + (size_t)(m0+row)*K + gk;
            } else {
                int rr = m0 + row, b = rr/9, m = rr - b*9 + 1;
                src = (hl ? Alo : Ahi) + ((size_t)b*10 + m)*256 + gk;
            }
            cpa16(st + hl*10240 + row*80 + q*16, src);
        }
        #pragma unroll
        for (int t=0;t<8;t++){
            int u = tid + t*256;
            int q = u & 3, row = (u>>2)&255, hl = u>>10;
            int gk = c*32 + q*8;
            const bf16* src = (hl ? Wlo : Whi) + (size_t)(n0+row)*K + gk;
            cpa16(st + 20480 + hl*20480 + row*80 + q*16, src);
        }
        CP_COMMIT();
    };

    load_chunk(0, 0);
    load_chunk(1, 1);

    for (int c = 0; c < nch; c++){
        CP_WAIT1();
        __syncthreads();
        if (c + 2 < nch) load_chunk(c + 2, (c + 2) % 3);

        uint32_t sA = sb + (c % 3)*STAGE_SZ;
        uint32_t sW = sA + 20480;
        #pragma unroll
        for (int kk = 0; kk < 2; kk++){
            uint32_t ah[4][4], al[4][4];
            #pragma unroll
            for (int i = 0; i < 4; i++){
                int rl = wm*64 + i*16 + (lane & 7) + ((lane & 8) ? 8 : 0);
                uint32_t colb = kk*32 + ((lane & 16) ? 16 : 0);
                ldsm4(ah[i], sA + rl*80 + colb);
                ldsm4(al[i], sA + 10240 + rl*80 + colb);
            }
            uint32_t bh[8][2], bl[8][2];
            #pragma unroll
            for (int jp = 0; jp < 4; jp++){
                int nl = wn*64 + jp*16 + (lane & 7) + ((lane & 16) ? 8 : 0);
                uint32_t colb = kk*32 + ((lane & 8) ? 16 : 0);
                uint32_t t4[4];
                ldsm4(t4, sW + nl*80 + colb);
                bh[2*jp][0]=t4[0]; bh[2*jp][1]=t4[1]; bh[2*jp+1][0]=t4[2]; bh[2*jp+1][1]=t4[3];
                ldsm4(t4, sW + 20480 + nl*80 + colb);
                bl[2*jp][0]=t4[0]; bl[2*jp][1]=t4[1]; bl[2*jp+1][0]=t4[2]; bl[2*jp+1][1]=t4[3];
            }
            #pragma unroll
            for (int i=0;i<4;i++)
                #pragma unroll
                for (int j=0;j<8;j++) mma16816(acc[i][j], ah[i], bh[j]);
            #pragma unroll
            for (int i=0;i<4;i++)
                #pragma unroll
                for (int j=0;j<8;j++) mma16816(acc[i][j], ah[i], bl[j]);
            #pragma unroll
            for (int i=0;i<4;i++)
                #pragma unroll
                for (int j=0;j<8;j++) mma16816(acc[i][j], al[i], bh[j]);
        }
        __syncthreads();
    }

    // ---- epilogue ----
    #pragma unroll
    for (int j = 0; j < 8; j++){
        int col = n0 + wn*64 + j*8 + (lane & 3)*2;
        float b0 = 0.f, b1 = 0.f;
        if (EPI == 0 || EPI == 2){
            if (bias){ b0 = bias[col]; b1 = bias[col+1]; }
        }
        #pragma unroll
        for (int i = 0; i < 4; i++){
            int row = m0 + wm*64 + i*16 + (lane >> 2);
            #pragma unroll
            for (int h = 0; h < 2; h++){
                int rr = row + h*8;
                float v0 = acc[i][j][2*h+0] + b0;
                float v1 = acc[i][j][2*h+1] + b1;
                if (EPI == 0){
                    *reinterpret_cast<float2*>(C + (size_t)rr*N + col) = make_float2(v0, v1);
                } else if (EPI == 2){
                    size_t o = (size_t)rr*256 + col;
                    bf16 h0,l0,h1,l1;
                    splitf(v0,&h0,&l0); splitf(v1,&h1,&l1);
                    *reinterpret_cast<uint32_t*>(Chi + o) = packbf(h0,h1);
                    *reinterpret_cast<uint32_t*>(Clo + o) = packbf(l0,l1);
                    float2 fv = make_float2(v0, v1);
                    *reinterpret_cast<float2*>(out0 + o) = fv;
                    *reinterpret_cast<float2*>(out2 + o) = fv;
                    *reinterpret_cast<float2*>(out_mem + (size_t)rr*(ML_*256) + 9*256 + col) = fv;
                } else if (EPI == 3){
                    int b = rr/9, m = rr - b*9 + 1;
                    float2 oz = *reinterpret_cast<const float2*>(ozh + (size_t)b*768 + 512 + col);
                    float mt0 = tanhf(v0 + oz.x), mt1 = tanhf(v1 + oz.y);
                    float2 zv = *reinterpret_cast<const float2*>(zs + (size_t)rr*256 + col);
                    float2 mv = *reinterpret_cast<const float2*>(memory + ((size_t)b*ML_ + m)*256 + col);
                    float r0 = zv.x*mv.x + (1.f - zv.x)*mt0;
                    float r1 = zv.y*mv.y + (1.f - zv.y)*mt1;
                    *reinterpret_cast<float2*>(out_mem + (size_t)b*(ML_*256) + (size_t)(m-1)*256 + col) = make_float2(r0, r1);
                } else {  // EPI 4
                    int b = rr/9, m = rr - b*9 + 1;
                    float2 oz = *reinterpret_cast<const float2*>(ozh + (size_t)b*768 + col);
                    float s0 = sigf(v0 + oz.x), s1 = sigf(v1 + oz.y);
                    if (col < 256){
                        *reinterpret_cast<float2*>(zs + (size_t)rr*256 + col) = make_float2(s0, s1);
                    } else {
                        int cc = col - 256;
                        float2 mv = *reinterpret_cast<const float2*>(memory + ((size_t)b*ML_ + m)*256 + cc);
                        float rm0 = s0*mv.x, rm1 = s1*mv.y;
                        bf16 h0,l0,h1,l1;
                        splitf(rm0,&h0,&l0); splitf(rm1,&h1,&l1);
                        size_t o = (size_t)rr*256 + cc;
                        *reinterpret_cast<uint32_t*>(rmhi + o) = packbf(h0,h1);
                        *reinterpret_cast<uint32_t*>(rmlo + o) = packbf(l0,l1);
                    }
                }
            }
        }
    }
}

// ---------------- fused prep ----------------
#define PB_WIGO 1536
#define PB_BIAS 6
#define PB_WQK  256
#define PB_WV   256
#define PB_WZRM 512
#define PB_WHM  256
#define PB_WOZH 768
#define PB_MEM  163840
#define PB_TOTAL (PB_WIGO+PB_BIAS+PB_WQK+PB_WV+PB_WZRM+PB_WHM+PB_WOZH+PB_MEM)

__global__ void k_prep_all(const float* __restrict__ Wih, const float* __restrict__ bih,
                           const float* __restrict__ bhh,
                           const float* __restrict__ qW, const float* __restrict__ kW,
                           const float* __restrict__ qb,
                           const float* __restrict__ vW,
                           const float* __restrict__ zW, const float* __restrict__ rW,
                           const float* __restrict__ hW,
                           const float* __restrict__ zb, const float* __restrict__ rb,
                           const float* __restrict__ hb,
                           const float* __restrict__ memory)
{
    int blk = blockIdx.x;
    if (blk < PB_WIGO){
        int i = blk*256 + threadIdx.x;
        int n = i >> 9, k = i & 511;
        int src = (n < 256) ? n : n + 256;
        splitf(Wih[(size_t)src*512 + k], g_Wigo_hi + i, g_Wigo_lo + i);
        return;
    } blk -= PB_WIGO;
    if (blk < PB_BIAS){
        int i = blk*256 + threadIdx.x;
        if (i < 768){
            int src = (i < 256) ? i : i + 256;
            g_bigo[i] = bih[src] + bhh[src];
        } else {
            int n = i - 768;
            g_bozh[n] = (n < 256) ? zb[n] : (n < 512) ? rb[n-256] : hb[n-512];
        }
        return;
    } blk -= PB_BIAS;
    if (blk < PB_WQK){
        // block j, thread e: Wqk[j,e] = sum_d qW[d,e]*kW[d,j]
        int j = blk, e = threadIdx.x;
        float s = 0.f;
        for (int d = 0; d < 256; d++) s = fmaf(qW[d*256 + e], kW[d*256 + j], s);
        splitf(s, g_Wqk_hi + j*256 + e, g_Wqk_lo + j*256 + e);
        if (e == 0){
            float bq = 0.f;
            for (int d = 0; d < 256; d++) bq = fmaf(qb[d], kW[d*256 + j], bq);
            g_bqk[j] = bq;
        }
        return;
    } blk -= PB_WQK;
    if (blk < PB_WV){
        int i = blk*256 + threadIdx.x;
        splitf(vW[i], g_Wv_hi + i, g_Wv_lo + i);
        return;
    } blk -= PB_WV;
    if (blk < PB_WZRM){
        int i = blk*256 + threadIdx.x;        // 512 x 256
        int n = i >> 8, k = i & 255;
        float v = (n < 256) ? zW[(size_t)n*512 + k] : rW[(size_t)(n-256)*512 + k];
        splitf(v, g_Wzrm_hi + i, g_Wzrm_lo + i);
        return;
    } blk -= PB_WZRM;
    if (blk < PB_WHM){
        int i = blk*256 + threadIdx.x;        // 256 x 256
        int n = i >> 8, k = i & 255;
        splitf(hW[(size_t)n*512 + k], g_Whm_hi + i, g_Whm_lo + i);
        return;
    } blk -= PB_WHM;
    if (blk < PB_WOZH){
        int i = blk*256 + threadIdx.x;        // 768 x 256
        int n = i >> 8, k = i & 255;
        float v = (n < 256) ? zW[(size_t)n*512 + 256 + k]
                : (n < 512) ? rW[(size_t)(n-256)*512 + 256 + k]
                            : hW[(size_t)(n-512)*512 + 256 + k];
        splitf(v, g_Wozh_hi + i, g_Wozh_lo + i);
        return;
    } blk -= PB_WOZH;
    {
        size_t i = (size_t)blk*256 + threadIdx.x;
        splitf(memory[i], g_MEMhi + i, g_MEMlo + i);
    }
}

// ---------------- frame weighting ----------------
__global__ void k_frame(const float* __restrict__ O_t, const float* __restrict__ O_prev,
                        const float* __restrict__ wW, const float* __restrict__ wb,
                        float* __restrict__ out_Wt)
{
    int b = blockIdx.x, t = threadIdx.x;
    float ot = O_t[(size_t)b*256 + t];
    float op = O_prev[(size_t)b*256 + t];
    float dl = ot - op;
    float s0 = ot*ot, s1 = op*op, s2 = dl*dl, s3 = ot*op;
    #pragma unroll
    for (int off = 16; off; off >>= 1){
        s0 += __shfl_xor_sync(0xffffffffu, s0, off);
        s1 += __shfl_xor_sync(0xffffffffu, s1, off);
        s2 += __shfl_xor_sync(0xffffffffu, s2, off);
        s3 += __shfl_xor_sync(0xffffffffu, s3, off);
    }
    __shared__ float4 ws[8];
    __shared__ float4 tot;
    int w = t >> 5;
    if ((t & 31) == 0) ws[w] = make_float4(s0, s1, s2, s3);
    __syncthreads();
    if (t == 0){
        float4 r = ws[0];
        #pragma unroll
        for (int i = 1; i < 8; i++){ r.x += ws[i].x; r.y += ws[i].y; r.z += ws[i].z; r.w += ws[i].w; }
        tot = r;
    }
    __syncthreads();
    float n_t = sqrtf(tot.x), n_p = sqrtf(tot.y), rd = sqrtf(tot.z);
    float ra  = tot.w / (n_t*n_p + 1e-6f);
    float wt  = 0.5f*(tanhf(n_t*wW[t*3+0] + rd*wW[t*3+1] + ra*wW[t*3+2] + wb[t]) + 1.f);
    out_Wt[(size_t)b*256 + t] = wt;
    splitf(op,      g_Xhi + (size_t)b*512 + t,       g_Xlo + (size_t)b*512 + t);
    splitf(ot * wt, g_Xhi + (size_t)b*512 + 256 + t, g_Xlo + (size_t)b*512 + 256 + t);
}

// ---------------- LSTM activations ----------------
__global__ void k_lstm_act(){
    size_t i = (size_t)blockIdx.x*256 + threadIdx.x;
    size_t b = i >> 8; int d = (int)(i & 255);
    float ig = g_gates[b*768 + d];
    float gg = g_gates[b*768 + 256 + d];
    float og = g_gates[b*768 + 512 + d];
    float c  = sigf(ig) * tanhf(gg);
    splitf(sigf(og) * tanhf(c), g_OTPhi + i, g_OTPlo + i);
}

// ---------------- attention ----------------
__global__ void k_attn(const float* __restrict__ memory){
    int b = blockIdx.x, t = threadIdx.x;
    float qk = g_QK[(size_t)b*256 + t];
    const float* mb = memory + (size_t)b*ML_*256;
    float mv[ML_];
    __shared__ float sc[ML_];
    __shared__ float attn[ML_];
    if (t < ML_) sc[t] = 0.f;
    __syncthreads();
    #pragma unroll
    for (int m = 0; m < ML_; m++){
        mv[m] = mb[m*256 + t];
        float v = qk * mv[m];
        #pragma unroll
        for (int off = 16; off; off >>= 1) v += __shfl_xor_sync(0xffffffffu, v, off);
        if ((t & 31) == 0) atomicAdd(&sc[m], v);
    }
    __syncthreads();
    if (t == 0){
        float mx = -1e30f;
        #pragma unroll
        for (int m = 0; m < ML_; m++){ sc[m] *= 0.0625f; mx = fmaxf(mx, sc[m]); }
        float e[ML_], s = 0.f;
        #pragma unroll
        for (int m = 0; m < ML_; m++){ e[m] = expf(sc[m] - mx); s += e[m]; }
        float inv = 1.f / s;
        #pragma unroll
        for (int m = 0; m < ML_; m++) attn[m] = e[m] * inv;
    }
    __syncthreads();
    float wm = 0.f;
    #pragma unroll
    for (int m = 0; m < ML_; m++) wm += attn[m] * mv[m];
    splitf(wm, g_WMhi + (size_t)b*256 + t, g_WMlo + (size_t)b*256 + t);
}

// ---------------- launcher ----------------
extern "C" void kernel_launch(void* const* d_in, const int* in_sizes, int n_in,
                              void* d_out, int out_size)
{
    const float* O_t     = (const float*)d_in[0];
    const float* O_prev  = (const float*)d_in[1];
    const float* memory  = (const float*)d_in[2];
    const float* w_mlp_W = (const float*)d_in[3];
    const float* w_mlp_b = (const float*)d_in[4];
    const float* lstm_Wih= (const float*)d_in[5];
    const float* lstm_bih= (const float*)d_in[7];
    const float* lstm_bhh= (const float*)d_in[8];
    const float* q_W = (const float*)d_in[9];   const float* q_b = (const float*)d_in[10];
    const float* k_W = (const float*)d_in[11];  // k_b cancels in softmax
    const float* v_W = (const float*)d_in[13];  const float* v_b = (const float*)d_in[14];
    const float* z_W = (const float*)d_in[15];  const float* z_b = (const float*)d_in[16];
    const float* r_W = (const float*)d_in[17];  const float* r_b = (const float*)d_in[18];
    const float* h_W = (const float*)d_in[19];  const float* h_b = (const float*)d_in[20];

    float* out      = (float*)d_out;
    float* out0     = out;
    float* out_mem  = out0 + (size_t)B_*D_;
    float* out2     = out_mem + (size_t)B_*ML_*D_;
    float* out3     = out2 + (size_t)B_*D_;

    cudaFuncSetAttribute(k_mma<0,0>, cudaFuncAttributeMaxDynamicSharedMemorySize, SMEM_TOTAL);
    cudaFuncSetAttribute(k_mma<0,2>, cudaFuncAttributeMaxDynamicSharedMemorySize, SMEM_TOTAL);
    cudaFuncSetAttribute(k_mma<1,4>, cudaFuncAttributeMaxDynamicSharedMemorySize, SMEM_TOTAL);
    cudaFuncSetAttribute(k_mma<0,3>, cudaFuncAttributeMaxDynamicSharedMemorySize, SMEM_TOTAL);

    float *pGates,*pQK,*pOZH,*pZs,*pbigo,*pbozh,*pbqk;
    cudaGetSymbolAddress((void**)&pGates, g_gates);
    cudaGetSymbolAddress((void**)&pQK,    g_QK);
    cudaGetSymbolAddress((void**)&pOZH,   g_OZH);
    cudaGetSymbolAddress((void**)&pZs,    g_Zs);
    cudaGetSymbolAddress((void**)&pbigo,  g_bigo);
    cudaGetSymbolAddress((void**)&pbozh,  g_bozh);
    cudaGetSymbolAddress((void**)&pbqk,   g_bqk);
    bf16 *pXhi,*pXlo,*pOTPhi,*pOTPlo,*pWMhi,*pWMlo,*pOUPhi,*pOUPlo,*pMEMhi,*pMEMlo,*pRMhi,*pRMlo;
    bf16 *pWigoH,*pWigoL,*pWqkH,*pWqkL,*pWvH,*pWvL,*pWzrmH,*pWzrmL,*pWhmH,*pWhmL,*pWozhH,*pWozhL;
    cudaGetSymbolAddress((void**)&pXhi, g_Xhi);     cudaGetSymbolAddress((void**)&pXlo, g_Xlo);
    cudaGetSymbolAddress((void**)&pOTPhi, g_OTPhi); cudaGetSymbolAddress((void**)&pOTPlo, g_OTPlo);
    cudaGetSymbolAddress((void**)&pWMhi, g_WMhi);   cudaGetSymbolAddress((void**)&pWMlo, g_WMlo);
    cudaGetSymbolAddress((void**)&pOUPhi, g_OUPhi); cudaGetSymbolAddress((void**)&pOUPlo, g_OUPlo);
    cudaGetSymbolAddress((void**)&pMEMhi, g_MEMhi); cudaGetSymbolAddress((void**)&pMEMlo, g_MEMlo);
    cudaGetSymbolAddress((void**)&pRMhi, g_RMhi);   cudaGetSymbolAddress((void**)&pRMlo, g_RMlo);
    cudaGetSymbolAddress((void**)&pWigoH, g_Wigo_hi); cudaGetSymbolAddress((void**)&pWigoL, g_Wigo_lo);
    cudaGetSymbolAddress((void**)&pWqkH, g_Wqk_hi);   cudaGetSymbolAddress((void**)&pWqkL, g_Wqk_lo);
    cudaGetSymbolAddress((void**)&pWvH, g_Wv_hi);     cudaGetSymbolAddress((void**)&pWvL, g_Wv_lo);
    cudaGetSymbolAddress((void**)&pWzrmH, g_Wzrm_hi); cudaGetSymbolAddress((void**)&pWzrmL, g_Wzrm_lo);
    cudaGetSymbolAddress((void**)&pWhmH, g_Whm_hi);   cudaGetSymbolAddress((void**)&pWhmL, g_Whm_lo);
    cudaGetSymbolAddress((void**)&pWozhH, g_Wozh_hi); cudaGetSymbolAddress((void**)&pWozhL, g_Wozh_lo);

    // 1: fused prep (weights, Wqk=q_W^T@k_W, memory split)
    k_prep_all<<<PB_TOTAL, 256>>>(lstm_Wih, lstm_bih, lstm_bhh, q_W, k_W, q_b,
                                  v_W, z_W, r_W, h_W, z_b, r_b, h_b, memory);
    // 2: frame weighting -> X split + W_t out
    k_frame<<<B_, 256>>>(O_t, O_prev, w_mlp_W, w_mlp_b, out3);
    // 3: LSTM gates [B,768], K=512
    k_mma<0,0><<<dim3(3, B_/128), 256, SMEM_TOTAL>>>(
        pXhi, pXlo, pWigoH, pWigoL, pbigo,
        pGates, nullptr, nullptr, nullptr, nullptr, nullptr,
        nullptr, nullptr, nullptr, nullptr, nullptr, B_, 768, 512);
    // 4: LSTM activations -> OTP split
    k_lstm_act<<<B_, 256>>>();
    // 5: QK = OTP @ Wqk^T + bqk  [B,256], K=256 (Q GEMM folded in)
    k_mma<0,0><<<dim3(1, B_/128), 256, SMEM_TOTAL>>>(
        pOTPhi, pOTPlo, pWqkH, pWqkL, pbqk,
        pQK, nullptr, nullptr, nullptr, nullptr, nullptr,
        nullptr, nullptr, nullptr, nullptr, nullptr, B_, 256, 256);
    // 6: attention -> WM split
    k_attn<<<B_, 256>>>(memory);
    // 7: V GEMM -> O_up split + out0/out2/mem slot 9
    k_mma<0,2><<<dim3(1, B_/128), 256, SMEM_TOTAL>>>(
        pWMhi, pWMlo, pWvH, pWvL, v_b,
        nullptr, pOUPhi, pOUPlo, out0, out_mem, out2,
        nullptr, nullptr, nullptr, nullptr, nullptr, B_, 256, 256);
    // 8: OZH = O_up @ [zW|rW|hW][:,256:512]^T + [zb|rb|hb]  [B,768], K=256
    k_mma<0,0><<<dim3(3, B_/128), 256, SMEM_TOTAL>>>(
        pOUPhi, pOUPlo, pWozhH, pWozhL, pbozh,
        pOZH, nullptr, nullptr, nullptr, nullptr, nullptr,
        nullptr, nullptr, nullptr, nullptr, nullptr, B_, 768, 256);
    // 9: zr GEMM (mem half) [M2,512], K=256; epi adds OZH, writes Zs + RM split
    k_mma<1,4><<<dim3(2, M2_/128), 256, SMEM_TOTAL>>>(
        pMEMhi, pMEMlo, pWzrmH, pWzrmL, nullptr,
        nullptr, nullptr, nullptr, nullptr, nullptr, nullptr,
        pOZH, pZs, pRMhi, pRMlo, memory, M2_, 512, 256);
    // 10: h GEMM (rm half) [M2,256], K=256; epi adds OZH, tanh, z-combine, shifted write
    k_mma<0,3><<<dim3(1, M2_/128), 256, SMEM_TOTAL>>>(
        pRMhi, pRMlo, pWhmH, pWhmL, nullptr,
        nullptr, nullptr, nullptr, nullptr, out_mem, nullptr,
        pOZH, pZs, nullptr, nullptr, memory, M2_, 256, 256);
}

// round 6
// speedup vs baseline: 3.0274x; 1.3159x over previous
#include <cuda_runtime.h>
#include <math.h>
#include <stdint.h>

#define B_   16384
#define D_   256
#define ML_  10
#define M2_  (B_*9)

// ---------------- fp32 scratch ----------------
__device__ __align__(256) float g_X    [(size_t)B_*512];   // [O_prev, O_t*W_t]
__device__ __align__(256) float g_gates[(size_t)B_*768];
__device__ __align__(256) float g_OTP  [(size_t)B_*256];
__device__ __align__(256) float g_QK   [(size_t)B_*256];
__device__ __align__(256) float g_WM   [(size_t)B_*256];
__device__ __align__(256) float g_OUP  [(size_t)B_*256];
__device__ __align__(256) float g_OZH  [(size_t)B_*768];   // O_up @ [zW|rW|hW][:,256:512]^T + bias
__device__ __align__(256) float g_Zs   [(size_t)M2_*256];  // sigmoid(z)
__device__ __align__(256) float g_RM   [(size_t)M2_*256];  // sigmoid(r)*mem
__device__ __align__(256) float g_Wqk  [65536];            // (q_W^T @ k_W)^T, [j,e]
__device__ __align__(256) float g_bigo [768];
__device__ __align__(256) float g_bozh [768];
__device__ __align__(256) float g_bqk  [256];

__device__ __forceinline__ float sigf(float x){ return 1.f/(1.f+expf(-x)); }

// ---------------- PTX helpers (base ISA only) ----------------
__device__ __forceinline__ uint32_t smem_u32(const void* p){
    uint32_t a; asm("{ .reg .u64 t; cvta.to.shared.u64 t, %1; cvt.u32.u64 %0, t; }" : "=r"(a) : "l"(p));
    return a;
}
__device__ __forceinline__ uint32_t lds_cvt(uint32_t addr){
    float f; uint32_t y;
    asm volatile("ld.shared.f32 %0, [%1];" : "=f"(f) : "r"(addr));
    asm("cvt.rna.tf32.f32 %0, %1;" : "=r"(y) : "f"(f));
    return y;
}
__device__ __forceinline__ void mma_tf32(float* c, const uint32_t* a, const uint32_t* b){
    asm volatile("mma.sync.aligned.m16n8k8.row.col.f32.tf32.tf32.f32 "
        "{%0,%1,%2,%3}, {%4,%5,%6,%7}, {%8,%9}, {%0,%1,%2,%3};"
        : "+f"(c[0]),"+f"(c[1]),"+f"(c[2]),"+f"(c[3])
        : "r"(a[0]),"r"(a[1]),"r"(a[2]),"r"(a[3]), "r"(b[0]),"r"(b[1]));
}
__device__ __forceinline__ void cpa16(uint32_t dst, const void* src){
    asm volatile("cp.async.cg.shared.global [%0], [%1], 16;" :: "r"(dst), "l"(src));
}
#define CP_COMMIT() asm volatile("cp.async.commit_group;" ::: "memory")
#define CP_WAIT1()  asm volatile("cp.async.wait_group 1;"  ::: "memory")

// SMEM per stage: A 128 rows x 80B = 10240; W 256 rows x 80B = 20480 ; stage 30720, 3 stages
#define STAGE_SZ 30720
#define SMEM_TOTAL (3*STAGE_SZ)

// ================== tf32 HMMA GEMM: C[M,N] = A[M,K] @ W[N,K]^T (1-pass) ==================
// CTA 128x256, 8 warps (2x4), warp tile 64x64, K-chunk 16, 3-stage cp.async pipeline.
// AMODE 0: A row r -> A + (m0+r)*K
// AMODE 1: A row r -> b=r/9, m=r%9+1 -> memory + (b*10+m)*256   (Amem arg)
// WMODE 0: W + row*ws + gk
// WMODE 1: LSTM remap: src=(row<256?row:row+256); Wih + src*512 + gk
// WMODE 2: z|r concat: row<256 -> W+row*512+gk else W2+(row-256)*512+gk
// WMODE 3: ozh: 3-way concat (W,W2,W3), row-blocks of 256, col offset +256
// EPI 0: C = v + bias[col]
// EPI 2: V-mode: v+=bias; v -> C(=OUP), out0, out2, out_mem slot 9
// EPI 3: h-mode: v += ozh[b*768+512+col]; mt=tanh(v); z=zs;
//        out_mem[b,m-1,col] = z*memory[b,m,col] + (1-z)*mt
// EPI 4: zr-mode: v += ozh[b*768+col]; col<256 -> zs=sig(v); else rm=sig(v)*mem
template<int AMODE,int WMODE,int EPI>
__global__ void __launch_bounds__(256,1) k_mma(
    const float* __restrict__ A, const float* __restrict__ Amem,
    const float* __restrict__ W, const float* __restrict__ W2, const float* __restrict__ W3,
    int ws,
    const float* __restrict__ bias,
    float* __restrict__ C,
    float* __restrict__ out0, float* __restrict__ out_mem, float* __restrict__ out2,
    const float* __restrict__ ozh, float* __restrict__ zs, float* __restrict__ rm,
    const float* __restrict__ memory,
    int M, int N, int K)
{
    extern __shared__ char smem[];
    uint32_t sb = smem_u32(smem);
    const int tid = threadIdx.x, lane = tid & 31, w = tid >> 5;
    const int wm = w >> 2, wn = w & 3;
    const int m0 = blockIdx.y * 128, n0 = blockIdx.x * 256;
    const int nch = K >> 4;

    float acc[4][8][4];
    #pragma unroll
    for (int i=0;i<4;i++)
        #pragma unroll
        for (int j=0;j<8;j++)
            #pragma unroll
            for (int k=0;k<4;k++) acc[i][j][k]=0.f;

    auto aptr = [&](int row, int gk)->const float*{
        if (AMODE == 0) return A + (size_t)(m0+row)*K + gk;
        int rr = m0 + row, b = rr/9, m = rr - b*9 + 1;
        return Amem + ((size_t)b*10 + m)*256 + gk;
    };
    auto wptr = [&](int row, int gk)->const float*{
        if (WMODE == 0) return W + (size_t)row*ws + gk;
        if (WMODE == 1){ int s = (row<256)?row:row+256; return W + (size_t)s*512 + gk; }
        if (WMODE == 2) return (row<256) ? W + (size_t)row*512 + gk
                                         : W2 + (size_t)(row-256)*512 + gk;
        return (row<256) ? W  + (size_t)row*512 + 256 + gk
             : (row<512) ? W2 + (size_t)(row-256)*512 + 256 + gk
                         : W3 + (size_t)(row-512)*512 + 256 + gk;
    };
    auto load_chunk = [&](int c, int s){
        uint32_t st = sb + s*STAGE_SZ;
        #pragma unroll
        for (int t=0;t<2;t++){
            int u = tid + t*256;
            int row = u >> 2, q = u & 3;
            cpa16(st + row*80 + q*16, aptr(row, c*16 + q*4));
        }
        #pragma unroll
        for (int t=0;t<4;t++){
            int u = tid + t*256;
            int row = u >> 2, q = u & 3;
            cpa16(st + 10240 + row*80 + q*16, wptr(n0 + row, c*16 + q*4));
        }
        CP_COMMIT();
    };

    load_chunk(0, 0);
    load_chunk(1, 1);

    for (int c = 0; c < nch; c++){
        CP_WAIT1();
        __syncthreads();
        if (c + 2 < nch) load_chunk(c + 2, (c + 2) % 3);

        uint32_t sA = sb + (c % 3)*STAGE_SZ;
        uint32_t sW = sA + 10240;
        #pragma unroll
        for (int kk = 0; kk < 2; kk++){
            uint32_t a[4][4];
            #pragma unroll
            for (int i = 0; i < 4; i++){
                int r0 = wm*64 + i*16 + (lane >> 2);
                uint32_t base = sA + r0*80 + (kk*8 + (lane & 3))*4;
                a[i][0] = lds_cvt(base);
                a[i][1] = lds_cvt(base + 8*80);
                a[i][2] = lds_cvt(base + 16);
                a[i][3] = lds_cvt(base + 8*80 + 16);
            }
            uint32_t bf[8][2];
            #pragma unroll
            for (int j = 0; j < 8; j++){
                int nl = wn*64 + j*8 + (lane >> 2);
                uint32_t base = sW + nl*80 + (kk*8 + (lane & 3))*4;
                bf[j][0] = lds_cvt(base);
                bf[j][1] = lds_cvt(base + 16);
            }
            #pragma unroll
            for (int i=0;i<4;i++)
                #pragma unroll
                for (int j=0;j<8;j++) mma_tf32(acc[i][j], a[i], bf[j]);
        }
        __syncthreads();
    }

    // ---- epilogue ----
    #pragma unroll
    for (int j = 0; j < 8; j++){
        int col = n0 + wn*64 + j*8 + (lane & 3)*2;
        float b0 = 0.f, b1 = 0.f;
        if (EPI == 0 || EPI == 2){
            if (bias){ b0 = bias[col]; b1 = bias[col+1]; }
        }
        #pragma unroll
        for (int i = 0; i < 4; i++){
            int row = m0 + wm*64 + i*16 + (lane >> 2);
            #pragma unroll
            for (int h = 0; h < 2; h++){
                int rr = row + h*8;
                float v0 = acc[i][j][2*h+0] + b0;
                float v1 = acc[i][j][2*h+1] + b1;
                if (EPI == 0){
                    *reinterpret_cast<float2*>(C + (size_t)rr*N + col) = make_float2(v0, v1);
                } else if (EPI == 2){
                    size_t o = (size_t)rr*256 + col;
                    float2 fv = make_float2(v0, v1);
                    *reinterpret_cast<float2*>(C + o)    = fv;
                    *reinterpret_cast<float2*>(out0 + o) = fv;
                    *reinterpret_cast<float2*>(out2 + o) = fv;
                    *reinterpret_cast<float2*>(out_mem + (size_t)rr*(ML_*256) + 9*256 + col) = fv;
                } else if (EPI == 3){
                    int b = rr/9, m = rr - b*9 + 1;
                    float2 oz = *reinterpret_cast<const float2*>(ozh + (size_t)b*768 + 512 + col);
                    float mt0 = tanhf(v0 + oz.x), mt1 = tanhf(v1 + oz.y);
                    float2 zv = *reinterpret_cast<const float2*>(zs + (size_t)rr*256 + col);
                    float2 mv = *reinterpret_cast<const float2*>(memory + ((size_t)b*ML_ + m)*256 + col);
                    float r0 = zv.x*mv.x + (1.f - zv.x)*mt0;
                    float r1 = zv.y*mv.y + (1.f - zv.y)*mt1;
                    *reinterpret_cast<float2*>(out_mem + (size_t)b*(ML_*256) + (size_t)(m-1)*256 + col) = make_float2(r0, r1);
                } else {  // EPI 4
                    int b = rr/9, m = rr - b*9 + 1;
                    float2 oz = *reinterpret_cast<const float2*>(ozh + (size_t)b*768 + col);
                    float s0 = sigf(v0 + oz.x), s1 = sigf(v1 + oz.y);
                    if (col < 256){
                        *reinterpret_cast<float2*>(zs + (size_t)rr*256 + col) = make_float2(s0, s1);
                    } else {
                        int cc = col - 256;
                        float2 mv = *reinterpret_cast<const float2*>(memory + ((size_t)b*ML_ + m)*256 + cc);
                        *reinterpret_cast<float2*>(rm + (size_t)rr*256 + cc) = make_float2(s0*mv.x, s1*mv.y);
                    }
                }
            }
        }
    }
}

// ---------------- prep: Wqk = (q_W^T @ k_W)^T, bqk, bigo, bozh ----------------
__global__ void k_prep(const float* __restrict__ qW, const float* __restrict__ kW,
                       const float* __restrict__ qb,
                       const float* __restrict__ bih, const float* __restrict__ bhh,
                       const float* __restrict__ zb, const float* __restrict__ rb,
                       const float* __restrict__ hb)
{
    int blk = blockIdx.x;
    if (blk < 256){
        int j = blk, e = threadIdx.x;
        float s = 0.f;
        for (int d = 0; d < 256; d++) s = fmaf(qW[d*256 + e], kW[d*256 + j], s);
        g_Wqk[j*256 + e] = s;
        if (e == 0){
            float bq = 0.f;
            for (int d = 0; d < 256; d++) bq = fmaf(qb[d], kW[d*256 + j], bq);
            g_bqk[j] = bq;
        }
        return;
    }
    int i = (blk - 256)*256 + threadIdx.x;
    if (i < 768){
        int src = (i < 256) ? i : i + 256;
        g_bigo[i] = bih[src] + bhh[src];
    } else if (i < 1536){
        int n = i - 768;
        g_bozh[n] = (n < 256) ? zb[n] : (n < 512) ? rb[n-256] : hb[n-512];
    }
}

// ---------------- frame weighting ----------------
__global__ void k_frame(const float* __restrict__ O_t, const float* __restrict__ O_prev,
                        const float* __restrict__ wW, const float* __restrict__ wb,
                        float* __restrict__ out_Wt)
{
    int b = blockIdx.x, t = threadIdx.x;
    float ot = O_t[(size_t)b*256 + t];
    float op = O_prev[(size_t)b*256 + t];
    float dl = ot - op;
    float s0 = ot*ot, s1 = op*op, s2 = dl*dl, s3 = ot*op;
    #pragma unroll
    for (int off = 16; off; off >>= 1){
        s0 += __shfl_xor_sync(0xffffffffu, s0, off);
        s1 += __shfl_xor_sync(0xffffffffu, s1, off);
        s2 += __shfl_xor_sync(0xffffffffu, s2, off);
        s3 += __shfl_xor_sync(0xffffffffu, s3, off);
    }
    __shared__ float4 ws[8];
    __shared__ float4 tot;
    int w = t >> 5;
    if ((t & 31) == 0) ws[w] = make_float4(s0, s1, s2, s3);
    __syncthreads();
    if (t == 0){
        float4 r = ws[0];
        #pragma unroll
        for (int i = 1; i < 8; i++){ r.x += ws[i].x; r.y += ws[i].y; r.z += ws[i].z; r.w += ws[i].w; }
        tot = r;
    }
    __syncthreads();
    float n_t = sqrtf(tot.x), n_p = sqrtf(tot.y), rd = sqrtf(tot.z);
    float ra  = tot.w / (n_t*n_p + 1e-6f);
    float wt  = 0.5f*(tanhf(n_t*wW[t*3+0] + rd*wW[t*3+1] + ra*wW[t*3+2] + wb[t]) + 1.f);
    out_Wt[(size_t)b*256 + t] = wt;
    g_X[(size_t)b*512 + t]       = op;
    g_X[(size_t)b*512 + 256 + t] = ot * wt;
}

// ---------------- LSTM activations ----------------
__global__ void k_lstm_act(){
    size_t i = (size_t)blockIdx.x*256 + threadIdx.x;
    size_t b = i >> 8; int d = (int)(i & 255);
    float ig = g_gates[b*768 + d];
    float gg = g_gates[b*768 + 256 + d];
    float og = g_gates[b*768 + 512 + d];
    float c  = sigf(ig) * tanhf(gg);
    g_OTP[i] = sigf(og) * tanhf(c);
}

// ---------------- attention ----------------
__global__ void k_attn(const float* __restrict__ memory){
    int b = blockIdx.x, t = threadIdx.x;
    float qk = g_QK[(size_t)b*256 + t];
    const float* mb = memory + (size_t)b*ML_*256;
    float mv[ML_];
    __shared__ float sc[ML_];
    __shared__ float attn[ML_];
    if (t < ML_) sc[t] = 0.f;
    __syncthreads();
    #pragma unroll
    for (int m = 0; m < ML_; m++){
        mv[m] = mb[m*256 + t];
        float v = qk * mv[m];
        #pragma unroll
        for (int off = 16; off; off >>= 1) v += __shfl_xor_sync(0xffffffffu, v, off);
        if ((t & 31) == 0) atomicAdd(&sc[m], v);
    }
    __syncthreads();
    if (t == 0){
        float mx = -1e30f;
        #pragma unroll
        for (int m = 0; m < ML_; m++){ sc[m] *= 0.0625f; mx = fmaxf(mx, sc[m]); }
        float e[ML_], s = 0.f;
        #pragma unroll
        for (int m = 0; m < ML_; m++){ e[m] = expf(sc[m] - mx); s += e[m]; }
        float inv = 1.f / s;
        #pragma unroll
        for (int m = 0; m < ML_; m++) attn[m] = e[m] * inv;
    }
    __syncthreads();
    float wm = 0.f;
    #pragma unroll
    for (int m = 0; m < ML_; m++) wm += attn[m] * mv[m];
    g_WM[(size_t)b*256 + t] = wm;
}

// ---------------- launcher ----------------
extern "C" void kernel_launch(void* const* d_in, const int* in_sizes, int n_in,
                              void* d_out, int out_size)
{
    const float* O_t     = (const float*)d_in[0];
    const float* O_prev  = (const float*)d_in[1];
    const float* memory  = (const float*)d_in[2];
    const float* w_mlp_W = (const float*)d_in[3];
    const float* w_mlp_b = (const float*)d_in[4];
    const float* lstm_Wih= (const float*)d_in[5];
    const float* lstm_bih= (const float*)d_in[7];
    const float* lstm_bhh= (const float*)d_in[8];
    const float* q_W = (const float*)d_in[9];   const float* q_b = (const float*)d_in[10];
    const float* k_W = (const float*)d_in[11];  // k_b cancels in softmax
    const float* v_W = (const float*)d_in[13];  const float* v_b = (const float*)d_in[14];
    const float* z_W = (const float*)d_in[15];  const float* z_b = (const float*)d_in[16];
    const float* r_W = (const float*)d_in[17];  const float* r_b = (const float*)d_in[18];
    const float* h_W = (const float*)d_in[19];  const float* h_b = (const float*)d_in[20];

    float* out      = (float*)d_out;
    float* out0     = out;
    float* out_mem  = out0 + (size_t)B_*D_;
    float* out2     = out_mem + (size_t)B_*ML_*D_;
    float* out3     = out2 + (size_t)B_*D_;

    cudaFuncSetAttribute(k_mma<0,1,0>, cudaFuncAttributeMaxDynamicSharedMemorySize, SMEM_TOTAL);
    cudaFuncSetAttribute(k_mma<0,0,0>, cudaFuncAttributeMaxDynamicSharedMemorySize, SMEM_TOTAL);
    cudaFuncSetAttribute(k_mma<0,0,2>, cudaFuncAttributeMaxDynamicSharedMemorySize, SMEM_TOTAL);
    cudaFuncSetAttribute(k_mma<0,3,0>, cudaFuncAttributeMaxDynamicSharedMemorySize, SMEM_TOTAL);
    cudaFuncSetAttribute(k_mma<1,2,4>, cudaFuncAttributeMaxDynamicSharedMemorySize, SMEM_TOTAL);
    cudaFuncSetAttribute(k_mma<0,0,3>, cudaFuncAttributeMaxDynamicSharedMemorySize, SMEM_TOTAL);

    float *pX,*pGates,*pOTP,*pQK,*pWM,*pOUP,*pOZH,*pZs,*pRM,*pWqk,*pbigo,*pbozh,*pbqk;
    cudaGetSymbolAddress((void**)&pX,     g_X);
    cudaGetSymbolAddress((void**)&pGates, g_gates);
    cudaGetSymbolAddress((void**)&pOTP,   g_OTP);
    cudaGetSymbolAddress((void**)&pQK,    g_QK);
    cudaGetSymbolAddress((void**)&pWM,    g_WM);
    cudaGetSymbolAddress((void**)&pOUP,   g_OUP);
    cudaGetSymbolAddress((void**)&pOZH,   g_OZH);
    cudaGetSymbolAddress((void**)&pZs,    g_Zs);
    cudaGetSymbolAddress((void**)&pRM,    g_RM);
    cudaGetSymbolAddress((void**)&pWqk,   g_Wqk);
    cudaGetSymbolAddress((void**)&pbigo,  g_bigo);
    cudaGetSymbolAddress((void**)&pbozh,  g_bozh);
    cudaGetSymbolAddress((void**)&pbqk,   g_bqk);

    // 1: prep (Wqk GEMM fp32 + biases)
    k_prep<<<262, 256>>>(q_W, k_W, q_b, lstm_bih, lstm_bhh, z_b, r_b, h_b);
    // 2: frame weighting -> X + W_t out
    k_frame<<<B_, 256>>>(O_t, O_prev, w_mlp_W, w_mlp_b, out3);
    // 3: LSTM gates [B,768], K=512 (gate-remapped Wih, no copy)
    k_mma<0,1,0><<<dim3(3, B_/128), 256, SMEM_TOTAL>>>(
        pX, nullptr, lstm_Wih, nullptr, nullptr, 512, pbigo,
        pGates, nullptr, nullptr, nullptr, nullptr, nullptr, nullptr, nullptr,
        B_, 768, 512);
    // 4: LSTM activations -> OTP
    k_lstm_act<<<B_, 256>>>();
    // 5: QK = OTP @ Wqk^T + bqk  [B,256]
    k_mma<0,0,0><<<dim3(1, B_/128), 256, SMEM_TOTAL>>>(
        pOTP, nullptr, pWqk, nullptr, nullptr, 256, pbqk,
        pQK, nullptr, nullptr, nullptr, nullptr, nullptr, nullptr, nullptr,
        B_, 256, 256);
    // 6: attention -> WM
    k_attn<<<B_, 256>>>(memory);
    // 7: V GEMM -> OUP + out0/out2/mem slot 9
    k_mma<0,0,2><<<dim3(1, B_/128), 256, SMEM_TOTAL>>>(
        pWM, nullptr, v_W, nullptr, nullptr, 256, v_b,
        pOUP, out0, out_mem, out2, nullptr, nullptr, nullptr, nullptr,
        B_, 256, 256);
    // 8: OZH = O_up @ [zW|rW|hW][:,256:512]^T + [zb|rb|hb]  [B,768] (sliced weights, no copy)
    k_mma<0,3,0><<<dim3(3, B_/128), 256, SMEM_TOTAL>>>(
        pOUP, nullptr, z_W, r_W, h_W, 0, pbozh,
        pOZH, nullptr, nullptr, nullptr, nullptr, nullptr, nullptr, nullptr,
        B_, 768, 256);
    // 9: zr GEMM (mem half, raw memory as A) [M2,512]; epi: +OZH, Zs=sig(z), RM=sig(r)*mem
    k_mma<1,2,4><<<dim3(2, M2_/128), 256, SMEM_TOTAL>>>(
        nullptr, memory, z_W, r_W, nullptr, 0, nullptr,
        nullptr, nullptr, nullptr, nullptr, pOZH, pZs, pRM, memory,
        M2_, 512, 256);
    // 10: h GEMM (rm half) [M2,256]; epi: +OZH, tanh, z-combine, shifted write
    k_mma<0,0,3><<<dim3(1, M2_/128), 256, SMEM_TOTAL>>>(
        pRM, nullptr, h_W, nullptr, nullptr, 512, nullptr,
        nullptr, nullptr, out_mem, nullptr, pOZH, pZs, nullptr, memory,
        M2_, 256, 256);
}

// round 7
// speedup vs baseline: 3.8012x; 1.2556x over previous
#include <cuda_runtime.h>
#include <math.h>
#include <stdint.h>

#define B_   16384
#define D_   256
#define ML_  10
#define M2_  (B_*9)

// ---------------- fp32 scratch ----------------
__device__ __align__(256) float g_X    [(size_t)B_*512];   // [O_prev, O_t*W_t]
__device__ __align__(256) float g_gates[(size_t)B_*768];
__device__ __align__(256) float g_OTP  [(size_t)B_*256];
__device__ __align__(256) float g_QK   [(size_t)B_*256];
__device__ __align__(256) float g_WM   [(size_t)B_*256];
__device__ __align__(256) float g_OUP  [(size_t)B_*256];
__device__ __align__(256) float g_OZH  [(size_t)B_*768];   // O_up @ [zW|rW|hW][:,256:512]^T + bias
__device__ __align__(256) float g_Zs   [(size_t)M2_*256];  // sigmoid(z)
__device__ __align__(256) float g_RM   [(size_t)M2_*256];  // sigmoid(r)*mem
__device__ __align__(256) float g_Wqk  [65536];            // (q_W^T @ k_W)^T, [j,e]
__device__ __align__(256) float g_bigo [768];
__device__ __align__(256) float g_bozh [768];
__device__ __align__(256) float g_bqk  [256];

__device__ __forceinline__ float sigf(float x){ return 1.f/(1.f+expf(-x)); }

// ---------------- PTX helpers (base ISA only) ----------------
__device__ __forceinline__ uint32_t smem_u32(const void* p){
    uint32_t a; asm("{ .reg .u64 t; cvta.to.shared.u64 t, %1; cvt.u32.u64 %0, t; }" : "=r"(a) : "l"(p));
    return a;
}
__device__ __forceinline__ uint32_t lds_cvt(uint32_t addr){
    float f; uint32_t y;
    asm volatile("ld.shared.f32 %0, [%1];" : "=f"(f) : "r"(addr));
    asm("cvt.rna.tf32.f32 %0, %1;" : "=r"(y) : "f"(f));
    return y;
}
__device__ __forceinline__ void mma_tf32(float* c, const uint32_t* a, const uint32_t* b){
    asm volatile("mma.sync.aligned.m16n8k8.row.col.f32.tf32.tf32.f32 "
        "{%0,%1,%2,%3}, {%4,%5,%6,%7}, {%8,%9}, {%0,%1,%2,%3};"
        : "+f"(c[0]),"+f"(c[1]),"+f"(c[2]),"+f"(c[3])
        : "r"(a[0]),"r"(a[1]),"r"(a[2]),"r"(a[3]), "r"(b[0]),"r"(b[1]));
}
__device__ __forceinline__ void cpa16(uint32_t dst, const void* src){
    asm volatile("cp.async.cg.shared.global [%0], [%1], 16;" :: "r"(dst), "l"(src));
}
#define CP_COMMIT() asm volatile("cp.async.commit_group;" ::: "memory")
#define CP_WAIT1()  asm volatile("cp.async.wait_group 1;"  ::: "memory")

// SMEM per stage: A 128 rows x 144B = 18432; W 128 rows x 144B = 18432 ; stage 36864, 3 stages
// 110592 B/CTA -> 2 CTAs/SM (221184 <= 227KB)
#define ROWB     144
#define STAGE_SZ 36864
#define SMEM_TOTAL (3*STAGE_SZ)

// ================== tf32 HMMA GEMM: C[M,N] = A[M,K] @ W[N,K]^T (1-pass) ==================
// CTA 128x128, 8 warps (2x4), warp tile 64x32, K-chunk 32, 3-stage cp.async, 2 CTAs/SM.
// AMODE 0: A row r -> A + (m0+r)*K
// AMODE 1: A row r -> b=r/9, m=r%9+1 -> memory + (b*10+m)*256   (Amem arg)
// WMODE 0: W + row*ws + gk
// WMODE 1: LSTM remap: src=(row<256?row:row+256); Wih + src*512 + gk
// WMODE 2: z|r concat: row<256 -> W+row*512+gk else W2+(row-256)*512+gk
// WMODE 3: ozh: 3-way concat (W,W2,W3), row-blocks of 256, col offset +256
// EPI 0: C = v + bias[col]
// EPI 2: V-mode: v+=bias; v -> C(=OUP), out0, out2, out_mem slot 9
// EPI 3: h-mode: v += ozh[b*768+512+col]; mt=tanh(v); z=zs;
//        out_mem[b,m-1,col] = z*memory[b,m,col] + (1-z)*mt
// EPI 4: zr-mode: v += ozh[b*768+col]; col<256 -> zs=sig(v); else rm=sig(v)*mem
template<int AMODE,int WMODE,int EPI>
__global__ void __launch_bounds__(256,2) k_mma(
    const float* __restrict__ A, const float* __restrict__ Amem,
    const float* __restrict__ W, const float* __restrict__ W2, const float* __restrict__ W3,
    int ws,
    const float* __restrict__ bias,
    float* __restrict__ C,
    float* __restrict__ out0, float* __restrict__ out_mem, float* __restrict__ out2,
    const float* __restrict__ ozh, float* __restrict__ zs, float* __restrict__ rm,
    const float* __restrict__ memory,
    int M, int N, int K)
{
    extern __shared__ char smem[];
    uint32_t sb = smem_u32(smem);
    const int tid = threadIdx.x, lane = tid & 31, w = tid >> 5;
    const int wm = w >> 2, wn = w & 3;
    const int m0 = blockIdx.y * 128, n0 = blockIdx.x * 128;
    const int nch = K >> 5;

    float acc[4][4][4];
    #pragma unroll
    for (int i=0;i<4;i++)
        #pragma unroll
        for (int j=0;j<4;j++)
            #pragma unroll
            for (int k=0;k<4;k++) acc[i][j][k]=0.f;

    auto aptr = [&](int row, int gk)->const float*{
        if (AMODE == 0) return A + (size_t)(m0+row)*K + gk;
        int rr = m0 + row, b = rr/9, m = rr - b*9 + 1;
        return Amem + ((size_t)b*10 + m)*256 + gk;
    };
    auto wptr = [&](int row, int gk)->const float*{
        if (WMODE == 0) return W + (size_t)row*ws + gk;
        if (WMODE == 1){ int s = (row<256)?row:row+256; return W + (size_t)s*512 + gk; }
        if (WMODE == 2) return (row<256) ? W + (size_t)row*512 + gk
                                         : W2 + (size_t)(row-256)*512 + gk;
        return (row<256) ? W  + (size_t)row*512 + 256 + gk
             : (row<512) ? W2 + (size_t)(row-256)*512 + 256 + gk
                         : W3 + (size_t)(row-512)*512 + 256 + gk;
    };
    auto load_chunk = [&](int c, int s){
        uint32_t st = sb + s*STAGE_SZ;
        #pragma unroll
        for (int t=0;t<4;t++){
            int u = tid + t*256;
            int row = u >> 3, q = u & 7;
            cpa16(st + row*ROWB + q*16, aptr(row, c*32 + q*4));
        }
        #pragma unroll
        for (int t=0;t<4;t++){
            int u = tid + t*256;
            int row = u >> 3, q = u & 7;
            cpa16(st + 18432 + row*ROWB + q*16, wptr(n0 + row, c*32 + q*4));
        }
        CP_COMMIT();
    };

    load_chunk(0, 0);
    load_chunk(1, 1);

    for (int c = 0; c < nch; c++){
        CP_WAIT1();
        __syncthreads();
        if (c + 2 < nch) load_chunk(c + 2, (c + 2) % 3);

        uint32_t sA = sb + (c % 3)*STAGE_SZ;
        uint32_t sW = sA + 18432;
        #pragma unroll
        for (int kk = 0; kk < 4; kk++){
            uint32_t a[4][4];
            #pragma unroll
            for (int i = 0; i < 4; i++){
                int r0 = wm*64 + i*16 + (lane >> 2);
                uint32_t base = sA + r0*ROWB + (kk*8 + (lane & 3))*4;
                a[i][0] = lds_cvt(base);
                a[i][1] = lds_cvt(base + 8*ROWB);
                a[i][2] = lds_cvt(base + 16);
                a[i][3] = lds_cvt(base + 8*ROWB + 16);
            }
            uint32_t bf[4][2];
            #pragma unroll
            for (int j = 0; j < 4; j++){
                int nl = wn*32 + j*8 + (lane >> 2);
                uint32_t base = sW + nl*ROWB + (kk*8 + (lane & 3))*4;
                bf[j][0] = lds_cvt(base);
                bf[j][1] = lds_cvt(base + 16);
            }
            #pragma unroll
            for (int i=0;i<4;i++)
                #pragma unroll
                for (int j=0;j<4;j++) mma_tf32(acc[i][j], a[i], bf[j]);
        }
        __syncthreads();
    }

    // ---- epilogue ----
    #pragma unroll
    for (int j = 0; j < 4; j++){
        int col = n0 + wn*32 + j*8 + (lane & 3)*2;
        float b0 = 0.f, b1 = 0.f;
        if (EPI == 0 || EPI == 2){
            if (bias){ b0 = bias[col]; b1 = bias[col+1]; }
        }
        #pragma unroll
        for (int i = 0; i < 4; i++){
            int row = m0 + wm*64 + i*16 + (lane >> 2);
            #pragma unroll
            for (int h = 0; h < 2; h++){
                int rr = row + h*8;
                float v0 = acc[i][j][2*h+0] + b0;
                float v1 = acc[i][j][2*h+1] + b1;
                if (EPI == 0){
                    *reinterpret_cast<float2*>(C + (size_t)rr*N + col) = make_float2(v0, v1);
                } else if (EPI == 2){
                    size_t o = (size_t)rr*256 + col;
                    float2 fv = make_float2(v0, v1);
                    *reinterpret_cast<float2*>(C + o)    = fv;
                    *reinterpret_cast<float2*>(out0 + o) = fv;
                    *reinterpret_cast<float2*>(out2 + o) = fv;
                    *reinterpret_cast<float2*>(out_mem + (size_t)rr*(ML_*256) + 9*256 + col) = fv;
                } else if (EPI == 3){
                    int b = rr/9, m = rr - b*9 + 1;
                    float2 oz = *reinterpret_cast<const float2*>(ozh + (size_t)b*768 + 512 + col);
                    float mt0 = tanhf(v0 + oz.x), mt1 = tanhf(v1 + oz.y);
                    float2 zv = *reinterpret_cast<const float2*>(zs + (size_t)rr*256 + col);
                    float2 mv = *reinterpret_cast<const float2*>(memory + ((size_t)b*ML_ + m)*256 + col);
                    float r0 = zv.x*mv.x + (1.f - zv.x)*mt0;
                    float r1 = zv.y*mv.y + (1.f - zv.y)*mt1;
                    *reinterpret_cast<float2*>(out_mem + (size_t)b*(ML_*256) + (size_t)(m-1)*256 + col) = make_float2(r0, r1);
                } else {  // EPI 4
                    int b = rr/9, m = rr - b*9 + 1;
                    float2 oz = *reinterpret_cast<const float2*>(ozh + (size_t)b*768 + col);
                    float s0 = sigf(v0 + oz.x), s1 = sigf(v1 + oz.y);
                    if (col < 256){
                        *reinterpret_cast<float2*>(zs + (size_t)rr*256 + col) = make_float2(s0, s1);
                    } else {
                        int cc = col - 256;
                        float2 mv = *reinterpret_cast<const float2*>(memory + ((size_t)b*ML_ + m)*256 + cc);
                        *reinterpret_cast<float2*>(rm + (size_t)rr*256 + cc) = make_float2(s0*mv.x, s1*mv.y);
                    }
                }
            }
        }
    }
}

// ---------------- prep: Wqk = (q_W^T @ k_W)^T, bqk, bigo, bozh ----------------
__global__ void k_prep(const float* __restrict__ qW, const float* __restrict__ kW,
                       const float* __restrict__ qb,
                       const float* __restrict__ bih, const float* __restrict__ bhh,
                       const float* __restrict__ zb, const float* __restrict__ rb,
                       const float* __restrict__ hb)
{
    int blk = blockIdx.x;
    if (blk < 256){
        int j = blk, e = threadIdx.x;
        float s = 0.f;
        for (int d = 0; d < 256; d++) s = fmaf(qW[d*256 + e], kW[d*256 + j], s);
        g_Wqk[j*256 + e] = s;
        if (e == 0){
            float bq = 0.f;
            for (int d = 0; d < 256; d++) bq = fmaf(qb[d], kW[d*256 + j], bq);
            g_bqk[j] = bq;
        }
        return;
    }
    int i = (blk - 256)*256 + threadIdx.x;
    if (i < 768){
        int src = (i < 256) ? i : i + 256;
        g_bigo[i] = bih[src] + bhh[src];
    } else if (i < 1536){
        int n = i - 768;
        g_bozh[n] = (n < 256) ? zb[n] : (n < 512) ? rb[n-256] : hb[n-512];
    }
}

// ---------------- frame weighting ----------------
__global__ void k_frame(const float* __restrict__ O_t, const float* __restrict__ O_prev,
                        const float* __restrict__ wW, const float* __restrict__ wb,
                        float* __restrict__ out_Wt)
{
    int b = blockIdx.x, t = threadIdx.x;
    float ot = O_t[(size_t)b*256 + t];
    float op = O_prev[(size_t)b*256 + t];
    float dl = ot - op;
    float s0 = ot*ot, s1 = op*op, s2 = dl*dl, s3 = ot*op;
    #pragma unroll
    for (int off = 16; off; off >>= 1){
        s0 += __shfl_xor_sync(0xffffffffu, s0, off);
        s1 += __shfl_xor_sync(0xffffffffu, s1, off);
        s2 += __shfl_xor_sync(0xffffffffu, s2, off);
        s3 += __shfl_xor_sync(0xffffffffu, s3, off);
    }
    __shared__ float4 ws[8];
    __shared__ float4 tot;
    int w = t >> 5;
    if ((t & 31) == 0) ws[w] = make_float4(s0, s1, s2, s3);
    __syncthreads();
    if (t == 0){
        float4 r = ws[0];
        #pragma unroll
        for (int i = 1; i < 8; i++){ r.x += ws[i].x; r.y += ws[i].y; r.z += ws[i].z; r.w += ws[i].w; }
        tot = r;
    }
    __syncthreads();
    float n_t = sqrtf(tot.x), n_p = sqrtf(tot.y), rd = sqrtf(tot.z);
    float ra  = tot.w / (n_t*n_p + 1e-6f);
    float wt  = 0.5f*(tanhf(n_t*wW[t*3+0] + rd*wW[t*3+1] + ra*wW[t*3+2] + wb[t]) + 1.f);
    out_Wt[(size_t)b*256 + t] = wt;
    g_X[(size_t)b*512 + t]       = op;
    g_X[(size_t)b*512 + 256 + t] = ot * wt;
}

// ---------------- LSTM activations ----------------
__global__ void k_lstm_act(){
    size_t i = (size_t)blockIdx.x*256 + threadIdx.x;
    size_t b = i >> 8; int d = (int)(i & 255);
    float ig = g_gates[b*768 + d];
    float gg = g_gates[b*768 + 256 + d];
    float og = g_gates[b*768 + 512 + d];
    float c  = sigf(ig) * tanhf(gg);
    g_OTP[i] = sigf(og) * tanhf(c);
}

// ---------------- attention ----------------
__global__ void k_attn(const float* __restrict__ memory){
    int b = blockIdx.x, t = threadIdx.x;
    float qk = g_QK[(size_t)b*256 + t];
    const float* mb = memory + (size_t)b*ML_*256;
    float mv[ML_];
    __shared__ float sc[ML_];
    __shared__ float attn[ML_];
    if (t < ML_) sc[t] = 0.f;
    __syncthreads();
    #pragma unroll
    for (int m = 0; m < ML_; m++){
        mv[m] = mb[m*256 + t];
        float v = qk * mv[m];
        #pragma unroll
        for (int off = 16; off; off >>= 1) v += __shfl_xor_sync(0xffffffffu, v, off);
        if ((t & 31) == 0) atomicAdd(&sc[m], v);
    }
    __syncthreads();
    if (t == 0){
        float mx = -1e30f;
        #pragma unroll
        for (int m = 0; m < ML_; m++){ sc[m] *= 0.0625f; mx = fmaxf(mx, sc[m]); }
        float e[ML_], s = 0.f;
        #pragma unroll
        for (int m = 0; m < ML_; m++){ e[m] = expf(sc[m] - mx); s += e[m]; }
        float inv = 1.f / s;
        #pragma unroll
        for (int m = 0; m < ML_; m++) attn[m] = e[m] * inv;
    }
    __syncthreads();
    float wm = 0.f;
    #pragma unroll
    for (int m = 0; m < ML_; m++) wm += attn[m] * mv[m];
    g_WM[(size_t)b*256 + t] = wm;
}

// ---------------- launcher ----------------
extern "C" void kernel_launch(void* const* d_in, const int* in_sizes, int n_in,
                              void* d_out, int out_size)
{
    const float* O_t     = (const float*)d_in[0];
    const float* O_prev  = (const float*)d_in[1];
    const float* memory  = (const float*)d_in[2];
    const float* w_mlp_W = (const float*)d_in[3];
    const float* w_mlp_b = (const float*)d_in[4];
    const float* lstm_Wih= (const float*)d_in[5];
    const float* lstm_bih= (const float*)d_in[7];
    const float* lstm_bhh= (const float*)d_in[8];
    const float* q_W = (const float*)d_in[9];   const float* q_b = (const float*)d_in[10];
    const float* k_W = (const float*)d_in[11];  // k_b cancels in softmax
    const float* v_W = (const float*)d_in[13];  const float* v_b = (const float*)d_in[14];
    const float* z_W = (const float*)d_in[15];  const float* z_b = (const float*)d_in[16];
    const float* r_W = (const float*)d_in[17];  const float* r_b = (const float*)d_in[18];
    const float* h_W = (const float*)d_in[19];  const float* h_b = (const float*)d_in[20];

    float* out      = (float*)d_out;
    float* out0     = out;
    float* out_mem  = out0 + (size_t)B_*D_;
    float* out2     = out_mem + (size_t)B_*ML_*D_;
    float* out3     = out2 + (size_t)B_*D_;

    cudaFuncSetAttribute(k_mma<0,1,0>, cudaFuncAttributeMaxDynamicSharedMemorySize, SMEM_TOTAL);
    cudaFuncSetAttribute(k_mma<0,0,0>, cudaFuncAttributeMaxDynamicSharedMemorySize, SMEM_TOTAL);
    cudaFuncSetAttribute(k_mma<0,0,2>, cudaFuncAttributeMaxDynamicSharedMemorySize, SMEM_TOTAL);
    cudaFuncSetAttribute(k_mma<0,3,0>, cudaFuncAttributeMaxDynamicSharedMemorySize, SMEM_TOTAL);
    cudaFuncSetAttribute(k_mma<1,2,4>, cudaFuncAttributeMaxDynamicSharedMemorySize, SMEM_TOTAL);
    cudaFuncSetAttribute(k_mma<0,0,3>, cudaFuncAttributeMaxDynamicSharedMemorySize, SMEM_TOTAL);

    float *pX,*pGates,*pOTP,*pQK,*pWM,*pOUP,*pOZH,*pZs,*pRM,*pWqk,*pbigo,*pbozh,*pbqk;
    cudaGetSymbolAddress((void**)&pX,     g_X);
    cudaGetSymbolAddress((void**)&pGates, g_gates);
    cudaGetSymbolAddress((void**)&pOTP,   g_OTP);
    cudaGetSymbolAddress((void**)&pQK,    g_QK);
    cudaGetSymbolAddress((void**)&pWM,    g_WM);
    cudaGetSymbolAddress((void**)&pOUP,   g_OUP);
    cudaGetSymbolAddress((void**)&pOZH,   g_OZH);
    cudaGetSymbolAddress((void**)&pZs,    g_Zs);
    cudaGetSymbolAddress((void**)&pRM,    g_RM);
    cudaGetSymbolAddress((void**)&pWqk,   g_Wqk);
    cudaGetSymbolAddress((void**)&pbigo,  g_bigo);
    cudaGetSymbolAddress((void**)&pbozh,  g_bozh);
    cudaGetSymbolAddress((void**)&pbqk,   g_bqk);

    // 1: prep (Wqk GEMM fp32 + biases)
    k_prep<<<262, 256>>>(q_W, k_W, q_b, lstm_bih, lstm_bhh, z_b, r_b, h_b);
    // 2: frame weighting -> X + W_t out
    k_frame<<<B_, 256>>>(O_t, O_prev, w_mlp_W, w_mlp_b, out3);
    // 3: LSTM gates [B,768], K=512 (gate-remapped Wih, no copy)
    k_mma<0,1,0><<<dim3(6, B_/128), 256, SMEM_TOTAL>>>(
        pX, nullptr, lstm_Wih, nullptr, nullptr, 512, pbigo,
        pGates, nullptr, nullptr, nullptr, nullptr, nullptr, nullptr, nullptr,
        B_, 768, 512);
    // 4: LSTM activations -> OTP
    k_lstm_act<<<B_, 256>>>();
    // 5: QK = OTP @ Wqk^T + bqk  [B,256]
    k_mma<0,0,0><<<dim3(2, B_/128), 256, SMEM_TOTAL>>>(
        pOTP, nullptr, pWqk, nullptr, nullptr, 256, pbqk,
        pQK, nullptr, nullptr, nullptr, nullptr, nullptr, nullptr, nullptr,
        B_, 256, 256);
    // 6: attention -> WM
    k_attn<<<B_, 256>>>(memory);
    // 7: V GEMM -> OUP + out0/out2/mem slot 9
    k_mma<0,0,2><<<dim3(2, B_/128), 256, SMEM_TOTAL>>>(
        pWM, nullptr, v_W, nullptr, nullptr, 256, v_b,
        pOUP, out0, out_mem, out2, nullptr, nullptr, nullptr, nullptr,
        B_, 256, 256);
    // 8: OZH = O_up @ [zW|rW|hW][:,256:512]^T + [zb|rb|hb]  [B,768] (sliced weights, no copy)
    k_mma<0,3,0><<<dim3(6, B_/128), 256, SMEM_TOTAL>>>(
        pOUP, nullptr, z_W, r_W, h_W, 0, pbozh,
        pOZH, nullptr, nullptr, nullptr, nullptr, nullptr, nullptr, nullptr,
        B_, 768, 256);
    // 9: zr GEMM (mem half, raw memory as A) [M2,512]; epi: +OZH, Zs=sig(z), RM=sig(r)*mem
    k_mma<1,2,4><<<dim3(4, M2_/128), 256, SMEM_TOTAL>>>(
        nullptr, memory, z_W, r_W, nullptr, 0, nullptr,
        nullptr, nullptr, nullptr, nullptr, pOZH, pZs, pRM, memory,
        M2_, 512, 256);
    // 10: h GEMM (rm half) [M2,256]; epi: +OZH, tanh, z-combine, shifted write
    k_mma<0,0,3><<<dim3(2, M2_/128), 256, SMEM_TOTAL>>>(
        pRM, nullptr, h_W, nullptr, nullptr, 512, nullptr,
        nullptr, nullptr, out_mem, nullptr, pOZH, pZs, nullptr, memory,
        M2_, 256, 256);
}

// round 8
// speedup vs baseline: 3.9273x; 1.0332x over previous
#include <cuda_runtime.h>
#include <math.h>
#include <stdint.h>

#define B_   16384
#define D_   256
#define ML_  10
#define M2_  (B_*9)

// ---------------- fp32 scratch ----------------
__device__ __align__(256) float g_X    [(size_t)B_*512];   // [O_prev, O_t*W_t] (tf32-rounded)
__device__ __align__(256) float g_gates[(size_t)B_*768];
__device__ __align__(256) float g_OTP  [(size_t)B_*256];   // tf32-rounded
__device__ __align__(256) float g_QK   [(size_t)B_*256];
__device__ __align__(256) float g_WM   [(size_t)B_*256];   // tf32-rounded
__device__ __align__(256) float g_OUP  [(size_t)B_*256];   // tf32-rounded
__device__ __align__(256) float g_OZH  [(size_t)B_*768];
__device__ __align__(256) float g_Zs   [(size_t)M2_*256];  // sigmoid(z), exact
__device__ __align__(256) float g_RM   [(size_t)M2_*256];  // sigmoid(r)*mem (tf32-rounded)
__device__ __align__(256) float g_MEMr [(size_t)B_*ML_*256]; // tf32-rounded memory
// tf32-rounded weights
__device__ __align__(256) float g_Wigo [768*512];  // gate-remapped Wih
__device__ __align__(256) float g_Wqk  [65536];    // (q_W^T @ k_W)^T, [j,e]
__device__ __align__(256) float g_Wv   [65536];
__device__ __align__(256) float g_Wzrm [512*256];  // z|r weights, mem half
__device__ __align__(256) float g_Whm  [256*256];  // h weights, mem half
__device__ __align__(256) float g_Wozh [768*256];  // z|r|h weights, O_up half
__device__ __align__(256) float g_bigo [768];
__device__ __align__(256) float g_bozh [768];
__device__ __align__(256) float g_bqk  [256];

__device__ __forceinline__ float sigf(float x){ return 1.f/(1.f+expf(-x)); }
__device__ __forceinline__ float tf32r(float x){
    uint32_t y; asm("cvt.rna.tf32.f32 %0, %1;" : "=r"(y) : "f"(x));
    return __uint_as_float(y);
}

// ---------------- PTX helpers (base ISA only) ----------------
__device__ __forceinline__ uint32_t smem_u32(const void* p){
    uint32_t a; asm("{ .reg .u64 t; cvta.to.shared.u64 t, %1; cvt.u32.u64 %0, t; }" : "=r"(a) : "l"(p));
    return a;
}
__device__ __forceinline__ uint32_t lds_raw(uint32_t addr){
    uint32_t y;
    asm volatile("ld.shared.b32 %0, [%1];" : "=r"(y) : "r"(addr));
    return y;
}
__device__ __forceinline__ void mma_tf32(float* c, const uint32_t* a, const uint32_t* b){
    asm volatile("mma.sync.aligned.m16n8k8.row.col.f32.tf32.tf32.f32 "
        "{%0,%1,%2,%3}, {%4,%5,%6,%7}, {%8,%9}, {%0,%1,%2,%3};"
        : "+f"(c[0]),"+f"(c[1]),"+f"(c[2]),"+f"(c[3])
        : "r"(a[0]),"r"(a[1]),"r"(a[2]),"r"(a[3]), "r"(b[0]),"r"(b[1]));
}
__device__ __forceinline__ void cpa16(uint32_t dst, const void* src){
    asm volatile("cp.async.cg.shared.global [%0], [%1], 16;" :: "r"(dst), "l"(src));
}
#define CP_COMMIT() asm volatile("cp.async.commit_group;" ::: "memory")
#define CP_WAIT1()  asm volatile("cp.async.wait_group 1;"  ::: "memory")

// SMEM per stage: A 128 rows x 144B = 18432; W 128 rows x 144B = 18432 ; stage 36864, 3 stages
// 110592 B/CTA -> 2 CTAs/SM
#define ROWB     144
#define STAGE_SZ 36864
#define SMEM_TOTAL (3*STAGE_SZ)

// ================== tf32 HMMA GEMM: C[M,N] = A[M,K] @ W[N,K]^T (pre-rounded operands) ==================
// CTA 128x128, 8 warps (2x4), warp tile 64x32, K-chunk 32, 3-stage cp.async, 2 CTAs/SM.
// AMODE 0: A row r -> A + (m0+r)*K
// AMODE 1: A row r -> b=r/9, m=r%9+1 -> Amem + (b*10+m)*256
// EPI 0: C = v + bias[col]
// EPI 2: V-mode: v+=bias; tf32(v) -> C(=OUP); v -> out0, out2, out_mem slot 9
// EPI 3: h-mode: v += ozh[b*768+512+col]; mt=tanh(v); z=zs;
//        out_mem[b,m-1,col] = z*memory[b,m,col] + (1-z)*mt
// EPI 4: zr-mode: v += ozh[b*768+col]; col<256 -> zs=sig(v); else rm=tf32(sig(v)*mem)
template<int AMODE,int EPI>
__global__ void __launch_bounds__(256,2) k_mma(
    const float* __restrict__ A, const float* __restrict__ Amem,
    const float* __restrict__ W, int ws,
    const float* __restrict__ bias,
    float* __restrict__ C,
    float* __restrict__ out0, float* __restrict__ out_mem, float* __restrict__ out2,
    const float* __restrict__ ozh, float* __restrict__ zs, float* __restrict__ rm,
    const float* __restrict__ memory,
    int M, int N, int K)
{
    extern __shared__ char smem[];
    uint32_t sb = smem_u32(smem);
    const int tid = threadIdx.x, lane = tid & 31, w = tid >> 5;
    const int wm = w >> 2, wn = w & 3;
    const int m0 = blockIdx.y * 128, n0 = blockIdx.x * 128;
    const int nch = K >> 5;

    float acc[4][4][4];
    #pragma unroll
    for (int i=0;i<4;i++)
        #pragma unroll
        for (int j=0;j<4;j++)
            #pragma unroll
            for (int k=0;k<4;k++) acc[i][j][k]=0.f;

    auto aptr = [&](int row, int gk)->const float*{
        if (AMODE == 0) return A + (size_t)(m0+row)*K + gk;
        int rr = m0 + row, b = rr/9, m = rr - b*9 + 1;
        return Amem + ((size_t)b*10 + m)*256 + gk;
    };
    auto load_chunk = [&](int c, int s){
        uint32_t st = sb + s*STAGE_SZ;
        #pragma unroll
        for (int t=0;t<4;t++){
            int u = tid + t*256;
            int row = u >> 3, q = u & 7;
            cpa16(st + row*ROWB + q*16, aptr(row, c*32 + q*4));
        }
        #pragma unroll
        for (int t=0;t<4;t++){
            int u = tid + t*256;
            int row = u >> 3, q = u & 7;
            cpa16(st + 18432 + row*ROWB + q*16, W + (size_t)(n0+row)*ws + c*32 + q*4);
        }
        CP_COMMIT();
    };

    load_chunk(0, 0);
    load_chunk(1, 1);

    for (int c = 0; c < nch; c++){
        CP_WAIT1();
        __syncthreads();
        if (c + 2 < nch) load_chunk(c + 2, (c + 2) % 3);

        uint32_t sA = sb + (c % 3)*STAGE_SZ;
        uint32_t sW = sA + 18432;
        #pragma unroll
        for (int kk = 0; kk < 4; kk++){
            uint32_t a[4][4];
            #pragma unroll
            for (int i = 0; i < 4; i++){
                int r0 = wm*64 + i*16 + (lane >> 2);
                uint32_t base = sA + r0*ROWB + (kk*8 + (lane & 3))*4;
                a[i][0] = lds_raw(base);
                a[i][1] = lds_raw(base + 8*ROWB);
                a[i][2] = lds_raw(base + 16);
                a[i][3] = lds_raw(base + 8*ROWB + 16);
            }
            uint32_t bf[4][2];
            #pragma unroll
            for (int j = 0; j < 4; j++){
                int nl = wn*32 + j*8 + (lane >> 2);
                uint32_t base = sW + nl*ROWB + (kk*8 + (lane & 3))*4;
                bf[j][0] = lds_raw(base);
                bf[j][1] = lds_raw(base + 16);
            }
            #pragma unroll
            for (int i=0;i<4;i++)
                #pragma unroll
                for (int j=0;j<4;j++) mma_tf32(acc[i][j], a[i], bf[j]);
        }
        __syncthreads();
    }

    // ---- epilogue ----
    #pragma unroll
    for (int j = 0; j < 4; j++){
        int col = n0 + wn*32 + j*8 + (lane & 3)*2;
        float b0 = 0.f, b1 = 0.f;
        if (EPI == 0 || EPI == 2){
            if (bias){ b0 = bias[col]; b1 = bias[col+1]; }
        }
        #pragma unroll
        for (int i = 0; i < 4; i++){
            int row = m0 + wm*64 + i*16 + (lane >> 2);
            #pragma unroll
            for (int h = 0; h < 2; h++){
                int rr = row + h*8;
                float v0 = acc[i][j][2*h+0] + b0;
                float v1 = acc[i][j][2*h+1] + b1;
                if (EPI == 0){
                    *reinterpret_cast<float2*>(C + (size_t)rr*N + col) = make_float2(v0, v1);
                } else if (EPI == 2){
                    size_t o = (size_t)rr*256 + col;
                    float2 fv = make_float2(v0, v1);
                    *reinterpret_cast<float2*>(C + o)    = make_float2(tf32r(v0), tf32r(v1));
                    *reinterpret_cast<float2*>(out0 + o) = fv;
                    *reinterpret_cast<float2*>(out2 + o) = fv;
                    *reinterpret_cast<float2*>(out_mem + (size_t)rr*(ML_*256) + 9*256 + col) = fv;
                } else if (EPI == 3){
                    int b = rr/9, m = rr - b*9 + 1;
                    float2 oz = *reinterpret_cast<const float2*>(ozh + (size_t)b*768 + 512 + col);
                    float mt0 = tanhf(v0 + oz.x), mt1 = tanhf(v1 + oz.y);
                    float2 zv = *reinterpret_cast<const float2*>(zs + (size_t)rr*256 + col);
                    float2 mv = *reinterpret_cast<const float2*>(memory + ((size_t)b*ML_ + m)*256 + col);
                    float r0 = zv.x*mv.x + (1.f - zv.x)*mt0;
                    float r1 = zv.y*mv.y + (1.f - zv.y)*mt1;
                    *reinterpret_cast<float2*>(out_mem + (size_t)b*(ML_*256) + (size_t)(m-1)*256 + col) = make_float2(r0, r1);
                } else {  // EPI 4
                    int b = rr/9, m = rr - b*9 + 1;
                    float2 oz = *reinterpret_cast<const float2*>(ozh + (size_t)b*768 + col);
                    float s0 = sigf(v0 + oz.x), s1 = sigf(v1 + oz.y);
                    if (col < 256){
                        *reinterpret_cast<float2*>(zs + (size_t)rr*256 + col) = make_float2(s0, s1);
                    } else {
                        int cc = col - 256;
                        float2 mv = *reinterpret_cast<const float2*>(memory + ((size_t)b*ML_ + m)*256 + cc);
                        *reinterpret_cast<float2*>(rm + (size_t)rr*256 + cc) =
                            make_float2(tf32r(s0*mv.x), tf32r(s1*mv.y));
                    }
                }
            }
        }
    }
}

// ---------------- prep: rounded/remapped weights + Wqk + biases ----------------
#define PB_QK   256
#define PB_BIAS 6
#define PB_WIGO 1536
#define PB_WZRM 512
#define PB_WHM  256
#define PB_WOZH 768
#define PB_WV   256
#define PB_TOTAL (PB_QK+PB_BIAS+PB_WIGO+PB_WZRM+PB_WHM+PB_WOZH+PB_WV)

__global__ void k_prep(const float* __restrict__ qW, const float* __restrict__ kW,
                       const float* __restrict__ qb,
                       const float* __restrict__ Wih,
                       const float* __restrict__ bih, const float* __restrict__ bhh,
                       const float* __restrict__ vW,
                       const float* __restrict__ zW, const float* __restrict__ rW,
                       const float* __restrict__ hW,
                       const float* __restrict__ zb, const float* __restrict__ rb,
                       const float* __restrict__ hb)
{
    int blk = blockIdx.x;
    if (blk < PB_QK){
        int j = blk, e = threadIdx.x;
        float s = 0.f;
        for (int d = 0; d < 256; d++) s = fmaf(qW[d*256 + e], kW[d*256 + j], s);
        g_Wqk[j*256 + e] = tf32r(s);
        if (e == 0){
            float bq = 0.f;
            for (int d = 0; d < 256; d++) bq = fmaf(qb[d], kW[d*256 + j], bq);
            g_bqk[j] = bq;
        }
        return;
    } blk -= PB_QK;
    if (blk < PB_BIAS){
        int i = blk*256 + threadIdx.x;
        if (i < 768){
            int src = (i < 256) ? i : i + 256;
            g_bigo[i] = bih[src] + bhh[src];
        } else if (i < 1536){
            int n = i - 768;
            g_bozh[n] = (n < 256) ? zb[n] : (n < 512) ? rb[n-256] : hb[n-512];
        }
        return;
    } blk -= PB_BIAS;
    if (blk < PB_WIGO){
        int i = blk*256 + threadIdx.x;
        int n = i >> 9, k = i & 511;
        int src = (n < 256) ? n : n + 256;
        g_Wigo[i] = tf32r(Wih[(size_t)src*512 + k]);
        return;
    } blk -= PB_WIGO;
    if (blk < PB_WZRM){
        int i = blk*256 + threadIdx.x;
        int n = i >> 8, k = i & 255;
        float v = (n < 256) ? zW[(size_t)n*512 + k] : rW[(size_t)(n-256)*512 + k];
        g_Wzrm[i] = tf32r(v);
        return;
    } blk -= PB_WZRM;
    if (blk < PB_WHM){
        int i = blk*256 + threadIdx.x;
        int n = i >> 8, k = i & 255;
        g_Whm[i] = tf32r(hW[(size_t)n*512 + k]);
        return;
    } blk -= PB_WHM;
    if (blk < PB_WOZH){
        int i = blk*256 + threadIdx.x;
        int n = i >> 8, k = i & 255;
        float v = (n < 256) ? zW[(size_t)n*512 + 256 + k]
                : (n < 512) ? rW[(size_t)(n-256)*512 + 256 + k]
                            : hW[(size_t)(n-512)*512 + 256 + k];
        g_Wozh[i] = tf32r(v);
        return;
    } blk -= PB_WOZH;
    {
        int i = blk*256 + threadIdx.x;
        g_Wv[i] = tf32r(vW[i]);
    }
}

// ---------------- frame weighting ----------------
__global__ void k_frame(const float* __restrict__ O_t, const float* __restrict__ O_prev,
                        const float* __restrict__ wW, const float* __restrict__ wb,
                        float* __restrict__ out_Wt)
{
    int b = blockIdx.x, t = threadIdx.x;
    float ot = O_t[(size_t)b*256 + t];
    float op = O_prev[(size_t)b*256 + t];
    float dl = ot - op;
    float s0 = ot*ot, s1 = op*op, s2 = dl*dl, s3 = ot*op;
    #pragma unroll
    for (int off = 16; off; off >>= 1){
        s0 += __shfl_xor_sync(0xffffffffu, s0, off);
        s1 += __shfl_xor_sync(0xffffffffu, s1, off);
        s2 += __shfl_xor_sync(0xffffffffu, s2, off);
        s3 += __shfl_xor_sync(0xffffffffu, s3, off);
    }
    __shared__ float4 ws[8];
    __shared__ float4 tot;
    int w = t >> 5;
    if ((t & 31) == 0) ws[w] = make_float4(s0, s1, s2, s3);
    __syncthreads();
    if (t == 0){
        float4 r = ws[0];
        #pragma unroll
        for (int i = 1; i < 8; i++){ r.x += ws[i].x; r.y += ws[i].y; r.z += ws[i].z; r.w += ws[i].w; }
        tot = r;
    }
    __syncthreads();
    float n_t = sqrtf(tot.x), n_p = sqrtf(tot.y), rd = sqrtf(tot.z);
    float ra  = tot.w / (n_t*n_p + 1e-6f);
    float wt  = 0.5f*(tanhf(n_t*wW[t*3+0] + rd*wW[t*3+1] + ra*wW[t*3+2] + wb[t]) + 1.f);
    out_Wt[(size_t)b*256 + t] = wt;
    g_X[(size_t)b*512 + t]       = tf32r(op);
    g_X[(size_t)b*512 + 256 + t] = tf32r(ot * wt);
}

// ---------------- LSTM activations ----------------
__global__ void k_lstm_act(){
    size_t i = (size_t)blockIdx.x*256 + threadIdx.x;
    size_t b = i >> 8; int d = (int)(i & 255);
    float ig = g_gates[b*768 + d];
    float gg = g_gates[b*768 + 256 + d];
    float og = g_gates[b*768 + 512 + d];
    float c  = sigf(ig) * tanhf(gg);
    g_OTP[i] = tf32r(sigf(og) * tanhf(c));
}

// ---------------- attention (also emits rounded memory copy) ----------------
__global__ void k_attn(const float* __restrict__ memory){
    int b = blockIdx.x, t = threadIdx.x;
    float qk = g_QK[(size_t)b*256 + t];
    const float* mb = memory + (size_t)b*ML_*256;
    float* mr = g_MEMr + (size_t)b*ML_*256;
    float mv[ML_];
    __shared__ float sc[ML_];
    __shared__ float attn[ML_];
    if (t < ML_) sc[t] = 0.f;
    __syncthreads();
    #pragma unroll
    for (int m = 0; m < ML_; m++){
        mv[m] = mb[m*256 + t];
        if (m >= 1) mr[m*256 + t] = tf32r(mv[m]);   // only slots 1..9 feed the zr GEMM
        float v = qk * mv[m];
        #pragma unroll
        for (int off = 16; off; off >>= 1) v += __shfl_xor_sync(0xffffffffu, v, off);
        if ((t & 31) == 0) atomicAdd(&sc[m], v);
    }
    __syncthreads();
    if (t == 0){
        float mx = -1e30f;
        #pragma unroll
        for (int m = 0; m < ML_; m++){ sc[m] *= 0.0625f; mx = fmaxf(mx, sc[m]); }
        float e[ML_], s = 0.f;
        #pragma unroll
        for (int m = 0; m < ML_; m++){ e[m] = expf(sc[m] - mx); s += e[m]; }
        float inv = 1.f / s;
        #pragma unroll
        for (int m = 0; m < ML_; m++) attn[m] = e[m] * inv;
    }
    __syncthreads();
    float wm = 0.f;
    #pragma unroll
    for (int m = 0; m < ML_; m++) wm += attn[m] * mv[m];
    g_WM[(size_t)b*256 + t] = tf32r(wm);
}

// ---------------- launcher ----------------
extern "C" void kernel_launch(void* const* d_in, const int* in_sizes, int n_in,
                              void* d_out, int out_size)
{
    const float* O_t     = (const float*)d_in[0];
    const float* O_prev  = (const float*)d_in[1];
    const float* memory  = (const float*)d_in[2];
    const float* w_mlp_W = (const float*)d_in[3];
    const float* w_mlp_b = (const float*)d_in[4];
    const float* lstm_Wih= (const float*)d_in[5];
    const float* lstm_bih= (const float*)d_in[7];
    const float* lstm_bhh= (const float*)d_in[8];
    const float* q_W = (const float*)d_in[9];   const float* q_b = (const float*)d_in[10];
    const float* k_W = (const float*)d_in[11];  // k_b cancels in softmax
    const float* v_W = (const float*)d_in[13];  const float* v_b = (const float*)d_in[14];
    const float* z_W = (const float*)d_in[15];  const float* z_b = (const float*)d_in[16];
    const float* r_W = (const float*)d_in[17];  const float* r_b = (const float*)d_in[18];
    const float* h_W = (const float*)d_in[19];  const float* h_b = (const float*)d_in[20];

    float* out      = (float*)d_out;
    float* out0     = out;
    float* out_mem  = out0 + (size_t)B_*D_;
    float* out2     = out_mem + (size_t)B_*ML_*D_;
    float* out3     = out2 + (size_t)B_*D_;

    cudaFuncSetAttribute(k_mma<0,0>, cudaFuncAttributeMaxDynamicSharedMemorySize, SMEM_TOTAL);
    cudaFuncSetAttribute(k_mma<0,2>, cudaFuncAttributeMaxDynamicSharedMemorySize, SMEM_TOTAL);
    cudaFuncSetAttribute(k_mma<1,4>, cudaFuncAttributeMaxDynamicSharedMemorySize, SMEM_TOTAL);
    cudaFuncSetAttribute(k_mma<0,3>, cudaFuncAttributeMaxDynamicSharedMemorySize, SMEM_TOTAL);

    float *pX,*pGates,*pOTP,*pQK,*pWM,*pOUP,*pOZH,*pZs,*pRM,*pMEMr;
    float *pWigo,*pWqk,*pWv,*pWzrm,*pWhm,*pWozh,*pbigo,*pbozh,*pbqk;
    cudaGetSymbolAddress((void**)&pX,     g_X);
    cudaGetSymbolAddress((void**)&pGates, g_gates);
    cudaGetSymbolAddress((void**)&pOTP,   g_OTP);
    cudaGetSymbolAddress((void**)&pQK,    g_QK);
    cudaGetSymbolAddress((void**)&pWM,    g_WM);
    cudaGetSymbolAddress((void**)&pOUP,   g_OUP);
    cudaGetSymbolAddress((void**)&pOZH,   g_OZH);
    cudaGetSymbolAddress((void**)&pZs,    g_Zs);
    cudaGetSymbolAddress((void**)&pRM,    g_RM);
    cudaGetSymbolAddress((void**)&pMEMr,  g_MEMr);
    cudaGetSymbolAddress((void**)&pWigo,  g_Wigo);
    cudaGetSymbolAddress((void**)&pWqk,   g_Wqk);
    cudaGetSymbolAddress((void**)&pWv,    g_Wv);
    cudaGetSymbolAddress((void**)&pWzrm,  g_Wzrm);
    cudaGetSymbolAddress((void**)&pWhm,   g_Whm);
    cudaGetSymbolAddress((void**)&pWozh,  g_Wozh);
    cudaGetSymbolAddress((void**)&pbigo,  g_bigo);
    cudaGetSymbolAddress((void**)&pbozh,  g_bozh);
    cudaGetSymbolAddress((void**)&pbqk,   g_bqk);

    // 1: prep (rounded/remapped weights, Wqk, biases)
    k_prep<<<PB_TOTAL, 256>>>(q_W, k_W, q_b, lstm_Wih, lstm_bih, lstm_bhh,
                              v_W, z_W, r_W, h_W, z_b, r_b, h_b);
    // 2: frame weighting -> X (rounded) + W_t out
    k_frame<<<B_, 256>>>(O_t, O_prev, w_mlp_W, w_mlp_b, out3);
    // 3: LSTM gates [B,768], K=512
    k_mma<0,0><<<dim3(6, B_/128), 256, SMEM_TOTAL>>>(
        pX, nullptr, pWigo, 512, pbigo,
        pGates, nullptr, nullptr, nullptr, nullptr, nullptr, nullptr, nullptr,
        B_, 768, 512);
    // 4: LSTM activations -> OTP (rounded)
    k_lstm_act<<<B_, 256>>>();
    // 5: QK = OTP @ Wqk^T + bqk  [B,256]
    k_mma<0,0><<<dim3(2, B_/128), 256, SMEM_TOTAL>>>(
        pOTP, nullptr, pWqk, 256, pbqk,
        pQK, nullptr, nullptr, nullptr, nullptr, nullptr, nullptr, nullptr,
        B_, 256, 256);
    // 6: attention -> WM (rounded) + MEMr (rounded memory copy)
    k_attn<<<B_, 256>>>(memory);
    // 7: V GEMM -> OUP (rounded) + out0/out2/mem slot 9 (exact)
    k_mma<0,2><<<dim3(2, B_/128), 256, SMEM_TOTAL>>>(
        pWM, nullptr, pWv, 256, v_b,
        pOUP, out0, out_mem, out2, nullptr, nullptr, nullptr, nullptr,
        B_, 256, 256);
    // 8: OZH = O_up @ Wozh^T + bozh  [B,768]
    k_mma<0,0><<<dim3(6, B_/128), 256, SMEM_TOTAL>>>(
        pOUP, nullptr, pWozh, 256, pbozh,
        pOZH, nullptr, nullptr, nullptr, nullptr, nullptr, nullptr, nullptr,
        B_, 768, 256);
    // 9: zr GEMM (rounded memory as A) [M2,512]; epi: +OZH, Zs=sig(z), RM=sig(r)*mem (rounded)
    k_mma<1,4><<<dim3(4, M2_/128), 256, SMEM_TOTAL>>>(
        nullptr, pMEMr, pWzrm, 256, nullptr,
        nullptr, nullptr, nullptr, nullptr, pOZH, pZs, pRM, memory,
        M2_, 512, 256);
    // 10: h GEMM (rm half) [M2,256]; epi: +OZH, tanh, z-combine, shifted write
    k_mma<0,3><<<dim3(2, M2_/128), 256, SMEM_TOTAL>>>(
        pRM, nullptr, pWhm, 256, nullptr,
        nullptr, nullptr, out_mem, nullptr, pOZH, pZs, nullptr, memory,
        M2_, 256, 256);
}

// round 9
// speedup vs baseline: 5.1101x; 1.3012x over previous
#include <cuda_runtime.h>
#include <cuda_fp16.h>
#include <math.h>
#include <stdint.h>

#define B_   16384
#define D_   256
#define ML_  10
#define M2_  (B_*9)

typedef __half h16;

// ---------------- fp32 scratch ----------------
__device__ __align__(256) float g_gates[(size_t)B_*768];
__device__ __align__(256) float g_QK   [(size_t)B_*256];
__device__ __align__(256) float g_OZH  [(size_t)B_*768];
__device__ __align__(256) float g_Zs   [(size_t)M2_*256];  // sigmoid(z), exact
// ---------------- fp16 GEMM operand scratch ----------------
__device__ __align__(256) h16 g_X   [(size_t)B_*512];
__device__ __align__(256) h16 g_OTP [(size_t)B_*256];
__device__ __align__(256) h16 g_WM  [(size_t)B_*256];
__device__ __align__(256) h16 g_OUP [(size_t)B_*256];
__device__ __align__(256) h16 g_MEMh[(size_t)B_*ML_*256];
__device__ __align__(256) h16 g_RM  [(size_t)M2_*256];
// ---------------- fp16 weights ----------------
__device__ __align__(256) h16 g_Wigo [768*512];
__device__ __align__(256) h16 g_Wqk  [65536];
__device__ __align__(256) h16 g_Wv   [65536];
__device__ __align__(256) h16 g_Wzrm [512*256];
__device__ __align__(256) h16 g_Whm  [256*256];
__device__ __align__(256) h16 g_Wozh [768*256];
__device__ __align__(256) float g_bigo[768];
__device__ __align__(256) float g_bozh[768];
__device__ __align__(256) float g_bqk [256];

__device__ __forceinline__ float sigf(float x){ return 1.f/(1.f+expf(-x)); }

// ---------------- PTX helpers (base ISA only) ----------------
__device__ __forceinline__ uint32_t smem_u32(const void* p){
    uint32_t a; asm("{ .reg .u64 t; cvta.to.shared.u64 t, %1; cvt.u32.u64 %0, t; }" : "=r"(a) : "l"(p));
    return a;
}
__device__ __forceinline__ void ldsm4(uint32_t* r, uint32_t addr){
    asm volatile("ldmatrix.sync.aligned.m8n8.x4.shared.b16 {%0,%1,%2,%3}, [%4];"
        : "=r"(r[0]),"=r"(r[1]),"=r"(r[2]),"=r"(r[3]) : "r"(addr));
}
__device__ __forceinline__ void mma_f16(float* c, const uint32_t* a, const uint32_t* b){
    asm volatile("mma.sync.aligned.m16n8k16.row.col.f32.f16.f16.f32 "
        "{%0,%1,%2,%3}, {%4,%5,%6,%7}, {%8,%9}, {%0,%1,%2,%3};"
        : "+f"(c[0]),"+f"(c[1]),"+f"(c[2]),"+f"(c[3])
        : "r"(a[0]),"r"(a[1]),"r"(a[2]),"r"(a[3]), "r"(b[0]),"r"(b[1]));
}
__device__ __forceinline__ void cpa16(uint32_t dst, const void* src){
    asm volatile("cp.async.cg.shared.global [%0], [%1], 16;" :: "r"(dst), "l"(src));
}
#define CP_COMMIT() asm volatile("cp.async.commit_group;" ::: "memory")
#define CP_WAIT1()  asm volatile("cp.async.wait_group 1;"  ::: "memory")

// SMEM per stage: A 128 rows x 144B (=64 fp16 + pad) ; W same ; 36864/stage, 3 stages
// 110592 B/CTA -> 2 CTAs/SM
#define ROWB     144
#define STAGE_SZ 36864
#define SMEM_TOTAL (3*STAGE_SZ)

// ================== fp16 HMMA GEMM: C[M,N] = A[M,K] @ W[N,K]^T ==================
// CTA 128x128, 8 warps (2x4), warp tile 64x32, K-chunk 64, 3-stage cp.async, 2 CTAs/SM.
// AMODE 0: A row r -> A + (m0+r)*K
// AMODE 1: A row r -> b=r/9, m=r%9+1 -> Amem + (b*10+m)*256   (fp16 memory copy)
// EPI 0: C = v + bias[col]  (fp32)
// EPI 2: V-mode: v+=bias; fp16(v) -> C16(=OUP); v -> out0, out2, out_mem slot 9
// EPI 3: h-mode: v += ozh[b*768+512+col]; mt=tanh(v); z=zs;
//        out_mem[b,m-1,col] = z*memory[b,m,col] + (1-z)*mt
// EPI 4: zr-mode: v += ozh[b*768+col]; col<256 -> zs=sig(v); else rm16=sig(v)*mem
template<int AMODE,int EPI>
__global__ void __launch_bounds__(256,2) k_mma(
    const h16* __restrict__ A, const h16* __restrict__ Amem,
    const h16* __restrict__ W,
    const float* __restrict__ bias,
    float* __restrict__ C, h16* __restrict__ C16,
    float* __restrict__ out0, float* __restrict__ out_mem, float* __restrict__ out2,
    const float* __restrict__ ozh, float* __restrict__ zs, h16* __restrict__ rm,
    const float* __restrict__ memory,
    int M, int N, int K)
{
    extern __shared__ char smem[];
    uint32_t sb = smem_u32(smem);
    const int tid = threadIdx.x, lane = tid & 31, w = tid >> 5;
    const int wm = w >> 2, wn = w & 3;
    const int m0 = blockIdx.y * 128, n0 = blockIdx.x * 128;
    const int nch = K >> 6;

    float acc[4][4][4];
    #pragma unroll
    for (int i=0;i<4;i++)
        #pragma unroll
        for (int j=0;j<4;j++)
            #pragma unroll
            for (int k=0;k<4;k++) acc[i][j][k]=0.f;

    auto aptr = [&](int row, int gk)->const h16*{
        if (AMODE == 0) return A + (size_t)(m0+row)*K + gk;
        int rr = m0 + row, b = rr/9, m = rr - b*9 + 1;
        return Amem + ((size_t)b*10 + m)*256 + gk;
    };
    auto load_chunk = [&](int c, int s){
        uint32_t st = sb + s*STAGE_SZ;
        #pragma unroll
        for (int t=0;t<4;t++){
            int u = tid + t*256;
            int row = u >> 3, q = u & 7;
            cpa16(st + row*ROWB + q*16, aptr(row, c*64 + q*8));
        }
        #pragma unroll
        for (int t=0;t<4;t++){
            int u = tid + t*256;
            int row = u >> 3, q = u & 7;
            cpa16(st + 18432 + row*ROWB + q*16, W + (size_t)(n0+row)*K + c*64 + q*8);
        }
        CP_COMMIT();
    };

    load_chunk(0, 0);
    load_chunk(1, 1);

    for (int c = 0; c < nch; c++){
        CP_WAIT1();
        __syncthreads();
        if (c + 2 < nch) load_chunk(c + 2, (c + 2) % 3);

        uint32_t sA = sb + (c % 3)*STAGE_SZ;
        uint32_t sW = sA + 18432;
        #pragma unroll
        for (int kk = 0; kk < 4; kk++){
            uint32_t a[4][4];
            #pragma unroll
            for (int i = 0; i < 4; i++){
                int rl = wm*64 + i*16 + (lane & 7) + ((lane & 8) ? 8 : 0);
                uint32_t colb = kk*32 + ((lane & 16) ? 16 : 0);
                ldsm4(a[i], sA + rl*ROWB + colb);
            }
            uint32_t bf[4][2];
            #pragma unroll
            for (int jp = 0; jp < 2; jp++){
                int nl = wn*32 + jp*16 + (lane & 7) + ((lane & 16) ? 8 : 0);
                uint32_t colb = kk*32 + ((lane & 8) ? 16 : 0);
                uint32_t t4[4];
                ldsm4(t4, sW + nl*ROWB + colb);
                bf[2*jp][0]=t4[0]; bf[2*jp][1]=t4[1]; bf[2*jp+1][0]=t4[2]; bf[2*jp+1][1]=t4[3];
            }
            #pragma unroll
            for (int i=0;i<4;i++)
                #pragma unroll
                for (int j=0;j<4;j++) mma_f16(acc[i][j], a[i], bf[j]);
        }
        __syncthreads();
    }

    // ---- epilogue ----
    #pragma unroll
    for (int j = 0; j < 4; j++){
        int col = n0 + wn*32 + j*8 + (lane & 3)*2;
        float b0 = 0.f, b1 = 0.f;
        if (EPI == 0 || EPI == 2){
            if (bias){ b0 = bias[col]; b1 = bias[col+1]; }
        }
        #pragma unroll
        for (int i = 0; i < 4; i++){
            int row = m0 + wm*64 + i*16 + (lane >> 2);
            #pragma unroll
            for (int h = 0; h < 2; h++){
                int rr = row + h*8;
                float v0 = acc[i][j][2*h+0] + b0;
                float v1 = acc[i][j][2*h+1] + b1;
                if (EPI == 0){
                    *reinterpret_cast<float2*>(C + (size_t)rr*N + col) = make_float2(v0, v1);
                } else if (EPI == 2){
                    size_t o = (size_t)rr*256 + col;
                    float2 fv = make_float2(v0, v1);
                    *reinterpret_cast<__half2*>(C16 + o) = __floats2half2_rn(v0, v1);
                    *reinterpret_cast<float2*>(out0 + o) = fv;
                    *reinterpret_cast<float2*>(out2 + o) = fv;
                    *reinterpret_cast<float2*>(out_mem + (size_t)rr*(ML_*256) + 9*256 + col) = fv;
                } else if (EPI == 3){
                    int b = rr/9, m = rr - b*9 + 1;
                    float2 oz = *reinterpret_cast<const float2*>(ozh + (size_t)b*768 + 512 + col);
                    float mt0 = tanhf(v0 + oz.x), mt1 = tanhf(v1 + oz.y);
                    float2 zv = *reinterpret_cast<const float2*>(zs + (size_t)rr*256 + col);
                    float2 mv = *reinterpret_cast<const float2*>(memory + ((size_t)b*ML_ + m)*256 + col);
                    float r0 = zv.x*mv.x + (1.f - zv.x)*mt0;
                    float r1 = zv.y*mv.y + (1.f - zv.y)*mt1;
                    *reinterpret_cast<float2*>(out_mem + (size_t)b*(ML_*256) + (size_t)(m-1)*256 + col) = make_float2(r0, r1);
                } else {  // EPI 4
                    int b = rr/9, m = rr - b*9 + 1;
                    float2 oz = *reinterpret_cast<const float2*>(ozh + (size_t)b*768 + col);
                    float s0 = sigf(v0 + oz.x), s1 = sigf(v1 + oz.y);
                    if (col < 256){
                        *reinterpret_cast<float2*>(zs + (size_t)rr*256 + col) = make_float2(s0, s1);
                    } else {
                        int cc = col - 256;
                        float2 mv = *reinterpret_cast<const float2*>(memory + ((size_t)b*ML_ + m)*256 + cc);
                        *reinterpret_cast<__half2*>(rm + (size_t)rr*256 + cc) =
                            __floats2half2_rn(s0*mv.x, s1*mv.y);
                    }
                }
            }
        }
    }
}

// ---------------- prep: fp16 weights + Wqk + biases ----------------
#define PB_QK   256
#define PB_BIAS 6
#define PB_WIGO 1536
#define PB_WZRM 512
#define PB_WHM  256
#define PB_WOZH 768
#define PB_WV   256
#define PB_TOTAL (PB_QK+PB_BIAS+PB_WIGO+PB_WZRM+PB_WHM+PB_WOZH+PB_WV)

__global__ void k_prep(const float* __restrict__ qW, const float* __restrict__ kW,
                       const float* __restrict__ qb,
                       const float* __restrict__ Wih,
                       const float* __restrict__ bih, const float* __restrict__ bhh,
                       const float* __restrict__ vW,
                       const float* __restrict__ zW, const float* __restrict__ rW,
                       const float* __restrict__ hW,
                       const float* __restrict__ zb, const float* __restrict__ rb,
                       const float* __restrict__ hb)
{
    int blk = blockIdx.x;
    if (blk < PB_QK){
        int j = blk, e = threadIdx.x;
        float s = 0.f;
        for (int d = 0; d < 256; d++) s = fmaf(qW[d*256 + e], kW[d*256 + j], s);
        g_Wqk[j*256 + e] = __float2half_rn(s);
        if (e == 0){
            float bq = 0.f;
            for (int d = 0; d < 256; d++) bq = fmaf(qb[d], kW[d*256 + j], bq);
            g_bqk[j] = bq;
        }
        return;
    } blk -= PB_QK;
    if (blk < PB_BIAS){
        int i = blk*256 + threadIdx.x;
        if (i < 768){
            int src = (i < 256) ? i : i + 256;
            g_bigo[i] = bih[src] + bhh[src];
        } else if (i < 1536){
            int n = i - 768;
            g_bozh[n] = (n < 256) ? zb[n] : (n < 512) ? rb[n-256] : hb[n-512];
        }
        return;
    } blk -= PB_BIAS;
    if (blk < PB_WIGO){
        int i = blk*256 + threadIdx.x;
        int n = i >> 9, k = i & 511;
        int src = (n < 256) ? n : n + 256;
        g_Wigo[i] = __float2half_rn(Wih[(size_t)src*512 + k]);
        return;
    } blk -= PB_WIGO;
    if (blk < PB_WZRM){
        int i = blk*256 + threadIdx.x;
        int n = i >> 8, k = i & 255;
        float v = (n < 256) ? zW[(size_t)n*512 + k] : rW[(size_t)(n-256)*512 + k];
        g_Wzrm[i] = __float2half_rn(v);
        return;
    } blk -= PB_WZRM;
    if (blk < PB_WHM){
        int i = blk*256 + threadIdx.x;
        int n = i >> 8, k = i & 255;
        g_Whm[i] = __float2half_rn(hW[(size_t)n*512 + k]);
        return;
    } blk -= PB_WHM;
    if (blk < PB_WOZH){
        int i = blk*256 + threadIdx.x;
        int n = i >> 8, k = i & 255;
        float v = (n < 256) ? zW[(size_t)n*512 + 256 + k]
                : (n < 512) ? rW[(size_t)(n-256)*512 + 256 + k]
                            : hW[(size_t)(n-512)*512 + 256 + k];
        g_Wozh[i] = __float2half_rn(v);
        return;
    } blk -= PB_WOZH;
    {
        int i = blk*256 + threadIdx.x;
        g_Wv[i] = __float2half_rn(vW[i]);
    }
}

// ---------------- frame weighting ----------------
__global__ void k_frame(const float* __restrict__ O_t, const float* __restrict__ O_prev,
                        const float* __restrict__ wW, const float* __restrict__ wb,
                        float* __restrict__ out_Wt)
{
    int b = blockIdx.x, t = threadIdx.x;
    float ot = O_t[(size_t)b*256 + t];
    float op = O_prev[(size_t)b*256 + t];
    float dl = ot - op;
    float s0 = ot*ot, s1 = op*op, s2 = dl*dl, s3 = ot*op;
    #pragma unroll
    for (int off = 16; off; off >>= 1){
        s0 += __shfl_xor_sync(0xffffffffu, s0, off);
        s1 += __shfl_xor_sync(0xffffffffu, s1, off);
        s2 += __shfl_xor_sync(0xffffffffu, s2, off);
        s3 += __shfl_xor_sync(0xffffffffu, s3, off);
    }
    __shared__ float4 ws[8];
    __shared__ float4 tot;
    int w = t >> 5;
    if ((t & 31) == 0) ws[w] = make_float4(s0, s1, s2, s3);
    __syncthreads();
    if (t == 0){
        float4 r = ws[0];
        #pragma unroll
        for (int i = 1; i < 8; i++){ r.x += ws[i].x; r.y += ws[i].y; r.z += ws[i].z; r.w += ws[i].w; }
        tot = r;
    }
    __syncthreads();
    float n_t = sqrtf(tot.x), n_p = sqrtf(tot.y), rd = sqrtf(tot.z);
    float ra  = tot.w / (n_t*n_p + 1e-6f);
    float wt  = 0.5f*(tanhf(n_t*wW[t*3+0] + rd*wW[t*3+1] + ra*wW[t*3+2] + wb[t]) + 1.f);
    out_Wt[(size_t)b*256 + t] = wt;
    g_X[(size_t)b*512 + t]       = __float2half_rn(op);
    g_X[(size_t)b*512 + 256 + t] = __float2half_rn(ot * wt);
}

// ---------------- LSTM activations ----------------
__global__ void k_lstm_act(){
    size_t i = (size_t)blockIdx.x*256 + threadIdx.x;
    size_t b = i >> 8; int d = (int)(i & 255);
    float ig = g_gates[b*768 + d];
    float gg = g_gates[b*768 + 256 + d];
    float og = g_gates[b*768 + 512 + d];
    float c  = sigf(ig) * tanhf(gg);
    g_OTP[i] = __float2half_rn(sigf(og) * tanhf(c));
}

// ---------------- attention (also emits fp16 memory copy, slots 1..9) ----------------
__global__ void k_attn(const float* __restrict__ memory){
    int b = blockIdx.x, t = threadIdx.x;
    float qk = g_QK[(size_t)b*256 + t];
    const float* mb = memory + (size_t)b*ML_*256;
    h16* mh = g_MEMh + (size_t)b*ML_*256;
    float mv[ML_];
    __shared__ float sc[ML_];
    __shared__ float attn[ML_];
    if (t < ML_) sc[t] = 0.f;
    __syncthreads();
    #pragma unroll
    for (int m = 0; m < ML_; m++){
        mv[m] = mb[m*256 + t];
        if (m >= 1) mh[m*256 + t] = __float2half_rn(mv[m]);
        float v = qk * mv[m];
        #pragma unroll
        for (int off = 16; off; off >>= 1) v += __shfl_xor_sync(0xffffffffu, v, off);
        if ((t & 31) == 0) atomicAdd(&sc[m], v);
    }
    __syncthreads();
    if (t == 0){
        float mx = -1e30f;
        #pragma unroll
        for (int m = 0; m < ML_; m++){ sc[m] *= 0.0625f; mx = fmaxf(mx, sc[m]); }
        float e[ML_], s = 0.f;
        #pragma unroll
        for (int m = 0; m < ML_; m++){ e[m] = expf(sc[m] - mx); s += e[m]; }
        float inv = 1.f / s;
        #pragma unroll
        for (int m = 0; m < ML_; m++) attn[m] = e[m] * inv;
    }
    __syncthreads();
    float wm = 0.f;
    #pragma unroll
    for (int m = 0; m < ML_; m++) wm += attn[m] * mv[m];
    g_WM[(size_t)b*256 + t] = __float2half_rn(wm);
}

// ---------------- launcher ----------------
extern "C" void kernel_launch(void* const* d_in, const int* in_sizes, int n_in,
                              void* d_out, int out_size)
{
    const float* O_t     = (const float*)d_in[0];
    const float* O_prev  = (const float*)d_in[1];
    const float* memory  = (const float*)d_in[2];
    const float* w_mlp_W = (const float*)d_in[3];
    const float* w_mlp_b = (const float*)d_in[4];
    const float* lstm_Wih= (const float*)d_in[5];
    const float* lstm_bih= (const float*)d_in[7];
    const float* lstm_bhh= (const float*)d_in[8];
    const float* q_W = (const float*)d_in[9];   const float* q_b = (const float*)d_in[10];
    const float* k_W = (const float*)d_in[11];  // k_b cancels in softmax
    const float* v_W = (const float*)d_in[13];  const float* v_b = (const float*)d_in[14];
    const float* z_W = (const float*)d_in[15];  const float* z_b = (const float*)d_in[16];
    const float* r_W = (const float*)d_in[17];  const float* r_b = (const float*)d_in[18];
    const float* h_W = (const float*)d_in[19];  const float* h_b = (const float*)d_in[20];

    float* out      = (float*)d_out;
    float* out0     = out;
    float* out_mem  = out0 + (size_t)B_*D_;
    float* out2     = out_mem + (size_t)B_*ML_*D_;
    float* out3     = out2 + (size_t)B_*D_;

    cudaFuncSetAttribute(k_mma<0,0>, cudaFuncAttributeMaxDynamicSharedMemorySize, SMEM_TOTAL);
    cudaFuncSetAttribute(k_mma<0,2>, cudaFuncAttributeMaxDynamicSharedMemorySize, SMEM_TOTAL);
    cudaFuncSetAttribute(k_mma<1,4>, cudaFuncAttributeMaxDynamicSharedMemorySize, SMEM_TOTAL);
    cudaFuncSetAttribute(k_mma<0,3>, cudaFuncAttributeMaxDynamicSharedMemorySize, SMEM_TOTAL);

    float *pGates,*pQK,*pOZH,*pZs,*pbigo,*pbozh,*pbqk;
    h16 *pX,*pOTP,*pWM,*pOUP,*pMEMh,*pRM,*pWigo,*pWqk,*pWv,*pWzrm,*pWhm,*pWozh;
    cudaGetSymbolAddress((void**)&pGates, g_gates);
    cudaGetSymbolAddress((void**)&pQK,    g_QK);
    cudaGetSymbolAddress((void**)&pOZH,   g_OZH);
    cudaGetSymbolAddress((void**)&pZs,    g_Zs);
    cudaGetSymbolAddress((void**)&pbigo,  g_bigo);
    cudaGetSymbolAddress((void**)&pbozh,  g_bozh);
    cudaGetSymbolAddress((void**)&pbqk,   g_bqk);
    cudaGetSymbolAddress((void**)&pX,     g_X);
    cudaGetSymbolAddress((void**)&pOTP,   g_OTP);
    cudaGetSymbolAddress((void**)&pWM,    g_WM);
    cudaGetSymbolAddress((void**)&pOUP,   g_OUP);
    cudaGetSymbolAddress((void**)&pMEMh,  g_MEMh);
    cudaGetSymbolAddress((void**)&pRM,    g_RM);
    cudaGetSymbolAddress((void**)&pWigo,  g_Wigo);
    cudaGetSymbolAddress((void**)&pWqk,   g_Wqk);
    cudaGetSymbolAddress((void**)&pWv,    g_Wv);
    cudaGetSymbolAddress((void**)&pWzrm,  g_Wzrm);
    cudaGetSymbolAddress((void**)&pWhm,   g_Whm);
    cudaGetSymbolAddress((void**)&pWozh,  g_Wozh);

    // 1: prep (fp16 weights, Wqk, biases)
    k_prep<<<PB_TOTAL, 256>>>(q_W, k_W, q_b, lstm_Wih, lstm_bih, lstm_bhh,
                              v_W, z_W, r_W, h_W, z_b, r_b, h_b);
    // 2: frame weighting -> X (fp16) + W_t out
    k_frame<<<B_, 256>>>(O_t, O_prev, w_mlp_W, w_mlp_b, out3);
    // 3: LSTM gates [B,768], K=512
    k_mma<0,0><<<dim3(6, B_/128), 256, SMEM_TOTAL>>>(
        pX, nullptr, pWigo, pbigo,
        pGates, nullptr, nullptr, nullptr, nullptr, nullptr, nullptr, nullptr, nullptr,
        B_, 768, 512);
    // 4: LSTM activations -> OTP (fp16)
    k_lstm_act<<<B_, 256>>>();
    // 5: QK = OTP @ Wqk^T + bqk  [B,256]
    k_mma<0,0><<<dim3(2, B_/128), 256, SMEM_TOTAL>>>(
        pOTP, nullptr, pWqk, pbqk,
        pQK, nullptr, nullptr, nullptr, nullptr, nullptr, nullptr, nullptr, nullptr,
        B_, 256, 256);
    // 6: attention -> WM (fp16) + MEMh (fp16 memory copy)
    k_attn<<<B_, 256>>>(memory);
    // 7: V GEMM -> OUP (fp16) + out0/out2/mem slot 9 (exact fp32)
    k_mma<0,2><<<dim3(2, B_/128), 256, SMEM_TOTAL>>>(
        pWM, nullptr, pWv, v_b,
        nullptr, pOUP, out0, out_mem, out2, nullptr, nullptr, nullptr, nullptr,
        B_, 256, 256);
    // 8: OZH = O_up @ Wozh^T + bozh  [B,768]
    k_mma<0,0><<<dim3(6, B_/128), 256, SMEM_TOTAL>>>(
        pOUP, nullptr, pWozh, pbozh,
        pOZH, nullptr, nullptr, nullptr, nullptr, nullptr, nullptr, nullptr, nullptr,
        B_, 768, 256);
    // 9: zr GEMM (fp16 memory as A) [M2,512]; epi: +OZH, Zs=sig(z), RM=sig(r)*mem (fp16)
    k_mma<1,4><<<dim3(4, M2_/128), 256, SMEM_TOTAL>>>(
        nullptr, pMEMh, pWzrm, nullptr,
        nullptr, nullptr, nullptr, nullptr, nullptr, pOZH, pZs, pRM, memory,
        M2_, 512, 256);
    // 10: h GEMM (rm half) [M2,256]; epi: +OZH, tanh, z-combine, shifted write
    k_mma<0,3><<<dim3(2, M2_/128), 256, SMEM_TOTAL>>>(
        pRM, nullptr, pWhm, nullptr,
        nullptr, nullptr, nullptr, out_mem, nullptr, pOZH, pZs, nullptr, memory,
        M2_, 256, 256);
}

// round 10
// speedup vs baseline: 5.7014x; 1.1157x over previous
#include <cuda_runtime.h>
#include <cuda_fp16.h>
#include <math.h>
#include <stdint.h>

#define B_   16384
#define D_   256
#define ML_  10
#define M2_  (B_*9)

typedef __half h16;

// ---------------- fp32 scratch ----------------
__device__ __align__(256) float g_QK   [(size_t)B_*256];
// ---------------- fp16 scratch ----------------
__device__ __align__(256) h16 g_gates[(size_t)B_*768];
__device__ __align__(256) h16 g_OZH  [(size_t)B_*768];
__device__ __align__(256) h16 g_Zs   [(size_t)M2_*256];
__device__ __align__(256) h16 g_X   [(size_t)B_*512];
__device__ __align__(256) h16 g_OTP [(size_t)B_*256];
__device__ __align__(256) h16 g_WM  [(size_t)B_*256];
__device__ __align__(256) h16 g_OUP [(size_t)B_*256];
__device__ __align__(256) h16 g_MEMh[(size_t)B_*ML_*256];
__device__ __align__(256) h16 g_RM  [(size_t)M2_*256];
// ---------------- fp16 weights ----------------
__device__ __align__(256) h16 g_Wigo [768*512];
__device__ __align__(256) h16 g_Wqk  [65536];
__device__ __align__(256) h16 g_Wv   [65536];
__device__ __align__(256) h16 g_Wzrm [512*256];
__device__ __align__(256) h16 g_Whm  [256*256];
__device__ __align__(256) h16 g_Wozh [768*256];
__device__ __align__(256) float g_bigo[768];
__device__ __align__(256) float g_bozh[768];
__device__ __align__(256) float g_bqk [256];

__device__ __forceinline__ float sigf(float x){ return 1.f/(1.f+expf(-x)); }

// ---------------- PTX helpers (base ISA only) ----------------
__device__ __forceinline__ uint32_t smem_u32(const void* p){
    uint32_t a; asm("{ .reg .u64 t; cvta.to.shared.u64 t, %1; cvt.u32.u64 %0, t; }" : "=r"(a) : "l"(p));
    return a;
}
__device__ __forceinline__ void ldsm4(uint32_t* r, uint32_t addr){
    asm volatile("ldmatrix.sync.aligned.m8n8.x4.shared.b16 {%0,%1,%2,%3}, [%4];"
        : "=r"(r[0]),"=r"(r[1]),"=r"(r[2]),"=r"(r[3]) : "r"(addr));
}
__device__ __forceinline__ void mma_f16(float* c, const uint32_t* a, const uint32_t* b){
    asm volatile("mma.sync.aligned.m16n8k16.row.col.f32.f16.f16.f32 "
        "{%0,%1,%2,%3}, {%4,%5,%6,%7}, {%8,%9}, {%0,%1,%2,%3};"
        : "+f"(c[0]),"+f"(c[1]),"+f"(c[2]),"+f"(c[3])
        : "r"(a[0]),"r"(a[1]),"r"(a[2]),"r"(a[3]), "r"(b[0]),"r"(b[1]));
}
__device__ __forceinline__ void cpa16(uint32_t dst, const void* src){
    asm volatile("cp.async.cg.shared.global [%0], [%1], 16;" :: "r"(dst), "l"(src));
}
#define CP_COMMIT() asm volatile("cp.async.commit_group;" ::: "memory")
#define CP_WAIT1()  asm volatile("cp.async.wait_group 1;"  ::: "memory")

#define ROWB     144
#define STAGE_SZ 36864
#define SMEM_TOTAL (3*STAGE_SZ)

// ================== fp16 HMMA GEMM: C[M,N] = A[M,K] @ W[N,K]^T ==================
// CTA 128x128, 8 warps (2x4), warp tile 64x32, K-chunk 64, 3-stage cp.async, 2 CTAs/SM.
// AMODE 0: A row r -> A + (m0+r)*K
// AMODE 1: A row r -> b=r/9, m=r%9+1 -> Amem + (b*10+m)*256   (fp16 memory copy)
// EPI 0: C fp32 = v + bias[col]
// EPI 5: C16 fp16 = v + bias[col]
// EPI 2: V-mode: v+=bias; fp16(v) -> C16(=OUP); v -> out0, out2, out_mem slot 9
// EPI 3: h-mode: v += ozh16[b*768+512+col]; mt=tanh(v); z=zs16; mem=memh;
//        out_mem[b,m-1,col] = z*mem + (1-z)*mt
// EPI 4: zr-mode: v += ozh16[b*768+col]; col<256 -> zs16=sig(v); else rm16=sig(v)*memh
template<int AMODE,int EPI>
__global__ void __launch_bounds__(256,2) k_mma(
    const h16* __restrict__ A, const h16* __restrict__ Amem,
    const h16* __restrict__ W,
    const float* __restrict__ bias,
    float* __restrict__ C, h16* __restrict__ C16,
    float* __restrict__ out0, float* __restrict__ out_mem, float* __restrict__ out2,
    const h16* __restrict__ ozh, h16* __restrict__ zs, h16* __restrict__ rm,
    const h16* __restrict__ memh,
    int M, int N, int K)
{
    extern __shared__ char smem[];
    uint32_t sb = smem_u32(smem);
    const int tid = threadIdx.x, lane = tid & 31, w = tid >> 5;
    const int wm = w >> 2, wn = w & 3;
    const int m0 = blockIdx.y * 128, n0 = blockIdx.x * 128;
    const int nch = K >> 6;

    float acc[4][4][4];
    #pragma unroll
    for (int i=0;i<4;i++)
        #pragma unroll
        for (int j=0;j<4;j++)
            #pragma unroll
            for (int k=0;k<4;k++) acc[i][j][k]=0.f;

    auto aptr = [&](int row, int gk)->const h16*{
        if (AMODE == 0) return A + (size_t)(m0+row)*K + gk;
        int rr = m0 + row, b = rr/9, m = rr - b*9 + 1;
        return Amem + ((size_t)b*10 + m)*256 + gk;
    };
    auto load_chunk = [&](int c, int s){
        uint32_t st = sb + s*STAGE_SZ;
        #pragma unroll
        for (int t=0;t<4;t++){
            int u = tid + t*256;
            int row = u >> 3, q = u & 7;
            cpa16(st + row*ROWB + q*16, aptr(row, c*64 + q*8));
        }
        #pragma unroll
        for (int t=0;t<4;t++){
            int u = tid + t*256;
            int row = u >> 3, q = u & 7;
            cpa16(st + 18432 + row*ROWB + q*16, W + (size_t)(n0+row)*K + c*64 + q*8);
        }
        CP_COMMIT();
    };

    load_chunk(0, 0);
    load_chunk(1, 1);

    for (int c = 0; c < nch; c++){
        CP_WAIT1();
        __syncthreads();
        if (c + 2 < nch) load_chunk(c + 2, (c + 2) % 3);

        uint32_t sA = sb + (c % 3)*STAGE_SZ;
        uint32_t sW = sA + 18432;
        #pragma unroll
        for (int kk = 0; kk < 4; kk++){
            uint32_t a[4][4];
            #pragma unroll
            for (int i = 0; i < 4; i++){
                int rl = wm*64 + i*16 + (lane & 7) + ((lane & 8) ? 8 : 0);
                uint32_t colb = kk*32 + ((lane & 16) ? 16 : 0);
                ldsm4(a[i], sA + rl*ROWB + colb);
            }
            uint32_t bf[4][2];
            #pragma unroll
            for (int jp = 0; jp < 2; jp++){
                int nl = wn*32 + jp*16 + (lane & 7) + ((lane & 16) ? 8 : 0);
                uint32_t colb = kk*32 + ((lane & 8) ? 16 : 0);
                uint32_t t4[4];
                ldsm4(t4, sW + nl*ROWB + colb);
                bf[2*jp][0]=t4[0]; bf[2*jp][1]=t4[1]; bf[2*jp+1][0]=t4[2]; bf[2*jp+1][1]=t4[3];
            }
            #pragma unroll
            for (int i=0;i<4;i++)
                #pragma unroll
                for (int j=0;j<4;j++) mma_f16(acc[i][j], a[i], bf[j]);
        }
        __syncthreads();
    }

    // ---- epilogue ----
    #pragma unroll
    for (int j = 0; j < 4; j++){
        int col = n0 + wn*32 + j*8 + (lane & 3)*2;
        float b0 = 0.f, b1 = 0.f;
        if (EPI == 0 || EPI == 2 || EPI == 5){
            if (bias){ b0 = bias[col]; b1 = bias[col+1]; }
        }
        #pragma unroll
        for (int i = 0; i < 4; i++){
            int row = m0 + wm*64 + i*16 + (lane >> 2);
            #pragma unroll
            for (int h = 0; h < 2; h++){
                int rr = row + h*8;
                float v0 = acc[i][j][2*h+0] + b0;
                float v1 = acc[i][j][2*h+1] + b1;
                if (EPI == 0){
                    *reinterpret_cast<float2*>(C + (size_t)rr*N + col) = make_float2(v0, v1);
                } else if (EPI == 5){
                    *reinterpret_cast<__half2*>(C16 + (size_t)rr*N + col) = __floats2half2_rn(v0, v1);
                } else if (EPI == 2){
                    size_t o = (size_t)rr*256 + col;
                    float2 fv = make_float2(v0, v1);
                    *reinterpret_cast<__half2*>(C16 + o) = __floats2half2_rn(v0, v1);
                    *reinterpret_cast<float2*>(out0 + o) = fv;
                    *reinterpret_cast<float2*>(out2 + o) = fv;
                    *reinterpret_cast<float2*>(out_mem + (size_t)rr*(ML_*256) + 9*256 + col) = fv;
                } else if (EPI == 3){
                    int b = rr/9, m = rr - b*9 + 1;
                    float2 oz = __half22float2(*reinterpret_cast<const __half2*>(ozh + (size_t)b*768 + 512 + col));
                    float mt0 = tanhf(v0 + oz.x), mt1 = tanhf(v1 + oz.y);
                    float2 zv = __half22float2(*reinterpret_cast<const __half2*>(zs + (size_t)rr*256 + col));
                    float2 mv = __half22float2(*reinterpret_cast<const __half2*>(memh + ((size_t)b*10 + m)*256 + col));
                    float r0 = zv.x*mv.x + (1.f - zv.x)*mt0;
                    float r1 = zv.y*mv.y + (1.f - zv.y)*mt1;
                    *reinterpret_cast<float2*>(out_mem + (size_t)b*(ML_*256) + (size_t)(m-1)*256 + col) = make_float2(r0, r1);
                } else {  // EPI 4
                    int b = rr/9, m = rr - b*9 + 1;
                    float2 oz = __half22float2(*reinterpret_cast<const __half2*>(ozh + (size_t)b*768 + col));
                    float s0 = sigf(v0 + oz.x), s1 = sigf(v1 + oz.y);
                    if (col < 256){
                        *reinterpret_cast<__half2*>(zs + (size_t)rr*256 + col) = __floats2half2_rn(s0, s1);
                    } else {
                        int cc = col - 256;
                        float2 mv = __half22float2(*reinterpret_cast<const __half2*>(memh + ((size_t)b*10 + m)*256 + cc));
                        *reinterpret_cast<__half2*>(rm + (size_t)rr*256 + cc) =
                            __floats2half2_rn(s0*mv.x, s1*mv.y);
                    }
                }
            }
        }
    }
}

// ---------------- prep: fp16 weights + Wqk + biases ----------------
#define PB_QK   256
#define PB_BIAS 6
#define PB_WIGO 1536
#define PB_WZRM 512
#define PB_WHM  256
#define PB_WOZH 768
#define PB_WV   256
#define PB_TOTAL (PB_QK+PB_BIAS+PB_WIGO+PB_WZRM+PB_WHM+PB_WOZH+PB_WV)

__global__ void k_prep(const float* __restrict__ qW, const float* __restrict__ kW,
                       const float* __restrict__ qb,
                       const float* __restrict__ Wih,
                       const float* __restrict__ bih, const float* __restrict__ bhh,
                       const float* __restrict__ vW,
                       const float* __restrict__ zW, const float* __restrict__ rW,
                       const float* __restrict__ hW,
                       const float* __restrict__ zb, const float* __restrict__ rb,
                       const float* __restrict__ hb)
{
    int blk = blockIdx.x;
    if (blk < PB_QK){
        int j = blk, e = threadIdx.x;
        float s = 0.f;
        for (int d = 0; d < 256; d++) s = fmaf(qW[d*256 + e], kW[d*256 + j], s);
        g_Wqk[j*256 + e] = __float2half_rn(s);
        if (e == 0){
            float bq = 0.f;
            for (int d = 0; d < 256; d++) bq = fmaf(qb[d], kW[d*256 + j], bq);
            g_bqk[j] = bq;
        }
        return;
    } blk -= PB_QK;
    if (blk < PB_BIAS){
        int i = blk*256 + threadIdx.x;
        if (i < 768){
            int src = (i < 256) ? i : i + 256;
            g_bigo[i] = bih[src] + bhh[src];
        } else if (i < 1536){
            int n = i - 768;
            g_bozh[n] = (n < 256) ? zb[n] : (n < 512) ? rb[n-256] : hb[n-512];
        }
        return;
    } blk -= PB_BIAS;
    if (blk < PB_WIGO){
        int i = blk*256 + threadIdx.x;
        int n = i >> 9, k = i & 511;
        int src = (n < 256) ? n : n + 256;
        g_Wigo[i] = __float2half_rn(Wih[(size_t)src*512 + k]);
        return;
    } blk -= PB_WIGO;
    if (blk < PB_WZRM){
        int i = blk*256 + threadIdx.x;
        int n = i >> 8, k = i & 255;
        float v = (n < 256) ? zW[(size_t)n*512 + k] : rW[(size_t)(n-256)*512 + k];
        g_Wzrm[i] = __float2half_rn(v);
        return;
    } blk -= PB_WZRM;
    if (blk < PB_WHM){
        int i = blk*256 + threadIdx.x;
        int n = i >> 8, k = i & 255;
        g_Whm[i] = __float2half_rn(hW[(size_t)n*512 + k]);
        return;
    } blk -= PB_WHM;
    if (blk < PB_WOZH){
        int i = blk*256 + threadIdx.x;
        int n = i >> 8, k = i & 255;
        float v = (n < 256) ? zW[(size_t)n*512 + 256 + k]
                : (n < 512) ? rW[(size_t)(n-256)*512 + 256 + k]
                            : hW[(size_t)(n-512)*512 + 256 + k];
        g_Wozh[i] = __float2half_rn(v);
        return;
    } blk -= PB_WOZH;
    {
        int i = blk*256 + threadIdx.x;
        g_Wv[i] = __float2half_rn(vW[i]);
    }
}

// ---------------- frame weighting ----------------
__global__ void k_frame(const float* __restrict__ O_t, const float* __restrict__ O_prev,
                        const float* __restrict__ wW, const float* __restrict__ wb,
                        float* __restrict__ out_Wt)
{
    int b = blockIdx.x, t = threadIdx.x;
    float ot = O_t[(size_t)b*256 + t];
    float op = O_prev[(size_t)b*256 + t];
    float dl = ot - op;
    float s0 = ot*ot, s1 = op*op, s2 = dl*dl, s3 = ot*op;
    #pragma unroll
    for (int off = 16; off; off >>= 1){
        s0 += __shfl_xor_sync(0xffffffffu, s0, off);
        s1 += __shfl_xor_sync(0xffffffffu, s1, off);
        s2 += __shfl_xor_sync(0xffffffffu, s2, off);
        s3 += __shfl_xor_sync(0xffffffffu, s3, off);
    }
    __shared__ float4 ws[8];
    __shared__ float4 tot;
    int w = t >> 5;
    if ((t & 31) == 0) ws[w] = make_float4(s0, s1, s2, s3);
    __syncthreads();
    if (t == 0){
        float4 r = ws[0];
        #pragma unroll
        for (int i = 1; i < 8; i++){ r.x += ws[i].x; r.y += ws[i].y; r.z += ws[i].z; r.w += ws[i].w; }
        tot = r;
    }
    __syncthreads();
    float n_t = sqrtf(tot.x), n_p = sqrtf(tot.y), rd = sqrtf(tot.z);
    float ra  = tot.w / (n_t*n_p + 1e-6f);
    float wt  = 0.5f*(tanhf(n_t*wW[t*3+0] + rd*wW[t*3+1] + ra*wW[t*3+2] + wb[t]) + 1.f);
    out_Wt[(size_t)b*256 + t] = wt;
    g_X[(size_t)b*512 + t]       = __float2half_rn(op);
    g_X[(size_t)b*512 + 256 + t] = __float2half_rn(ot * wt);
}

// ---------------- LSTM activations ----------------
__global__ void k_lstm_act(){
    size_t i = (size_t)blockIdx.x*256 + threadIdx.x;
    size_t b = i >> 8; int d = (int)(i & 255);
    float ig = __half2float(g_gates[b*768 + d]);
    float gg = __half2float(g_gates[b*768 + 256 + d]);
    float og = __half2float(g_gates[b*768 + 512 + d]);
    float c  = sigf(ig) * tanhf(gg);
    g_OTP[i] = __float2half_rn(sigf(og) * tanhf(c));
}

// ---------------- attention (also emits fp16 memory copy, slots 1..9) ----------------
__global__ void k_attn(const float* __restrict__ memory){
    int b = blockIdx.x, t = threadIdx.x;
    float qk = g_QK[(size_t)b*256 + t];
    const float* mb = memory + (size_t)b*ML_*256;
    h16* mh = g_MEMh + (size_t)b*ML_*256;
    float mv[ML_];
    __shared__ float sc[ML_];
    __shared__ float attn[ML_];
    if (t < ML_) sc[t] = 0.f;
    __syncthreads();
    #pragma unroll
    for (int m = 0; m < ML_; m++){
        mv[m] = mb[m*256 + t];
        if (m >= 1) mh[m*256 + t] = __float2half_rn(mv[m]);
        float v = qk * mv[m];
        #pragma unroll
        for (int off = 16; off; off >>= 1) v += __shfl_xor_sync(0xffffffffu, v, off);
        if ((t & 31) == 0) atomicAdd(&sc[m], v);
    }
    __syncthreads();
    if (t == 0){
        float mx = -1e30f;
        #pragma unroll
        for (int m = 0; m < ML_; m++){ sc[m] *= 0.0625f; mx = fmaxf(mx, sc[m]); }
        float e[ML_], s = 0.f;
        #pragma unroll
        for (int m = 0; m < ML_; m++){ e[m] = expf(sc[m] - mx); s += e[m]; }
        float inv = 1.f / s;
        #pragma unroll
        for (int m = 0; m < ML_; m++) attn[m] = e[m] * inv;
    }
    __syncthreads();
    float wm = 0.f;
    #pragma unroll
    for (int m = 0; m < ML_; m++) wm += attn[m] * mv[m];
    g_WM[(size_t)b*256 + t] = __float2half_rn(wm);
}

// ---------------- launcher ----------------
extern "C" void kernel_launch(void* const* d_in, const int* in_sizes, int n_in,
                              void* d_out, int out_size)
{
    const float* O_t     = (const float*)d_in[0];
    const float* O_prev  = (const float*)d_in[1];
    const float* memory  = (const float*)d_in[2];
    const float* w_mlp_W = (const float*)d_in[3];
    const float* w_mlp_b = (const float*)d_in[4];
    const float* lstm_Wih= (const float*)d_in[5];
    const float* lstm_bih= (const float*)d_in[7];
    const float* lstm_bhh= (const float*)d_in[8];
    const float* q_W = (const float*)d_in[9];   const float* q_b = (const float*)d_in[10];
    const float* k_W = (const float*)d_in[11];  // k_b cancels in softmax
    const float* v_W = (const float*)d_in[13];  const float* v_b = (const float*)d_in[14];
    const float* z_W = (const float*)d_in[15];  const float* z_b = (const float*)d_in[16];
    const float* r_W = (const float*)d_in[17];  const float* r_b = (const float*)d_in[18];
    const float* h_W = (const float*)d_in[19];  const float* h_b = (const float*)d_in[20];

    float* out      = (float*)d_out;
    float* out0     = out;
    float* out_mem  = out0 + (size_t)B_*D_;
    float* out2     = out_mem + (size_t)B_*ML_*D_;
    float* out3     = out2 + (size_t)B_*D_;

    cudaFuncSetAttribute(k_mma<0,0>, cudaFuncAttributeMaxDynamicSharedMemorySize, SMEM_TOTAL);
    cudaFuncSetAttribute(k_mma<0,5>, cudaFuncAttributeMaxDynamicSharedMemorySize, SMEM_TOTAL);
    cudaFuncSetAttribute(k_mma<0,2>, cudaFuncAttributeMaxDynamicSharedMemorySize, SMEM_TOTAL);
    cudaFuncSetAttribute(k_mma<1,4>, cudaFuncAttributeMaxDynamicSharedMemorySize, SMEM_TOTAL);
    cudaFuncSetAttribute(k_mma<0,3>, cudaFuncAttributeMaxDynamicSharedMemorySize, SMEM_TOTAL);

    float *pQK,*pbigo,*pbozh,*pbqk;
    h16 *pGates,*pOZH,*pZs,*pX,*pOTP,*pWM,*pOUP,*pMEMh,*pRM;
    h16 *pWigo,*pWqk,*pWv,*pWzrm,*pWhm,*pWozh;
    cudaGetSymbolAddress((void**)&pQK,    g_QK);
    cudaGetSymbolAddress((void**)&pbigo,  g_bigo);
    cudaGetSymbolAddress((void**)&pbozh,  g_bozh);
    cudaGetSymbolAddress((void**)&pbqk,   g_bqk);
    cudaGetSymbolAddress((void**)&pGates, g_gates);
    cudaGetSymbolAddress((void**)&pOZH,   g_OZH);
    cudaGetSymbolAddress((void**)&pZs,    g_Zs);
    cudaGetSymbolAddress((void**)&pX,     g_X);
    cudaGetSymbolAddress((void**)&pOTP,   g_OTP);
    cudaGetSymbolAddress((void**)&pWM,    g_WM);
    cudaGetSymbolAddress((void**)&pOUP,   g_OUP);
    cudaGetSymbolAddress((void**)&pMEMh,  g_MEMh);
    cudaGetSymbolAddress((void**)&pRM,    g_RM);
    cudaGetSymbolAddress((void**)&pWigo,  g_Wigo);
    cudaGetSymbolAddress((void**)&pWqk,   g_Wqk);
    cudaGetSymbolAddress((void**)&pWv,    g_Wv);
    cudaGetSymbolAddress((void**)&pWzrm,  g_Wzrm);
    cudaGetSymbolAddress((void**)&pWhm,   g_Whm);
    cudaGetSymbolAddress((void**)&pWozh,  g_Wozh);

    // 1: prep (fp16 weights, Wqk, biases)
    k_prep<<<PB_TOTAL, 256>>>(q_W, k_W, q_b, lstm_Wih, lstm_bih, lstm_bhh,
                              v_W, z_W, r_W, h_W, z_b, r_b, h_b);
    // 2: frame weighting -> X (fp16) + W_t out
    k_frame<<<B_, 256>>>(O_t, O_prev, w_mlp_W, w_mlp_b, out3);
    // 3: LSTM gates [B,768] fp16, K=512
    k_mma<0,5><<<dim3(6, B_/128), 256, SMEM_TOTAL>>>(
        pX, nullptr, pWigo, pbigo,
        nullptr, pGates, nullptr, nullptr, nullptr, nullptr, nullptr, nullptr, nullptr,
        B_, 768, 512);
    // 4: LSTM activations -> OTP (fp16)
    k_lstm_act<<<B_, 256>>>();
    // 5: QK = OTP @ Wqk^T + bqk  [B,256] fp32
    k_mma<0,0><<<dim3(2, B_/128), 256, SMEM_TOTAL>>>(
        pOTP, nullptr, pWqk, pbqk,
        pQK, nullptr, nullptr, nullptr, nullptr, nullptr, nullptr, nullptr, nullptr,
        B_, 256, 256);
    // 6: attention -> WM (fp16) + MEMh (fp16 memory copy)
    k_attn<<<B_, 256>>>(memory);
    // 7: V GEMM -> OUP (fp16) + out0/out2/mem slot 9 (exact fp32)
    k_mma<0,2><<<dim3(2, B_/128), 256, SMEM_TOTAL>>>(
        pWM, nullptr, pWv, v_b,
        nullptr, pOUP, out0, out_mem, out2, nullptr, nullptr, nullptr, nullptr,
        B_, 256, 256);
    // 8: OZH = O_up @ Wozh^T + bozh  [B,768] fp16
    k_mma<0,5><<<dim3(6, B_/128), 256, SMEM_TOTAL>>>(
        pOUP, nullptr, pWozh, pbozh,
        nullptr, pOZH, nullptr, nullptr, nullptr, nullptr, nullptr, nullptr, nullptr,
        B_, 768, 256);
    // 9: zr GEMM (fp16 memory as A) [M2,512]; epi: +OZH, Zs=sig(z) fp16, RM=sig(r)*memh fp16
    k_mma<1,4><<<dim3(4, M2_/128), 256, SMEM_TOTAL>>>(
        nullptr, pMEMh, pWzrm, nullptr,
        nullptr, nullptr, nullptr, nullptr, nullptr, pOZH, pZs, pRM, pMEMh,
        M2_, 512, 256);
    // 10: h GEMM (rm half) [M2,256]; epi: +OZH, tanh, z-combine (fp16 z/mem), shifted write
    k_mma<0,3><<<dim3(2, M2_/128), 256, SMEM_TOTAL>>>(
        pRM, nullptr, pWhm, nullptr,
        nullptr, nullptr, nullptr, out_mem, nullptr, pOZH, pZs, nullptr, pMEMh,
        M2_, 256, 256);
}

// round 11
// speedup vs baseline: 6.0542x; 1.0619x over previous
#include <cuda_runtime.h>
#include <cuda_fp16.h>
#include <math.h>
#include <stdint.h>

#define B_   16384
#define D_   256
#define ML_  10
#define M2_  (B_*9)

typedef __half h16;

// ---------------- fp32 scratch ----------------
__device__ __align__(256) float g_QK   [(size_t)B_*256];
// ---------------- fp16 scratch ----------------
__device__ __align__(256) h16 g_gates[(size_t)B_*768];
__device__ __align__(256) h16 g_OZH  [(size_t)B_*768];
__device__ __align__(256) h16 g_X   [(size_t)B_*512];
__device__ __align__(256) h16 g_OTP [(size_t)B_*256];
__device__ __align__(256) h16 g_WM  [(size_t)B_*256];
__device__ __align__(256) h16 g_OUP [(size_t)B_*256];
__device__ __align__(256) h16 g_MEMh[(size_t)B_*ML_*256];
// ---------------- fp16 weights ----------------
__device__ __align__(256) h16 g_Wigo [768*512];
__device__ __align__(256) h16 g_Wqk  [65536];
__device__ __align__(256) h16 g_Wv   [65536];
__device__ __align__(256) h16 g_Wzrm [512*256];
__device__ __align__(256) h16 g_Whm  [256*256];
__device__ __align__(256) h16 g_Wozh [768*256];
__device__ __align__(256) float g_bigo[768];
__device__ __align__(256) float g_bozh[768];
__device__ __align__(256) float g_bqk [256];

__device__ __forceinline__ float sigf(float x){ return 1.f/(1.f+expf(-x)); }

// ---------------- PTX helpers (base ISA only) ----------------
__device__ __forceinline__ uint32_t smem_u32(const void* p){
    uint32_t a; asm("{ .reg .u64 t; cvta.to.shared.u64 t, %1; cvt.u32.u64 %0, t; }" : "=r"(a) : "l"(p));
    return a;
}
__device__ __forceinline__ void ldsm4(uint32_t* r, uint32_t addr){
    asm volatile("ldmatrix.sync.aligned.m8n8.x4.shared.b16 {%0,%1,%2,%3}, [%4];"
        : "=r"(r[0]),"=r"(r[1]),"=r"(r[2]),"=r"(r[3]) : "r"(addr));
}
__device__ __forceinline__ void mma_f16(float* c, const uint32_t* a, const uint32_t* b){
    asm volatile("mma.sync.aligned.m16n8k16.row.col.f32.f16.f16.f32 "
        "{%0,%1,%2,%3}, {%4,%5,%6,%7}, {%8,%9}, {%0,%1,%2,%3};"
        : "+f"(c[0]),"+f"(c[1]),"+f"(c[2]),"+f"(c[3])
        : "r"(a[0]),"r"(a[1]),"r"(a[2]),"r"(a[3]), "r"(b[0]),"r"(b[1]));
}
__device__ __forceinline__ void cpa16(uint32_t dst, const void* src){
    asm volatile("cp.async.cg.shared.global [%0], [%1], 16;" :: "r"(dst), "l"(src));
}
#define CP_COMMIT() asm volatile("cp.async.commit_group;" ::: "memory")
#define CP_WAIT1()  asm volatile("cp.async.wait_group 1;"  ::: "memory")
#define CP_WAIT0()  asm volatile("cp.async.wait_group 0;"  ::: "memory")

#define ROWB     144
#define STAGE_SZ 36864
#define SMEM_TOTAL (3*STAGE_SZ)

// ================== fp16 HMMA GEMM: C[M,N] = A[M,K] @ W[N,K]^T ==================
// CTA 128x128, 8 warps (2x4), warp tile 64x32, K-chunk 64, 3-stage cp.async, 2 CTAs/SM.
// EPI 0: C fp32 = v + bias[col]
// EPI 5: C16 fp16 = v + bias[col]
// EPI 2: V-mode: v+=bias; fp16(v) -> C16(=OUP); v -> out0, out2, out_mem slot 9
template<int EPI>
__global__ void __launch_bounds__(256,2) k_mma(
    const h16* __restrict__ A,
    const h16* __restrict__ W,
    const float* __restrict__ bias,
    float* __restrict__ C, h16* __restrict__ C16,
    float* __restrict__ out0, float* __restrict__ out_mem, float* __restrict__ out2,
    int M, int N, int K)
{
    extern __shared__ char smem[];
    uint32_t sb = smem_u32(smem);
    const int tid = threadIdx.x, lane = tid & 31, w = tid >> 5;
    const int wm = w >> 2, wn = w & 3;
    const int m0 = blockIdx.y * 128, n0 = blockIdx.x * 128;
    const int nch = K >> 6;

    float acc[4][4][4];
    #pragma unroll
    for (int i=0;i<4;i++)
        #pragma unroll
        for (int j=0;j<4;j++)
            #pragma unroll
            for (int k=0;k<4;k++) acc[i][j][k]=0.f;

    auto load_chunk = [&](int c, int s){
        uint32_t st = sb + s*STAGE_SZ;
        #pragma unroll
        for (int t=0;t<4;t++){
            int u = tid + t*256;
            int row = u >> 3, q = u & 7;
            cpa16(st + row*ROWB + q*16, A + (size_t)(m0+row)*K + c*64 + q*8);
        }
        #pragma unroll
        for (int t=0;t<4;t++){
            int u = tid + t*256;
            int row = u >> 3, q = u & 7;
            cpa16(st + 18432 + row*ROWB + q*16, W + (size_t)(n0+row)*K + c*64 + q*8);
        }
        CP_COMMIT();
    };

    load_chunk(0, 0);
    load_chunk(1, 1);

    for (int c = 0; c < nch; c++){
        if (c == nch - 1) CP_WAIT0(); else CP_WAIT1();
        __syncthreads();
        if (c + 2 < nch) load_chunk(c + 2, (c + 2) % 3);

        uint32_t sA = sb + (c % 3)*STAGE_SZ;
        uint32_t sW = sA + 18432;
        #pragma unroll
        for (int kk = 0; kk < 4; kk++){
            uint32_t a[4][4];
            #pragma unroll
            for (int i = 0; i < 4; i++){
                int rl = wm*64 + i*16 + (lane & 7) + ((lane & 8) ? 8 : 0);
                uint32_t colb = kk*32 + ((lane & 16) ? 16 : 0);
                ldsm4(a[i], sA + rl*ROWB + colb);
            }
            uint32_t bf[4][2];
            #pragma unroll
            for (int jp = 0; jp < 2; jp++){
                int nl = wn*32 + jp*16 + (lane & 7) + ((lane & 16) ? 8 : 0);
                uint32_t colb = kk*32 + ((lane & 8) ? 16 : 0);
                uint32_t t4[4];
                ldsm4(t4, sW + nl*ROWB + colb);
                bf[2*jp][0]=t4[0]; bf[2*jp][1]=t4[1]; bf[2*jp+1][0]=t4[2]; bf[2*jp+1][1]=t4[3];
            }
            #pragma unroll
            for (int i=0;i<4;i++)
                #pragma unroll
                for (int j=0;j<4;j++) mma_f16(acc[i][j], a[i], bf[j]);
        }
        __syncthreads();
    }

    #pragma unroll
    for (int j = 0; j < 4; j++){
        int col = n0 + wn*32 + j*8 + (lane & 3)*2;
        float b0 = bias ? bias[col]   : 0.f;
        float b1 = bias ? bias[col+1] : 0.f;
        #pragma unroll
        for (int i = 0; i < 4; i++){
            int row = m0 + wm*64 + i*16 + (lane >> 2);
            #pragma unroll
            for (int h = 0; h < 2; h++){
                int rr = row + h*8;
                float v0 = acc[i][j][2*h+0] + b0;
                float v1 = acc[i][j][2*h+1] + b1;
                if (EPI == 0){
                    *reinterpret_cast<float2*>(C + (size_t)rr*N + col) = make_float2(v0, v1);
                } else if (EPI == 5){
                    *reinterpret_cast<__half2*>(C16 + (size_t)rr*N + col) = __floats2half2_rn(v0, v1);
                } else {  // EPI 2
                    size_t o = (size_t)rr*256 + col;
                    float2 fv = make_float2(v0, v1);
                    *reinterpret_cast<__half2*>(C16 + o) = __floats2half2_rn(v0, v1);
                    *reinterpret_cast<float2*>(out0 + o) = fv;
                    *reinterpret_cast<float2*>(out2 + o) = fv;
                    *reinterpret_cast<float2*>(out_mem + (size_t)rr*(ML_*256) + 9*256 + col) = fv;
                }
            }
        }
    }
}

// ================== fused GRU: z, r, h GEMMs + combine, SMEM-resident ==================
// 1 CTA = 128 rows of M2. 512 threads (16 warps, 4x4), warp tile 32x32 per pass.
// SMEM: A(memh rows) 128x528B; Zs 128x528B; RM 128x528B; W double-buffer 2x(128x80B).
#define GRU_ROWSTR 528
#define GRU_A_OFF  0
#define GRU_ZS_OFF 67584
#define GRU_RM_OFF 135168
#define GRU_W_OFF  202752
#define GRU_WSTG   10240
#define GRU_SMEM   223232

__global__ void __launch_bounds__(512,1) k_gru(
    const h16* __restrict__ memh,
    const h16* __restrict__ Wzrm, const h16* __restrict__ Whm,
    const h16* __restrict__ ozh,
    float* __restrict__ out_mem)
{
    extern __shared__ char smem[];
    uint32_t sb = smem_u32(smem);
    const int tid = threadIdx.x, lane = tid & 31, w = tid >> 5;
    const int wm = w >> 2, wn = w & 3;
    const int m0 = blockIdx.x * 128;

    // load this block's memory rows (fp16) into SMEM once
    #pragma unroll
    for (int t = 0; t < 8; t++){
        int u = tid + t*512;
        int row = u >> 5, q = u & 31;
        int rr = m0 + row, b = rr/9, m = rr - b*9 + 1;
        cpa16(sb + GRU_A_OFF + row*GRU_ROWSTR + q*16,
              memh + ((size_t)b*10 + m)*256 + q*8);
    }
    CP_COMMIT();
    CP_WAIT0();
    __syncthreads();

    for (int pass = 0; pass < 6; pass++){
        uint32_t aBase = sb + ((pass < 4) ? GRU_A_OFF : GRU_RM_OFF);
        const h16* Wg = (pass < 4) ? (Wzrm + (size_t)pass*(128*256))
                                   : (Whm  + (size_t)(pass-4)*(128*256));

        float acc[2][4][4];
        #pragma unroll
        for (int i=0;i<2;i++)
            #pragma unroll
            for (int j=0;j<4;j++)
                #pragma unroll
                for (int k=0;k<4;k++) acc[i][j][k]=0.f;

        // W pipeline: 8 chunks of 32 K-elements, 2 stages
        {
            int row = tid >> 2, q = tid & 3;
            cpa16(sb + GRU_W_OFF + row*80 + q*16, Wg + (size_t)row*256 + q*8);
            CP_COMMIT();
            cpa16(sb + GRU_W_OFF + GRU_WSTG + row*80 + q*16, Wg + (size_t)row*256 + 32 + q*8);
            CP_COMMIT();
        }

        for (int c = 0; c < 8; c++){
            if (c == 7) CP_WAIT0(); else CP_WAIT1();
            __syncthreads();
            uint32_t sW = sb + GRU_W_OFF + (c & 1)*GRU_WSTG;
            #pragma unroll
            for (int s = 0; s < 2; s++){
                int kk = c*2 + s;
                uint32_t a[2][4];
                #pragma unroll
                for (int i = 0; i < 2; i++){
                    int rl = wm*32 + i*16 + (lane & 7) + ((lane & 8) ? 8 : 0);
                    uint32_t colb = kk*32 + ((lane & 16) ? 16 : 0);
                    ldsm4(a[i], aBase + rl*GRU_ROWSTR + colb);
                }
                uint32_t bf[4][2];
                #pragma unroll
                for (int jp = 0; jp < 2; jp++){
                    int nl = wn*32 + jp*16 + (lane & 7) + ((lane & 16) ? 8 : 0);
                    uint32_t colb = s*32 + ((lane & 8) ? 16 : 0);
                    uint32_t t4[4];
                    ldsm4(t4, sW + nl*80 + colb);
                    bf[2*jp][0]=t4[0]; bf[2*jp][1]=t4[1]; bf[2*jp+1][0]=t4[2]; bf[2*jp+1][1]=t4[3];
                }
                #pragma unroll
                for (int i=0;i<2;i++)
                    #pragma unroll
                    for (int j=0;j<4;j++) mma_f16(acc[i][j], a[i], bf[j]);
            }
            __syncthreads();
            if (c + 2 < 8){
                int row = tid >> 2, q = tid & 3;
                cpa16(sb + GRU_W_OFF + (c & 1)*GRU_WSTG + row*80 + q*16,
                      Wg + (size_t)row*256 + (c+2)*32 + q*8);
                CP_COMMIT();
            }
        }

        // epilogue
        int colBase = (pass & 1) * 128;
        #pragma unroll
        for (int j = 0; j < 4; j++){
            int cc = colBase + wn*32 + j*8 + (lane & 3)*2;
            #pragma unroll
            for (int i = 0; i < 2; i++){
                #pragma unroll
                for (int h = 0; h < 2; h++){
                    int rl = wm*32 + i*16 + (lane >> 2) + h*8;
                    int rr = m0 + rl, b = rr/9, m = rr - b*9 + 1;
                    float v0 = acc[i][j][2*h], v1 = acc[i][j][2*h+1];
                    if (pass < 2){
                        float2 oz = __half22float2(*reinterpret_cast<const __half2*>(ozh + (size_t)b*768 + cc));
                        *reinterpret_cast<__half2*>(smem + GRU_ZS_OFF + rl*GRU_ROWSTR + cc*2) =
                            __floats2half2_rn(sigf(v0+oz.x), sigf(v1+oz.y));
                    } else if (pass < 4){
                        float2 oz = __half22float2(*reinterpret_cast<const __half2*>(ozh + (size_t)b*768 + 256 + cc));
                        float2 mv = __half22float2(*reinterpret_cast<const __half2*>(smem + GRU_A_OFF + rl*GRU_ROWSTR + cc*2));
                        *reinterpret_cast<__half2*>(smem + GRU_RM_OFF + rl*GRU_ROWSTR + cc*2) =
                            __floats2half2_rn(sigf(v0+oz.x)*mv.x, sigf(v1+oz.y)*mv.y);
                    } else {
                        float2 oz = __half22float2(*reinterpret_cast<const __half2*>(ozh + (size_t)b*768 + 512 + cc));
                        float mt0 = tanhf(v0+oz.x), mt1 = tanhf(v1+oz.y);
                        float2 zv = __half22float2(*reinterpret_cast<const __half2*>(smem + GRU_ZS_OFF + rl*GRU_ROWSTR + cc*2));
                        float2 mv = __half22float2(*reinterpret_cast<const __half2*>(smem + GRU_A_OFF + rl*GRU_ROWSTR + cc*2));
                        *reinterpret_cast<float2*>(out_mem + (size_t)b*(ML_*256) + (size_t)(m-1)*256 + cc) =
                            make_float2(zv.x*mv.x + (1.f-zv.x)*mt0, zv.y*mv.y + (1.f-zv.y)*mt1);
                    }
                }
            }
        }
        __syncthreads();
    }
}

// ---------------- prep: fp16 weights + Wqk + biases ----------------
#define PB_QK   256
#define PB_BIAS 6
#define PB_WIGO 1536
#define PB_WZRM 512
#define PB_WHM  256
#define PB_WOZH 768
#define PB_WV   256
#define PB_TOTAL (PB_QK+PB_BIAS+PB_WIGO+PB_WZRM+PB_WHM+PB_WOZH+PB_WV)

__global__ void k_prep(const float* __restrict__ qW, const float* __restrict__ kW,
                       const float* __restrict__ qb,
                       const float* __restrict__ Wih,
                       const float* __restrict__ bih, const float* __restrict__ bhh,
                       const float* __restrict__ vW,
                       const float* __restrict__ zW, const float* __restrict__ rW,
                       const float* __restrict__ hW,
                       const float* __restrict__ zb, const float* __restrict__ rb,
                       const float* __restrict__ hb)
{
    int blk = blockIdx.x;
    if (blk < PB_QK){
        int j = blk, e = threadIdx.x;
        float s = 0.f;
        for (int d = 0; d < 256; d++) s = fmaf(qW[d*256 + e], kW[d*256 + j], s);
        g_Wqk[j*256 + e] = __float2half_rn(s);
        if (e == 0){
            float bq = 0.f;
            for (int d = 0; d < 256; d++) bq = fmaf(qb[d], kW[d*256 + j], bq);
            g_bqk[j] = bq;
        }
        return;
    } blk -= PB_QK;
    if (blk < PB_BIAS){
        int i = blk*256 + threadIdx.x;
        if (i < 768){
            int src = (i < 256) ? i : i + 256;
            g_bigo[i] = bih[src] + bhh[src];
        } else if (i < 1536){
            int n = i - 768;
            g_bozh[n] = (n < 256) ? zb[n] : (n < 512) ? rb[n-256] : hb[n-512];
        }
        return;
    } blk -= PB_BIAS;
    if (blk < PB_WIGO){
        int i = blk*256 + threadIdx.x;
        int n = i >> 9, k = i & 511;
        int src = (n < 256) ? n : n + 256;
        g_Wigo[i] = __float2half_rn(Wih[(size_t)src*512 + k]);
        return;
    } blk -= PB_WIGO;
    if (blk < PB_WZRM){
        int i = blk*256 + threadIdx.x;
        int n = i >> 8, k = i & 255;
        float v = (n < 256) ? zW[(size_t)n*512 + k] : rW[(size_t)(n-256)*512 + k];
        g_Wzrm[i] = __float2half_rn(v);
        return;
    } blk -= PB_WZRM;
    if (blk < PB_WHM){
        int i = blk*256 + threadIdx.x;
        int n = i >> 8, k = i & 255;
        g_Whm[i] = __float2half_rn(hW[(size_t)n*512 + k]);
        return;
    } blk -= PB_WHM;
    if (blk < PB_WOZH){
        int i = blk*256 + threadIdx.x;
        int n = i >> 8, k = i & 255;
        float v = (n < 256) ? zW[(size_t)n*512 + 256 + k]
                : (n < 512) ? rW[(size_t)(n-256)*512 + 256 + k]
                            : hW[(size_t)(n-512)*512 + 256 + k];
        g_Wozh[i] = __float2half_rn(v);
        return;
    } blk -= PB_WOZH;
    {
        int i = blk*256 + threadIdx.x;
        g_Wv[i] = __float2half_rn(vW[i]);
    }
}

// ---------------- frame weighting ----------------
__global__ void k_frame(const float* __restrict__ O_t, const float* __restrict__ O_prev,
                        const float* __restrict__ wW, const float* __restrict__ wb,
                        float* __restrict__ out_Wt)
{
    int b = blockIdx.x, t = threadIdx.x;
    float ot = O_t[(size_t)b*256 + t];
    float op = O_prev[(size_t)b*256 + t];
    float dl = ot - op;
    float s0 = ot*ot, s1 = op*op, s2 = dl*dl, s3 = ot*op;
    #pragma unroll
    for (int off = 16; off; off >>= 1){
        s0 += __shfl_xor_sync(0xffffffffu, s0, off);
        s1 += __shfl_xor_sync(0xffffffffu, s1, off);
        s2 += __shfl_xor_sync(0xffffffffu, s2, off);
        s3 += __shfl_xor_sync(0xffffffffu, s3, off);
    }
    __shared__ float4 ws[8];
    __shared__ float4 tot;
    int w = t >> 5;
    if ((t & 31) == 0) ws[w] = make_float4(s0, s1, s2, s3);
    __syncthreads();
    if (t == 0){
        float4 r = ws[0];
        #pragma unroll
        for (int i = 1; i < 8; i++){ r.x += ws[i].x; r.y += ws[i].y; r.z += ws[i].z; r.w += ws[i].w; }
        tot = r;
    }
    __syncthreads();
    float n_t = sqrtf(tot.x), n_p = sqrtf(tot.y), rd = sqrtf(tot.z);
    float ra  = tot.w / (n_t*n_p + 1e-6f);
    float wt  = 0.5f*(tanhf(n_t*wW[t*3+0] + rd*wW[t*3+1] + ra*wW[t*3+2] + wb[t]) + 1.f);
    out_Wt[(size_t)b*256 + t] = wt;
    g_X[(size_t)b*512 + t]       = __float2half_rn(op);
    g_X[(size_t)b*512 + 256 + t] = __float2half_rn(ot * wt);
}

// ---------------- LSTM activations ----------------
__global__ void k_lstm_act(){
    size_t i = (size_t)blockIdx.x*256 + threadIdx.x;
    size_t b = i >> 8; int d = (int)(i & 255);
    float ig = __half2float(g_gates[b*768 + d]);
    float gg = __half2float(g_gates[b*768 + 256 + d]);
    float og = __half2float(g_gates[b*768 + 512 + d]);
    float c  = sigf(ig) * tanhf(gg);
    g_OTP[i] = __float2half_rn(sigf(og) * tanhf(c));
}

// ---------------- attention (also emits fp16 memory copy, slots 1..9) ----------------
__global__ void k_attn(const float* __restrict__ memory){
    int b = blockIdx.x, t = threadIdx.x;
    float qk = g_QK[(size_t)b*256 + t];
    const float* mb = memory + (size_t)b*ML_*256;
    h16* mh = g_MEMh + (size_t)b*ML_*256;
    float mv[ML_];
    __shared__ float sc[ML_];
    __shared__ float attn[ML_];
    if (t < ML_) sc[t] = 0.f;
    __syncthreads();
    #pragma unroll
    for (int m = 0; m < ML_; m++){
        mv[m] = mb[m*256 + t];
        if (m >= 1) mh[m*256 + t] = __float2half_rn(mv[m]);
        float v = qk * mv[m];
        #pragma unroll
        for (int off = 16; off; off >>= 1) v += __shfl_xor_sync(0xffffffffu, v, off);
        if ((t & 31) == 0) atomicAdd(&sc[m], v);
    }
    __syncthreads();
    if (t == 0){
        float mx = -1e30f;
        #pragma unroll
        for (int m = 0; m < ML_; m++){ sc[m] *= 0.0625f; mx = fmaxf(mx, sc[m]); }
        float e[ML_], s = 0.f;
        #pragma unroll
        for (int m = 0; m < ML_; m++){ e[m] = expf(sc[m] - mx); s += e[m]; }
        float inv = 1.f / s;
        #pragma unroll
        for (int m = 0; m < ML_; m++) attn[m] = e[m] * inv;
    }
    __syncthreads();
    float wm = 0.f;
    #pragma unroll
    for (int m = 0; m < ML_; m++) wm += attn[m] * mv[m];
    g_WM[(size_t)b*256 + t] = __float2half_rn(wm);
}

// ---------------- launcher ----------------
extern "C" void kernel_launch(void* const* d_in, const int* in_sizes, int n_in,
                              void* d_out, int out_size)
{
    const float* O_t     = (const float*)d_in[0];
    const float* O_prev  = (const float*)d_in[1];
    const float* memory  = (const float*)d_in[2];
    const float* w_mlp_W = (const float*)d_in[3];
    const float* w_mlp_b = (const float*)d_in[4];
    const float* lstm_Wih= (const float*)d_in[5];
    const float* lstm_bih= (const float*)d_in[7];
    const float* lstm_bhh= (const float*)d_in[8];
    const float* q_W = (const float*)d_in[9];   const float* q_b = (const float*)d_in[10];
    const float* k_W = (const float*)d_in[11];  // k_b cancels in softmax
    const float* v_W = (const float*)d_in[13];  const float* v_b = (const float*)d_in[14];
    const float* z_W = (const float*)d_in[15];  const float* z_b = (const float*)d_in[16];
    const float* r_W = (const float*)d_in[17];  const float* r_b = (const float*)d_in[18];
    const float* h_W = (const float*)d_in[19];  const float* h_b = (const float*)d_in[20];

    float* out      = (float*)d_out;
    float* out0     = out;
    float* out_mem  = out0 + (size_t)B_*D_;
    float* out2     = out_mem + (size_t)B_*ML_*D_;
    float* out3     = out2 + (size_t)B_*D_;

    cudaFuncSetAttribute(k_mma<0>, cudaFuncAttributeMaxDynamicSharedMemorySize, SMEM_TOTAL);
    cudaFuncSetAttribute(k_mma<5>, cudaFuncAttributeMaxDynamicSharedMemorySize, SMEM_TOTAL);
    cudaFuncSetAttribute(k_mma<2>, cudaFuncAttributeMaxDynamicSharedMemorySize, SMEM_TOTAL);
    cudaFuncSetAttribute(k_gru,    cudaFuncAttributeMaxDynamicSharedMemorySize, GRU_SMEM);

    float *pQK,*pbigo,*pbozh,*pbqk;
    h16 *pGates,*pOZH,*pX,*pOTP,*pWM,*pOUP,*pMEMh;
    h16 *pWigo,*pWqk,*pWv,*pWzrm,*pWhm,*pWozh;
    cudaGetSymbolAddress((void**)&pQK,    g_QK);
    cudaGetSymbolAddress((void**)&pbigo,  g_bigo);
    cudaGetSymbolAddress((void**)&pbozh,  g_bozh);
    cudaGetSymbolAddress((void**)&pbqk,   g_bqk);
    cudaGetSymbolAddress((void**)&pGates, g_gates);
    cudaGetSymbolAddress((void**)&pOZH,   g_OZH);
    cudaGetSymbolAddress((void**)&pX,     g_X);
    cudaGetSymbolAddress((void**)&pOTP,   g_OTP);
    cudaGetSymbolAddress((void**)&pWM,    g_WM);
    cudaGetSymbolAddress((void**)&pOUP,   g_OUP);
    cudaGetSymbolAddress((void**)&pMEMh,  g_MEMh);
    cudaGetSymbolAddress((void**)&pWigo,  g_Wigo);
    cudaGetSymbolAddress((void**)&pWqk,   g_Wqk);
    cudaGetSymbolAddress((void**)&pWv,    g_Wv);
    cudaGetSymbolAddress((void**)&pWzrm,  g_Wzrm);
    cudaGetSymbolAddress((void**)&pWhm,   g_Whm);
    cudaGetSymbolAddress((void**)&pWozh,  g_Wozh);

    // 1: prep (fp16 weights, Wqk, biases)
    k_prep<<<PB_TOTAL, 256>>>(q_W, k_W, q_b, lstm_Wih, lstm_bih, lstm_bhh,
                              v_W, z_W, r_W, h_W, z_b, r_b, h_b);
    // 2: frame weighting -> X (fp16) + W_t out
    k_frame<<<B_, 256>>>(O_t, O_prev, w_mlp_W, w_mlp_b, out3);
    // 3: LSTM gates [B,768] fp16, K=512
    k_mma<5><<<dim3(6, B_/128), 256, SMEM_TOTAL>>>(
        pX, pWigo, pbigo, nullptr, pGates, nullptr, nullptr, nullptr,
        B_, 768, 512);
    // 4: LSTM activations -> OTP (fp16)
    k_lstm_act<<<B_, 256>>>();
    // 5: QK = OTP @ Wqk^T + bqk  [B,256] fp32
    k_mma<0><<<dim3(2, B_/128), 256, SMEM_TOTAL>>>(
        pOTP, pWqk, pbqk, pQK, nullptr, nullptr, nullptr, nullptr,
        B_, 256, 256);
    // 6: attention -> WM (fp16) + MEMh (fp16 memory copy)
    k_attn<<<B_, 256>>>(memory);
    // 7: V GEMM -> OUP (fp16) + out0/out2/mem slot 9 (fp32)
    k_mma<2><<<dim3(2, B_/128), 256, SMEM_TOTAL>>>(
        pWM, pWv, v_b, nullptr, pOUP, out0, out_mem, out2,
        B_, 256, 256);
    // 8: OZH = O_up @ Wozh^T + bozh  [B,768] fp16
    k_mma<5><<<dim3(6, B_/128), 256, SMEM_TOTAL>>>(
        pOUP, pWozh, pbozh, nullptr, pOZH, nullptr, nullptr, nullptr,
        B_, 768, 256);
    // 9: fused GRU (z, r, h + combine + shift), replaces old launches 9+10
    k_gru<<<M2_/128, 512, GRU_SMEM>>>(pMEMh, pWzrm, pWhm, pOZH, out_mem);
}

// round 12
// speedup vs baseline: 6.2590x; 1.0338x over previous
#include <cuda_runtime.h>
#include <cuda_fp16.h>
#include <math.h>
#include <stdint.h>

#define B_   16384
#define D_   256
#define ML_  10
#define M2_  (B_*9)

typedef __half h16;

// ---------------- fp32 scratch ----------------
__device__ __align__(256) float g_QK   [(size_t)B_*256];
// ---------------- fp16 scratch ----------------
__device__ __align__(256) h16 g_gates[(size_t)B_*768];
__device__ __align__(256) h16 g_OZH  [(size_t)B_*768];
__device__ __align__(256) h16 g_X   [(size_t)B_*512];
__device__ __align__(256) h16 g_OTP [(size_t)B_*256];
__device__ __align__(256) h16 g_WM  [(size_t)B_*256];
__device__ __align__(256) h16 g_OUP [(size_t)B_*256];
__device__ __align__(256) h16 g_MEMh[(size_t)B_*ML_*256];
// ---------------- fp16 weights ----------------
__device__ __align__(256) h16 g_Wigo [768*512];
__device__ __align__(256) h16 g_Wqk  [65536];
__device__ __align__(256) h16 g_Wv   [65536];
__device__ __align__(256) h16 g_Wzrm [512*256];
__device__ __align__(256) h16 g_Whm  [256*256];
__device__ __align__(256) h16 g_Wozh [768*256];
__device__ __align__(256) float g_bigo[768];
__device__ __align__(256) float g_bozh[768];
__device__ __align__(256) float g_bqk [256];

__device__ __forceinline__ float sigf(float x){ return 1.f/(1.f+expf(-x)); }

// ---------------- PTX helpers (base ISA only) ----------------
__device__ __forceinline__ uint32_t smem_u32(const void* p){
    uint32_t a; asm("{ .reg .u64 t; cvta.to.shared.u64 t, %1; cvt.u32.u64 %0, t; }" : "=r"(a) : "l"(p));
    return a;
}
__device__ __forceinline__ void ldsm4(uint32_t* r, uint32_t addr){
    asm volatile("ldmatrix.sync.aligned.m8n8.x4.shared.b16 {%0,%1,%2,%3}, [%4];"
        : "=r"(r[0]),"=r"(r[1]),"=r"(r[2]),"=r"(r[3]) : "r"(addr));
}
__device__ __forceinline__ void mma_f16(float* c, const uint32_t* a, const uint32_t* b){
    asm volatile("mma.sync.aligned.m16n8k16.row.col.f32.f16.f16.f32 "
        "{%0,%1,%2,%3}, {%4,%5,%6,%7}, {%8,%9}, {%0,%1,%2,%3};"
        : "+f"(c[0]),"+f"(c[1]),"+f"(c[2]),"+f"(c[3])
        : "r"(a[0]),"r"(a[1]),"r"(a[2]),"r"(a[3]), "r"(b[0]),"r"(b[1]));
}
__device__ __forceinline__ void cpa16(uint32_t dst, const void* src){
    asm volatile("cp.async.cg.shared.global [%0], [%1], 16;" :: "r"(dst), "l"(src));
}
#define CP_COMMIT() asm volatile("cp.async.commit_group;" ::: "memory")
#define CP_WAIT1()  asm volatile("cp.async.wait_group 1;"  ::: "memory")
#define CP_WAIT0()  asm volatile("cp.async.wait_group 0;"  ::: "memory")

#define ROWB     144
#define STAGE_SZ 36864
#define SMEM_TOTAL (3*STAGE_SZ)

// ================== fp16 HMMA GEMM: C[M,N] = A[M,K] @ W[N,K]^T ==================
// CTA 128x128, 8 warps (2x4), warp tile 64x32, K-chunk 64, 3-stage cp.async, 2 CTAs/SM.
// EPI 0: C fp32 = v + bias[col]
// EPI 5: C16 fp16 = v + bias[col]
// EPI 2: V-mode: v+=bias; fp16(v) -> C16(=OUP); v -> out0, out2, out_mem slot 9
template<int EPI>
__global__ void __launch_bounds__(256,2) k_mma(
    const h16* __restrict__ A,
    const h16* __restrict__ W,
    const float* __restrict__ bias,
    float* __restrict__ C, h16* __restrict__ C16,
    float* __restrict__ out0, float* __restrict__ out_mem, float* __restrict__ out2,
    int M, int N, int K)
{
    extern __shared__ char smem[];
    uint32_t sb = smem_u32(smem);
    const int tid = threadIdx.x, lane = tid & 31, w = tid >> 5;
    const int wm = w >> 2, wn = w & 3;
    const int m0 = blockIdx.y * 128, n0 = blockIdx.x * 128;
    const int nch = K >> 6;

    float acc[4][4][4];
    #pragma unroll
    for (int i=0;i<4;i++)
        #pragma unroll
        for (int j=0;j<4;j++)
            #pragma unroll
            for (int k=0;k<4;k++) acc[i][j][k]=0.f;

    auto load_chunk = [&](int c, int s){
        uint32_t st = sb + s*STAGE_SZ;
        #pragma unroll
        for (int t=0;t<4;t++){
            int u = tid + t*256;
            int row = u >> 3, q = u & 7;
            cpa16(st + row*ROWB + q*16, A + (size_t)(m0+row)*K + c*64 + q*8);
        }
        #pragma unroll
        for (int t=0;t<4;t++){
            int u = tid + t*256;
            int row = u >> 3, q = u & 7;
            cpa16(st + 18432 + row*ROWB + q*16, W + (size_t)(n0+row)*K + c*64 + q*8);
        }
        CP_COMMIT();
    };

    load_chunk(0, 0);
    load_chunk(1, 1);

    for (int c = 0; c < nch; c++){
        if (c == nch - 1) CP_WAIT0(); else CP_WAIT1();
        __syncthreads();
        if (c + 2 < nch) load_chunk(c + 2, (c + 2) % 3);

        uint32_t sA = sb + (c % 3)*STAGE_SZ;
        uint32_t sW = sA + 18432;
        #pragma unroll
        for (int kk = 0; kk < 4; kk++){
            uint32_t a[4][4];
            #pragma unroll
            for (int i = 0; i < 4; i++){
                int rl = wm*64 + i*16 + (lane & 7) + ((lane & 8) ? 8 : 0);
                uint32_t colb = kk*32 + ((lane & 16) ? 16 : 0);
                ldsm4(a[i], sA + rl*ROWB + colb);
            }
            uint32_t bf[4][2];
            #pragma unroll
            for (int jp = 0; jp < 2; jp++){
                int nl = wn*32 + jp*16 + (lane & 7) + ((lane & 16) ? 8 : 0);
                uint32_t colb = kk*32 + ((lane & 8) ? 16 : 0);
                uint32_t t4[4];
                ldsm4(t4, sW + nl*ROWB + colb);
                bf[2*jp][0]=t4[0]; bf[2*jp][1]=t4[1]; bf[2*jp+1][0]=t4[2]; bf[2*jp+1][1]=t4[3];
            }
            #pragma unroll
            for (int i=0;i<4;i++)
                #pragma unroll
                for (int j=0;j<4;j++) mma_f16(acc[i][j], a[i], bf[j]);
        }
        __syncthreads();
    }

    #pragma unroll
    for (int j = 0; j < 4; j++){
        int col = n0 + wn*32 + j*8 + (lane & 3)*2;
        float b0 = bias ? bias[col]   : 0.f;
        float b1 = bias ? bias[col+1] : 0.f;
        #pragma unroll
        for (int i = 0; i < 4; i++){
            int row = m0 + wm*64 + i*16 + (lane >> 2);
            #pragma unroll
            for (int h = 0; h < 2; h++){
                int rr = row + h*8;
                float v0 = acc[i][j][2*h+0] + b0;
                float v1 = acc[i][j][2*h+1] + b1;
                if (EPI == 0){
                    *reinterpret_cast<float2*>(C + (size_t)rr*N + col) = make_float2(v0, v1);
                } else if (EPI == 5){
                    *reinterpret_cast<__half2*>(C16 + (size_t)rr*N + col) = __floats2half2_rn(v0, v1);
                } else {  // EPI 2
                    size_t o = (size_t)rr*256 + col;
                    float2 fv = make_float2(v0, v1);
                    *reinterpret_cast<__half2*>(C16 + o) = __floats2half2_rn(v0, v1);
                    *reinterpret_cast<float2*>(out0 + o) = fv;
                    *reinterpret_cast<float2*>(out2 + o) = fv;
                    *reinterpret_cast<float2*>(out_mem + (size_t)rr*(ML_*256) + 9*256 + col) = fv;
                }
            }
        }
    }
}

// ================== fused GRU v2: pass order {z0, r0, r1, h0, z1, h1} ==================
// 1 CTA = 128 rows. 512 threads (16 warps, 4x4), warp tile 32x32.
// SMEM: A 128x528B; RM 128x528B; Zs 128x256B (XOR-swizzled); W 2x(128x144B) K-chunk 64.
#define GRU_ROWSTR 528
#define GRU_A_OFF  0
#define GRU_RM_OFF 67584
#define GRU_ZS_OFF 135168
#define GRU_W_OFF  167936
#define GRU_WSTG   18432
#define GRU_SMEM   204800

__device__ __forceinline__ uint32_t zswz(int rl, int ccl){
    return (uint32_t)((rl*256 + ccl*2) ^ ((rl & 7) << 4));
}

__global__ void __launch_bounds__(512,1) k_gru(
    const h16* __restrict__ memh,
    const h16* __restrict__ Wzrm, const h16* __restrict__ Whm,
    const h16* __restrict__ ozh,
    float* __restrict__ out_mem)
{
    extern __shared__ char smem[];
    uint32_t sb = smem_u32(smem);
    const int tid = threadIdx.x, lane = tid & 31, w = tid >> 5;
    const int wm = w >> 2, wn = w & 3;
    const int m0 = blockIdx.x * 128;

    // load this block's memory rows (fp16) into SMEM once
    #pragma unroll
    for (int t = 0; t < 8; t++){
        int u = tid + t*512;
        int row = u >> 5, q = u & 31;
        int rr = m0 + row, b = rr/9, m = rr - b*9 + 1;
        cpa16(sb + GRU_A_OFF + row*GRU_ROWSTR + q*16,
              memh + ((size_t)b*10 + m)*256 + q*8);
    }
    CP_COMMIT(); CP_WAIT0(); __syncthreads();

    // per-pass config: weights, A base, global col offset, mode (0=z,1=r,2=h)
    auto wptr = [&](int p)->const h16*{
        switch(p){
            case 0: return Wzrm;                       // z cols 0-127
            case 1: return Wzrm + 256*256;             // r cols 0-127
            case 2: return Wzrm + 384*256;             // r cols 128-255
            case 3: return Whm;                        // h cols 0-127
            case 4: return Wzrm + 128*256;             // z cols 128-255
            default:return Whm + 128*256;              // h cols 128-255
        }
    };
    auto wload = [&](const h16* Wg, int c, int s){
        #pragma unroll
        for (int t = 0; t < 2; t++){
            int u = tid + t*512;
            int row = u >> 3, q = u & 7;
            cpa16(sb + GRU_W_OFF + s*GRU_WSTG + row*144 + q*16,
                  Wg + (size_t)row*256 + c*64 + q*8);
        }
        CP_COMMIT();
    };

    wload(wptr(0), 0, 0);
    wload(wptr(0), 1, 1);

    for (int pass = 0; pass < 6; pass++){
        const h16* Wg;
        uint32_t aOff; int colOff, mode;
        switch(pass){
            case 0: Wg=wptr(0); aOff=GRU_A_OFF;  colOff=0;   mode=0; break;
            case 1: Wg=wptr(1); aOff=GRU_A_OFF;  colOff=0;   mode=1; break;
            case 2: Wg=wptr(2); aOff=GRU_A_OFF;  colOff=128; mode=1; break;
            case 3: Wg=wptr(3); aOff=GRU_RM_OFF; colOff=0;   mode=2; break;
            case 4: Wg=wptr(4); aOff=GRU_A_OFF;  colOff=128; mode=0; break;
            default:Wg=wptr(5); aOff=GRU_RM_OFF; colOff=128; mode=2; break;
        }
        uint32_t aBase = sb + aOff;

        float acc[2][4][4];
        #pragma unroll
        for (int i=0;i<2;i++)
            #pragma unroll
            for (int j=0;j<4;j++)
                #pragma unroll
                for (int k=0;k<4;k++) acc[i][j][k]=0.f;

        for (int c = 0; c < 4; c++){
            if (c == 3) CP_WAIT0(); else CP_WAIT1();
            __syncthreads();
            uint32_t sW = sb + GRU_W_OFF + (c & 1)*GRU_WSTG;
            #pragma unroll
            for (int kk = 0; kk < 4; kk++){
                int kg = c*4 + kk;
                uint32_t a[2][4];
                #pragma unroll
                for (int i = 0; i < 2; i++){
                    int rl = wm*32 + i*16 + (lane & 7) + ((lane & 8) ? 8 : 0);
                    uint32_t colb = kg*32 + ((lane & 16) ? 16 : 0);
                    ldsm4(a[i], aBase + rl*GRU_ROWSTR + colb);
                }
                uint32_t bf[4][2];
                #pragma unroll
                for (int jp = 0; jp < 2; jp++){
                    int nl = wn*32 + jp*16 + (lane & 7) + ((lane & 16) ? 8 : 0);
                    uint32_t colb = kk*32 + ((lane & 8) ? 16 : 0);
                    uint32_t t4[4];
                    ldsm4(t4, sW + nl*144 + colb);
                    bf[2*jp][0]=t4[0]; bf[2*jp][1]=t4[1]; bf[2*jp+1][0]=t4[2]; bf[2*jp+1][1]=t4[3];
                }
                #pragma unroll
                for (int i=0;i<2;i++)
                    #pragma unroll
                    for (int j=0;j<4;j++) mma_f16(acc[i][j], a[i], bf[j]);
            }
            __syncthreads();
            if (c + 2 < 4) wload(Wg, c + 2, c & 1);
        }

        // prefetch next pass's first two W chunks (stages 0,1) before epilogue
        if (pass < 5){
            const h16* Wn = wptr(pass + 1);
            wload(Wn, 0, 0);
            wload(Wn, 1, 1);
        }

        // epilogue
        #pragma unroll
        for (int j = 0; j < 4; j++){
            int ccl = wn*32 + j*8 + (lane & 3)*2;   // local col 0..127
            int cc  = colOff + ccl;                 // global gate col
            #pragma unroll
            for (int i = 0; i < 2; i++){
                #pragma unroll
                for (int h = 0; h < 2; h++){
                    int rl = wm*32 + i*16 + (lane >> 2) + h*8;
                    int rr = m0 + rl, b = rr/9;
                    float v0 = acc[i][j][2*h], v1 = acc[i][j][2*h+1];
                    if (mode == 0){
                        float2 oz = __half22float2(*reinterpret_cast<const __half2*>(ozh + (size_t)b*768 + cc));
                        *reinterpret_cast<__half2*>(smem + GRU_ZS_OFF + zswz(rl, ccl)) =
                            __floats2half2_rn(sigf(v0+oz.x), sigf(v1+oz.y));
                    } else if (mode == 1){
                        float2 oz = __half22float2(*reinterpret_cast<const __half2*>(ozh + (size_t)b*768 + 256 + cc));
                        float2 mv = __half22float2(*reinterpret_cast<const __half2*>(smem + GRU_A_OFF + rl*GRU_ROWSTR + cc*2));
                        *reinterpret_cast<__half2*>(smem + GRU_RM_OFF + rl*GRU_ROWSTR + cc*2) =
                            __floats2half2_rn(sigf(v0+oz.x)*mv.x, sigf(v1+oz.y)*mv.y);
                    } else {
                        int m = rr - b*9 + 1;
                        float2 oz = __half22float2(*reinterpret_cast<const __half2*>(ozh + (size_t)b*768 + 512 + cc));
                        float mt0 = tanhf(v0+oz.x), mt1 = tanhf(v1+oz.y);
                        float2 zv = __half22float2(*reinterpret_cast<const __half2*>(smem + GRU_ZS_OFF + zswz(rl, ccl)));
                        float2 mv = __half22float2(*reinterpret_cast<const __half2*>(smem + GRU_A_OFF + rl*GRU_ROWSTR + cc*2));
                        *reinterpret_cast<float2*>(out_mem + (size_t)b*(ML_*256) + (size_t)(m-1)*256 + cc) =
                            make_float2(zv.x*mv.x + (1.f-zv.x)*mt0, zv.y*mv.y + (1.f-zv.y)*mt1);
                    }
                }
            }
        }
        __syncthreads();
    }
}

// ---------------- prep: fp16 weights + Wqk + biases ----------------
#define PB_QK   256
#define PB_BIAS 6
#define PB_WIGO 1536
#define PB_WZRM 512
#define PB_WHM  256
#define PB_WOZH 768
#define PB_WV   256
#define PB_TOTAL (PB_QK+PB_BIAS+PB_WIGO+PB_WZRM+PB_WHM+PB_WOZH+PB_WV)

__global__ void k_prep(const float* __restrict__ qW, const float* __restrict__ kW,
                       const float* __restrict__ qb,
                       const float* __restrict__ Wih,
                       const float* __restrict__ bih, const float* __restrict__ bhh,
                       const float* __restrict__ vW,
                       const float* __restrict__ zW, const float* __restrict__ rW,
                       const float* __restrict__ hW,
                       const float* __restrict__ zb, const float* __restrict__ rb,
                       const float* __restrict__ hb)
{
    int blk = blockIdx.x;
    if (blk < PB_QK){
        int j = blk, e = threadIdx.x;
        float s = 0.f;
        for (int d = 0; d < 256; d++) s = fmaf(qW[d*256 + e], kW[d*256 + j], s);
        g_Wqk[j*256 + e] = __float2half_rn(s);
        if (e == 0){
            float bq = 0.f;
            for (int d = 0; d < 256; d++) bq = fmaf(qb[d], kW[d*256 + j], bq);
            g_bqk[j] = bq;
        }
        return;
    } blk -= PB_QK;
    if (blk < PB_BIAS){
        int i = blk*256 + threadIdx.x;
        if (i < 768){
            int src = (i < 256) ? i : i + 256;
            g_bigo[i] = bih[src] + bhh[src];
        } else if (i < 1536){
            int n = i - 768;
            g_bozh[n] = (n < 256) ? zb[n] : (n < 512) ? rb[n-256] : hb[n-512];
        }
        return;
    } blk -= PB_BIAS;
    if (blk < PB_WIGO){
        int i = blk*256 + threadIdx.x;
        int n = i >> 9, k = i & 511;
        int src = (n < 256) ? n : n + 256;
        g_Wigo[i] = __float2half_rn(Wih[(size_t)src*512 + k]);
        return;
    } blk -= PB_WIGO;
    if (blk < PB_WZRM){
        int i = blk*256 + threadIdx.x;
        int n = i >> 8, k = i & 255;
        float v = (n < 256) ? zW[(size_t)n*512 + k] : rW[(size_t)(n-256)*512 + k];
        g_Wzrm[i] = __float2half_rn(v);
        return;
    } blk -= PB_WZRM;
    if (blk < PB_WHM){
        int i = blk*256 + threadIdx.x;
        int n = i >> 8, k = i & 255;
        g_Whm[i] = __float2half_rn(hW[(size_t)n*512 + k]);
        return;
    } blk -= PB_WHM;
    if (blk < PB_WOZH){
        int i = blk*256 + threadIdx.x;
        int n = i >> 8, k = i & 255;
        float v = (n < 256) ? zW[(size_t)n*512 + 256 + k]
                : (n < 512) ? rW[(size_t)(n-256)*512 + 256 + k]
                            : hW[(size_t)(n-512)*512 + 256 + k];
        g_Wozh[i] = __float2half_rn(v);
        return;
    } blk -= PB_WOZH;
    {
        int i = blk*256 + threadIdx.x;
        g_Wv[i] = __float2half_rn(vW[i]);
    }
}

// ---------------- frame weighting ----------------
__global__ void k_frame(const float* __restrict__ O_t, const float* __restrict__ O_prev,
                        const float* __restrict__ wW, const float* __restrict__ wb,
                        float* __restrict__ out_Wt)
{
    int b = blockIdx.x, t = threadIdx.x;
    float ot = O_t[(size_t)b*256 + t];
    float op = O_prev[(size_t)b*256 + t];
    float dl = ot - op;
    float s0 = ot*ot, s1 = op*op, s2 = dl*dl, s3 = ot*op;
    #pragma unroll
    for (int off = 16; off; off >>= 1){
        s0 += __shfl_xor_sync(0xffffffffu, s0, off);
        s1 += __shfl_xor_sync(0xffffffffu, s1, off);
        s2 += __shfl_xor_sync(0xffffffffu, s2, off);
        s3 += __shfl_xor_sync(0xffffffffu, s3, off);
    }
    __shared__ float4 ws[8];
    __shared__ float4 tot;
    int w = t >> 5;
    if ((t & 31) == 0) ws[w] = make_float4(s0, s1, s2, s3);
    __syncthreads();
    if (t == 0){
        float4 r = ws[0];
        #pragma unroll
        for (int i = 1; i < 8; i++){ r.x += ws[i].x; r.y += ws[i].y; r.z += ws[i].z; r.w += ws[i].w; }
        tot = r;
    }
    __syncthreads();
    float n_t = sqrtf(tot.x), n_p = sqrtf(tot.y), rd = sqrtf(tot.z);
    float ra  = tot.w / (n_t*n_p + 1e-6f);
    float wt  = 0.5f*(tanhf(n_t*wW[t*3+0] + rd*wW[t*3+1] + ra*wW[t*3+2] + wb[t]) + 1.f);
    out_Wt[(size_t)b*256 + t] = wt;
    g_X[(size_t)b*512 + t]       = __float2half_rn(op);
    g_X[(size_t)b*512 + 256 + t] = __float2half_rn(ot * wt);
}

// ---------------- LSTM activations (half2-vectorized) ----------------
__global__ void k_lstm_act(){
    int i = blockIdx.x*256 + threadIdx.x;       // over B_*128 half2 elements
    const __half2* G = reinterpret_cast<const __half2*>(g_gates);
    int b = i >> 7, d2 = i & 127;
    float2 ig = __half22float2(G[(size_t)b*384 + d2]);
    float2 gg = __half22float2(G[(size_t)b*384 + 128 + d2]);
    float2 og = __half22float2(G[(size_t)b*384 + 256 + d2]);
    float c0 = sigf(ig.x) * tanhf(gg.x);
    float c1 = sigf(ig.y) * tanhf(gg.y);
    reinterpret_cast<__half2*>(g_OTP)[i] =
        __floats2half2_rn(sigf(og.x)*tanhf(c0), sigf(og.y)*tanhf(c1));
}

// ---------------- attention (also emits fp16 memory copy, slots 1..9) ----------------
__global__ void k_attn(const float* __restrict__ memory){
    int b = blockIdx.x, t = threadIdx.x;
    float qk = g_QK[(size_t)b*256 + t];
    const float* mb = memory + (size_t)b*ML_*256;
    h16* mh = g_MEMh + (size_t)b*ML_*256;
    float mv[ML_];
    __shared__ float sc[ML_];
    __shared__ float attn[ML_];
    if (t < ML_) sc[t] = 0.f;
    __syncthreads();
    #pragma unroll
    for (int m = 0; m < ML_; m++){
        mv[m] = mb[m*256 + t];
        if (m >= 1) mh[m*256 + t] = __float2half_rn(mv[m]);
        float v = qk * mv[m];
        #pragma unroll
        for (int off = 16; off; off >>= 1) v += __shfl_xor_sync(0xffffffffu, v, off);
        if ((t & 31) == 0) atomicAdd(&sc[m], v);
    }
    __syncthreads();
    if (t == 0){
        float mx = -1e30f;
        #pragma unroll
        for (int m = 0; m < ML_; m++){ sc[m] *= 0.0625f; mx = fmaxf(mx, sc[m]); }
        float e[ML_], s = 0.f;
        #pragma unroll
        for (int m = 0; m < ML_; m++){ e[m] = expf(sc[m] - mx); s += e[m]; }
        float inv = 1.f / s;
        #pragma unroll
        for (int m = 0; m < ML_; m++) attn[m] = e[m] * inv;
    }
    __syncthreads();
    float wm = 0.f;
    #pragma unroll
    for (int m = 0; m < ML_; m++) wm += attn[m] * mv[m];
    g_WM[(size_t)b*256 + t] = __float2half_rn(wm);
}

// ---------------- launcher ----------------
extern "C" void kernel_launch(void* const* d_in, const int* in_sizes, int n_in,
                              void* d_out, int out_size)
{
    const float* O_t     = (const float*)d_in[0];
    const float* O_prev  = (const float*)d_in[1];
    const float* memory  = (const float*)d_in[2];
    const float* w_mlp_W = (const float*)d_in[3];
    const float* w_mlp_b = (const float*)d_in[4];
    const float* lstm_Wih= (const float*)d_in[5];
    const float* lstm_bih= (const float*)d_in[7];
    const float* lstm_bhh= (const float*)d_in[8];
    const float* q_W = (const float*)d_in[9];   const float* q_b = (const float*)d_in[10];
    const float* k_W = (const float*)d_in[11];  // k_b cancels in softmax
    const float* v_W = (const float*)d_in[13];  const float* v_b = (const float*)d_in[14];
    const float* z_W = (const float*)d_in[15];  const float* z_b = (const float*)d_in[16];
    const float* r_W = (const float*)d_in[17];  const float* r_b = (const float*)d_in[18];
    const float* h_W = (const float*)d_in[19];  const float* h_b = (const float*)d_in[20];

    float* out      = (float*)d_out;
    float* out0     = out;
    float* out_mem  = out0 + (size_t)B_*D_;
    float* out2     = out_mem + (size_t)B_*ML_*D_;
    float* out3     = out2 + (size_t)B_*D_;

    cudaFuncSetAttribute(k_mma<0>, cudaFuncAttributeMaxDynamicSharedMemorySize, SMEM_TOTAL);
    cudaFuncSetAttribute(k_mma<5>, cudaFuncAttributeMaxDynamicSharedMemorySize, SMEM_TOTAL);
    cudaFuncSetAttribute(k_mma<2>, cudaFuncAttributeMaxDynamicSharedMemorySize, SMEM_TOTAL);
    cudaFuncSetAttribute(k_gru,    cudaFuncAttributeMaxDynamicSharedMemorySize, GRU_SMEM);

    float *pQK,*pbigo,*pbozh,*pbqk;
    h16 *pGates,*pOZH,*pX,*pOTP,*pWM,*pOUP,*pMEMh;
    h16 *pWigo,*pWqk,*pWv,*pWzrm,*pWhm,*pWozh;
    cudaGetSymbolAddress((void**)&pQK,    g_QK);
    cudaGetSymbolAddress((void**)&pbigo,  g_bigo);
    cudaGetSymbolAddress((void**)&pbozh,  g_bozh);
    cudaGetSymbolAddress((void**)&pbqk,   g_bqk);
    cudaGetSymbolAddress((void**)&pGates, g_gates);
    cudaGetSymbolAddress((void**)&pOZH,   g_OZH);
    cudaGetSymbolAddress((void**)&pX,     g_X);
    cudaGetSymbolAddress((void**)&pOTP,   g_OTP);
    cudaGetSymbolAddress((void**)&pWM,    g_WM);
    cudaGetSymbolAddress((void**)&pOUP,   g_OUP);
    cudaGetSymbolAddress((void**)&pMEMh,  g_MEMh);
    cudaGetSymbolAddress((void**)&pWigo,  g_Wigo);
    cudaGetSymbolAddress((void**)&pWqk,   g_Wqk);
    cudaGetSymbolAddress((void**)&pWv,    g_Wv);
    cudaGetSymbolAddress((void**)&pWzrm,  g_Wzrm);
    cudaGetSymbolAddress((void**)&pWhm,   g_Whm);
    cudaGetSymbolAddress((void**)&pWozh,  g_Wozh);

    // 1: prep (fp16 weights, Wqk, biases)
    k_prep<<<PB_TOTAL, 256>>>(q_W, k_W, q_b, lstm_Wih, lstm_bih, lstm_bhh,
                              v_W, z_W, r_W, h_W, z_b, r_b, h_b);
    // 2: frame weighting -> X (fp16) + W_t out
    k_frame<<<B_, 256>>>(O_t, O_prev, w_mlp_W, w_mlp_b, out3);
    // 3: LSTM gates [B,768] fp16, K=512
    k_mma<5><<<dim3(6, B_/128), 256, SMEM_TOTAL>>>(
        pX, pWigo, pbigo, nullptr, pGates, nullptr, nullptr, nullptr,
        B_, 768, 512);
    // 4: LSTM activations -> OTP (fp16), half2-vectorized
    k_lstm_act<<<(B_*128)/256, 256>>>();
    // 5: QK = OTP @ Wqk^T + bqk  [B,256] fp32
    k_mma<0><<<dim3(2, B_/128), 256, SMEM_TOTAL>>>(
        pOTP, pWqk, pbqk, pQK, nullptr, nullptr, nullptr, nullptr,
        B_, 256, 256);
    // 6: attention -> WM (fp16) + MEMh (fp16 memory copy)
    k_attn<<<B_, 256>>>(memory);
    // 7: V GEMM -> OUP (fp16) + out0/out2/mem slot 9 (fp32)
    k_mma<2><<<dim3(2, B_/128), 256, SMEM_TOTAL>>>(
        pWM, pWv, v_b, nullptr, pOUP, out0, out_mem, out2,
        B_, 256, 256);
    // 8: OZH = O_up @ Wozh^T + bozh  [B,768] fp16
    k_mma<5><<<dim3(6, B_/128), 256, SMEM_TOTAL>>>(
        pOUP, pWozh, pbozh, nullptr, pOZH, nullptr, nullptr, nullptr,
        B_, 768, 256);
    // 9: fused GRU v2 (z, r, h + combine + shift)
    k_gru<<<M2_/128, 512, GRU_SMEM>>>(pMEMh, pWzrm, pWhm, pOZH, out_mem);
}

// round 13
// speedup vs baseline: 6.2922x; 1.0053x over previous
#include <cuda_runtime.h>
#include <cuda_fp16.h>
#include <math.h>
#include <stdint.h>

#define B_   16384
#define D_   256
#define ML_  10
#define M2_  (B_*9)

typedef __half h16;

// ---------------- fp16 scratch ----------------
__device__ __align__(256) h16 g_QK   [(size_t)B_*256];
__device__ __align__(256) h16 g_gates[(size_t)B_*768];
__device__ __align__(256) h16 g_OZH  [(size_t)B_*768];
__device__ __align__(256) h16 g_X   [(size_t)B_*512];
__device__ __align__(256) h16 g_OTP [(size_t)B_*256];
__device__ __align__(256) h16 g_WM  [(size_t)B_*256];
__device__ __align__(256) h16 g_OUP [(size_t)B_*256];
__device__ __align__(256) h16 g_MEMh[(size_t)B_*ML_*256];
// ---------------- fp16 weights ----------------
__device__ __align__(256) h16 g_Wigo [768*512];
__device__ __align__(256) h16 g_Wqk  [65536];
__device__ __align__(256) h16 g_Wv   [65536];
__device__ __align__(256) h16 g_Wzrm [512*256];
__device__ __align__(256) h16 g_Whm  [256*256];
__device__ __align__(256) h16 g_Wozh [768*256];
__device__ __align__(256) float g_bigo[768];
__device__ __align__(256) float g_bozh[768];
__device__ __align__(256) float g_bqk [256];

__device__ __forceinline__ float sigf(float x){ return 1.f/(1.f+expf(-x)); }

// ---------------- PTX helpers (base ISA only) ----------------
__device__ __forceinline__ uint32_t smem_u32(const void* p){
    uint32_t a; asm("{ .reg .u64 t; cvta.to.shared.u64 t, %1; cvt.u32.u64 %0, t; }" : "=r"(a) : "l"(p));
    return a;
}
__device__ __forceinline__ void ldsm4(uint32_t* r, uint32_t addr){
    asm volatile("ldmatrix.sync.aligned.m8n8.x4.shared.b16 {%0,%1,%2,%3}, [%4];"
        : "=r"(r[0]),"=r"(r[1]),"=r"(r[2]),"=r"(r[3]) : "r"(addr));
}
__device__ __forceinline__ void mma_f16(float* c, const uint32_t* a, const uint32_t* b){
    asm volatile("mma.sync.aligned.m16n8k16.row.col.f32.f16.f16.f32 "
        "{%0,%1,%2,%3}, {%4,%5,%6,%7}, {%8,%9}, {%0,%1,%2,%3};"
        : "+f"(c[0]),"+f"(c[1]),"+f"(c[2]),"+f"(c[3])
        : "r"(a[0]),"r"(a[1]),"r"(a[2]),"r"(a[3]), "r"(b[0]),"r"(b[1]));
}
__device__ __forceinline__ void cpa16(uint32_t dst, const void* src){
    asm volatile("cp.async.cg.shared.global [%0], [%1], 16;" :: "r"(dst), "l"(src));
}
#define CP_COMMIT() asm volatile("cp.async.commit_group;" ::: "memory")
#define CP_WAIT1()  asm volatile("cp.async.wait_group 1;"  ::: "memory")
#define CP_WAIT0()  asm volatile("cp.async.wait_group 0;"  ::: "memory")

#define ROWB     144
#define STAGE_SZ 36864
#define SMEM_TOTAL (3*STAGE_SZ)

// ================== fp16 HMMA GEMM: C[M,N] = A[M,K] @ W[N,K]^T ==================
// CTA 128x128, 8 warps (2x4), warp tile 64x32, K-chunk 64, 3-stage cp.async, 2 CTAs/SM.
// EPI 5: C16 fp16 = v + bias[col]
// EPI 2: V-mode: v+=bias; fp16(v) -> C16(=OUP); v -> out0, out2, out_mem slot 9
template<int EPI>
__global__ void __launch_bounds__(256,2) k_mma(
    const h16* __restrict__ A,
    const h16* __restrict__ W,
    const float* __restrict__ bias,
    h16* __restrict__ C16,
    float* __restrict__ out0, float* __restrict__ out_mem, float* __restrict__ out2,
    int M, int N, int K)
{
    extern __shared__ char smem[];
    uint32_t sb = smem_u32(smem);
    const int tid = threadIdx.x, lane = tid & 31, w = tid >> 5;
    const int wm = w >> 2, wn = w & 3;
    const int m0 = blockIdx.y * 128, n0 = blockIdx.x * 128;
    const int nch = K >> 6;

    float acc[4][4][4];
    #pragma unroll
    for (int i=0;i<4;i++)
        #pragma unroll
        for (int j=0;j<4;j++)
            #pragma unroll
            for (int k=0;k<4;k++) acc[i][j][k]=0.f;

    auto load_chunk = [&](int c, int s){
        uint32_t st = sb + s*STAGE_SZ;
        #pragma unroll
        for (int t=0;t<4;t++){
            int u = tid + t*256;
            int row = u >> 3, q = u & 7;
            cpa16(st + row*ROWB + q*16, A + (size_t)(m0+row)*K + c*64 + q*8);
        }
        #pragma unroll
        for (int t=0;t<4;t++){
            int u = tid + t*256;
            int row = u >> 3, q = u & 7;
            cpa16(st + 18432 + row*ROWB + q*16, W + (size_t)(n0+row)*K + c*64 + q*8);
        }
        CP_COMMIT();
    };

    load_chunk(0, 0);
    load_chunk(1, 1);

    for (int c = 0; c < nch; c++){
        if (c == nch - 1) CP_WAIT0(); else CP_WAIT1();
        __syncthreads();
        if (c + 2 < nch) load_chunk(c + 2, (c + 2) % 3);

        uint32_t sA = sb + (c % 3)*STAGE_SZ;
        uint32_t sW = sA + 18432;
        #pragma unroll
        for (int kk = 0; kk < 4; kk++){
            uint32_t a[4][4];
            #pragma unroll
            for (int i = 0; i < 4; i++){
                int rl = wm*64 + i*16 + (lane & 7) + ((lane & 8) ? 8 : 0);
                uint32_t colb = kk*32 + ((lane & 16) ? 16 : 0);
                ldsm4(a[i], sA + rl*ROWB + colb);
            }
            uint32_t bf[4][2];
            #pragma unroll
            for (int jp = 0; jp < 2; jp++){
                int nl = wn*32 + jp*16 + (lane & 7) + ((lane & 16) ? 8 : 0);
                uint32_t colb = kk*32 + ((lane & 8) ? 16 : 0);
                uint32_t t4[4];
                ldsm4(t4, sW + nl*ROWB + colb);
                bf[2*jp][0]=t4[0]; bf[2*jp][1]=t4[1]; bf[2*jp+1][0]=t4[2]; bf[2*jp+1][1]=t4[3];
            }
            #pragma unroll
            for (int i=0;i<4;i++)
                #pragma unroll
                for (int j=0;j<4;j++) mma_f16(acc[i][j], a[i], bf[j]);
        }
        __syncthreads();
    }

    #pragma unroll
    for (int j = 0; j < 4; j++){
        int col = n0 + wn*32 + j*8 + (lane & 3)*2;
        float b0 = bias ? bias[col]   : 0.f;
        float b1 = bias ? bias[col+1] : 0.f;
        #pragma unroll
        for (int i = 0; i < 4; i++){
            int row = m0 + wm*64 + i*16 + (lane >> 2);
            #pragma unroll
            for (int h = 0; h < 2; h++){
                int rr = row + h*8;
                float v0 = acc[i][j][2*h+0] + b0;
                float v1 = acc[i][j][2*h+1] + b1;
                if (EPI == 5){
                    *reinterpret_cast<__half2*>(C16 + (size_t)rr*N + col) = __floats2half2_rn(v0, v1);
                } else {  // EPI 2
                    size_t o = (size_t)rr*256 + col;
                    float2 fv = make_float2(v0, v1);
                    *reinterpret_cast<__half2*>(C16 + o) = __floats2half2_rn(v0, v1);
                    *reinterpret_cast<float2*>(out0 + o) = fv;
                    *reinterpret_cast<float2*>(out2 + o) = fv;
                    *reinterpret_cast<float2*>(out_mem + (size_t)rr*(ML_*256) + 9*256 + col) = fv;
                }
            }
        }
    }
}

// ================== fused GRU v3: 64-row CTAs, 2 CTAs/SM ==================
// 256 threads (8 warps, 2x4), warp tile 32x32, pass order {z0, r0, r1, h0, z1, h1}.
// SMEM: A 64x528B; RM 64x528B; Zs 64x256B (XOR-swizzled); W 2x(128x80B) K-chunk 32.
#define GRU_ROWSTR 528
#define GRU_A_OFF  0
#define GRU_RM_OFF 33792
#define GRU_ZS_OFF 67584
#define GRU_W_OFF  83968
#define GRU_WSTG   10240
#define GRU_SMEM   104448

__device__ __forceinline__ uint32_t zswz(int rl, int ccl){
    return (uint32_t)((rl*256 + ccl*2) ^ ((rl & 7) << 4));
}

__global__ void __launch_bounds__(256,2) k_gru(
    const h16* __restrict__ memh,
    const h16* __restrict__ Wzrm, const h16* __restrict__ Whm,
    const h16* __restrict__ ozh,
    float* __restrict__ out_mem)
{
    extern __shared__ char smem[];
    uint32_t sb = smem_u32(smem);
    const int tid = threadIdx.x, lane = tid & 31, w = tid >> 5;
    const int wm = w >> 2, wn = w & 3;
    const int m0 = blockIdx.x * 64;

    // load this block's 64 memory rows (fp16) into SMEM once
    #pragma unroll
    for (int t = 0; t < 8; t++){
        int u = tid + t*256;
        int row = u >> 5, q = u & 31;
        int rr = m0 + row, b = rr/9, m = rr - b*9 + 1;
        cpa16(sb + GRU_A_OFF + row*GRU_ROWSTR + q*16,
              memh + ((size_t)b*10 + m)*256 + q*8);
    }
    CP_COMMIT(); CP_WAIT0(); __syncthreads();

    auto wptr = [&](int p)->const h16*{
        switch(p){
            case 0: return Wzrm;                       // z cols 0-127
            case 1: return Wzrm + 256*256;             // r cols 0-127
            case 2: return Wzrm + 384*256;             // r cols 128-255
            case 3: return Whm;                        // h cols 0-127
            case 4: return Wzrm + 128*256;             // z cols 128-255
            default:return Whm + 128*256;              // h cols 128-255
        }
    };
    // one W chunk: 128 gate rows x 32 K fp16 (64B) -> 80B rows
    auto wload = [&](const h16* Wg, int c, int s){
        #pragma unroll
        for (int t = 0; t < 2; t++){
            int u = tid + t*256;
            int row = u >> 2, q = u & 3;
            cpa16(sb + GRU_W_OFF + s*GRU_WSTG + row*80 + q*16,
                  Wg + (size_t)row*256 + c*32 + q*8);
        }
        CP_COMMIT();
    };

    wload(wptr(0), 0, 0);
    wload(wptr(0), 1, 1);

    for (int pass = 0; pass < 6; pass++){
        const h16* Wg;
        uint32_t aOff; int colOff, mode;
        switch(pass){
            case 0: Wg=wptr(0); aOff=GRU_A_OFF;  colOff=0;   mode=0; break;
            case 1: Wg=wptr(1); aOff=GRU_A_OFF;  colOff=0;   mode=1; break;
            case 2: Wg=wptr(2); aOff=GRU_A_OFF;  colOff=128; mode=1; break;
            case 3: Wg=wptr(3); aOff=GRU_RM_OFF; colOff=0;   mode=2; break;
            case 4: Wg=wptr(4); aOff=GRU_A_OFF;  colOff=128; mode=0; break;
            default:Wg=wptr(5); aOff=GRU_RM_OFF; colOff=128; mode=2; break;
        }
        uint32_t aBase = sb + aOff;

        float acc[2][4][4];
        #pragma unroll
        for (int i=0;i<2;i++)
            #pragma unroll
            for (int j=0;j<4;j++)
                #pragma unroll
                for (int k=0;k<4;k++) acc[i][j][k]=0.f;

        for (int c = 0; c < 8; c++){
            if (c == 7) CP_WAIT0(); else CP_WAIT1();
            __syncthreads();
            uint32_t sW = sb + GRU_W_OFF + (c & 1)*GRU_WSTG;
            #pragma unroll
            for (int s = 0; s < 2; s++){
                int kg = c*2 + s;
                uint32_t a[2][4];
                #pragma unroll
                for (int i = 0; i < 2; i++){
                    int rl = wm*32 + i*16 + (lane & 7) + ((lane & 8) ? 8 : 0);
                    uint32_t colb = kg*32 + ((lane & 16) ? 16 : 0);
                    ldsm4(a[i], aBase + rl*GRU_ROWSTR + colb);
                }
                uint32_t bf[4][2];
                #pragma unroll
                for (int jp = 0; jp < 2; jp++){
                    int nl = wn*32 + jp*16 + (lane & 7) + ((lane & 16) ? 8 : 0);
                    uint32_t colb = s*32 + ((lane & 8) ? 16 : 0);
                    uint32_t t4[4];
                    ldsm4(t4, sW + nl*80 + colb);
                    bf[2*jp][0]=t4[0]; bf[2*jp][1]=t4[1]; bf[2*jp+1][0]=t4[2]; bf[2*jp+1][1]=t4[3];
                }
                #pragma unroll
                for (int i=0;i<2;i++)
                    #pragma unroll
                    for (int j=0;j<4;j++) mma_f16(acc[i][j], a[i], bf[j]);
            }
            __syncthreads();
            if (c + 2 < 8) wload(Wg, c + 2, c & 1);
        }

        // prefetch next pass's first two W chunks before epilogue
        if (pass < 5){
            const h16* Wn = wptr(pass + 1);
            wload(Wn, 0, 0);
            wload(Wn, 1, 1);
        }

        // epilogue
        #pragma unroll
        for (int j = 0; j < 4; j++){
            int ccl = wn*32 + j*8 + (lane & 3)*2;   // local col 0..127
            int cc  = colOff + ccl;                 // global gate col
            #pragma unroll
            for (int i = 0; i < 2; i++){
                #pragma unroll
                for (int h = 0; h < 2; h++){
                    int rl = wm*32 + i*16 + (lane >> 2) + h*8;
                    int rr = m0 + rl, b = rr/9;
                    float v0 = acc[i][j][2*h], v1 = acc[i][j][2*h+1];
                    if (mode == 0){
                        float2 oz = __half22float2(*reinterpret_cast<const __half2*>(ozh + (size_t)b*768 + cc));
                        *reinterpret_cast<__half2*>(smem + GRU_ZS_OFF + zswz(rl, ccl)) =
                            __floats2half2_rn(sigf(v0+oz.x), sigf(v1+oz.y));
                    } else if (mode == 1){
                        float2 oz = __half22float2(*reinterpret_cast<const __half2*>(ozh + (size_t)b*768 + 256 + cc));
                        float2 mv = __half22float2(*reinterpret_cast<const __half2*>(smem + GRU_A_OFF + rl*GRU_ROWSTR + cc*2));
                        *reinterpret_cast<__half2*>(smem + GRU_RM_OFF + rl*GRU_ROWSTR + cc*2) =
                            __floats2half2_rn(sigf(v0+oz.x)*mv.x, sigf(v1+oz.y)*mv.y);
                    } else {
                        int m = rr - b*9 + 1;
                        float2 oz = __half22float2(*reinterpret_cast<const __half2*>(ozh + (size_t)b*768 + 512 + cc));
                        float mt0 = tanhf(v0+oz.x), mt1 = tanhf(v1+oz.y);
                        float2 zv = __half22float2(*reinterpret_cast<const __half2*>(smem + GRU_ZS_OFF + zswz(rl, ccl)));
                        float2 mv = __half22float2(*reinterpret_cast<const __half2*>(smem + GRU_A_OFF + rl*GRU_ROWSTR + cc*2));
                        *reinterpret_cast<float2*>(out_mem + (size_t)b*(ML_*256) + (size_t)(m-1)*256 + cc) =
                            make_float2(zv.x*mv.x + (1.f-zv.x)*mt0, zv.y*mv.y + (1.f-zv.y)*mt1);
                    }
                }
            }
        }
        __syncthreads();
    }
}

// ---------------- prep: fp16 weights + Wqk + biases ----------------
#define PB_QK   256
#define PB_BIAS 6
#define PB_WIGO 1536
#define PB_WZRM 512
#define PB_WHM  256
#define PB_WOZH 768
#define PB_WV   256
#define PB_TOTAL (PB_QK+PB_BIAS+PB_WIGO+PB_WZRM+PB_WHM+PB_WOZH+PB_WV)

__global__ void k_prep(const float* __restrict__ qW, const float* __restrict__ kW,
                       const float* __restrict__ qb,
                       const float* __restrict__ Wih,
                       const float* __restrict__ bih, const float* __restrict__ bhh,
                       const float* __restrict__ vW,
                       const float* __restrict__ zW, const float* __restrict__ rW,
                       const float* __restrict__ hW,
                       const float* __restrict__ zb, const float* __restrict__ rb,
                       const float* __restrict__ hb)
{
    int blk = blockIdx.x;
    if (blk < PB_QK){
        int j = blk, e = threadIdx.x;
        float s = 0.f;
        for (int d = 0; d < 256; d++) s = fmaf(qW[d*256 + e], kW[d*256 + j], s);
        g_Wqk[j*256 + e] = __float2half_rn(s);
        if (e == 0){
            float bq = 0.f;
            for (int d = 0; d < 256; d++) bq = fmaf(qb[d], kW[d*256 + j], bq);
            g_bqk[j] = bq;
        }
        return;
    } blk -= PB_QK;
    if (blk < PB_BIAS){
        int i = blk*256 + threadIdx.x;
        if (i < 768){
            int src = (i < 256) ? i : i + 256;
            g_bigo[i] = bih[src] + bhh[src];
        } else if (i < 1536){
            int n = i - 768;
            g_bozh[n] = (n < 256) ? zb[n] : (n < 512) ? rb[n-256] : hb[n-512];
        }
        return;
    } blk -= PB_BIAS;
    if (blk < PB_WIGO){
        int i = blk*256 + threadIdx.x;
        int n = i >> 9, k = i & 511;
        int src = (n < 256) ? n : n + 256;
        g_Wigo[i] = __float2half_rn(Wih[(size_t)src*512 + k]);
        return;
    } blk -= PB_WIGO;
    if (blk < PB_WZRM){
        int i = blk*256 + threadIdx.x;
        int n = i >> 8, k = i & 255;
        float v = (n < 256) ? zW[(size_t)n*512 + k] : rW[(size_t)(n-256)*512 + k];
        g_Wzrm[i] = __float2half_rn(v);
        return;
    } blk -= PB_WZRM;
    if (blk < PB_WHM){
        int i = blk*256 + threadIdx.x;
        int n = i >> 8, k = i & 255;
        g_Whm[i] = __float2half_rn(hW[(size_t)n*512 + k]);
        return;
    } blk -= PB_WHM;
    if (blk < PB_WOZH){
        int i = blk*256 + threadIdx.x;
        int n = i >> 8, k = i & 255;
        float v = (n < 256) ? zW[(size_t)n*512 + 256 + k]
                : (n < 512) ? rW[(size_t)(n-256)*512 + 256 + k]
                            : hW[(size_t)(n-512)*512 + 256 + k];
        g_Wozh[i] = __float2half_rn(v);
        return;
    } blk -= PB_WOZH;
    {
        int i = blk*256 + threadIdx.x;
        g_Wv[i] = __float2half_rn(vW[i]);
    }
}

// ---------------- frame weighting ----------------
__global__ void k_frame(const float* __restrict__ O_t, const float* __restrict__ O_prev,
                        const float* __restrict__ wW, const float* __restrict__ wb,
                        float* __restrict__ out_Wt)
{
    int b = blockIdx.x, t = threadIdx.x;
    float ot = O_t[(size_t)b*256 + t];
    float op = O_prev[(size_t)b*256 + t];
    float dl = ot - op;
    float s0 = ot*ot, s1 = op*op, s2 = dl*dl, s3 = ot*op;
    #pragma unroll
    for (int off = 16; off; off >>= 1){
        s0 += __shfl_xor_sync(0xffffffffu, s0, off);
        s1 += __shfl_xor_sync(0xffffffffu, s1, off);
        s2 += __shfl_xor_sync(0xffffffffu, s2, off);
        s3 += __shfl_xor_sync(0xffffffffu, s3, off);
    }
    __shared__ float4 ws[8];
    __shared__ float4 tot;
    int w = t >> 5;
    if ((t & 31) == 0) ws[w] = make_float4(s0, s1, s2, s3);
    __syncthreads();
    if (t == 0){
        float4 r = ws[0];
        #pragma unroll
        for (int i = 1; i < 8; i++){ r.x += ws[i].x; r.y += ws[i].y; r.z += ws[i].z; r.w += ws[i].w; }
        tot = r;
    }
    __syncthreads();
    float n_t = sqrtf(tot.x), n_p = sqrtf(tot.y), rd = sqrtf(tot.z);
    float ra  = tot.w / (n_t*n_p + 1e-6f);
    float wt  = 0.5f*(tanhf(n_t*wW[t*3+0] + rd*wW[t*3+1] + ra*wW[t*3+2] + wb[t]) + 1.f);
    out_Wt[(size_t)b*256 + t] = wt;
    g_X[(size_t)b*512 + t]       = __float2half_rn(op);
    g_X[(size_t)b*512 + 256 + t] = __float2half_rn(ot * wt);
}

// ---------------- LSTM activations (half2-vectorized) ----------------
__global__ void k_lstm_act(){
    int i = blockIdx.x*256 + threadIdx.x;       // over B_*128 half2 elements
    const __half2* G = reinterpret_cast<const __half2*>(g_gates);
    int b = i >> 7, d2 = i & 127;
    float2 ig = __half22float2(G[(size_t)b*384 + d2]);
    float2 gg = __half22float2(G[(size_t)b*384 + 128 + d2]);
    float2 og = __half22float2(G[(size_t)b*384 + 256 + d2]);
    float c0 = sigf(ig.x) * tanhf(gg.x);
    float c1 = sigf(ig.y) * tanhf(gg.y);
    reinterpret_cast<__half2*>(g_OTP)[i] =
        __floats2half2_rn(sigf(og.x)*tanhf(c0), sigf(og.y)*tanhf(c1));
}

// ---------------- attention (also emits fp16 memory copy, slots 1..9) ----------------
__global__ void k_attn(const float* __restrict__ memory){
    int b = blockIdx.x, t = threadIdx.x;
    float qk = __half2float(g_QK[(size_t)b*256 + t]);
    const float* mb = memory + (size_t)b*ML_*256;
    h16* mh = g_MEMh + (size_t)b*ML_*256;
    float mv[ML_];
    __shared__ float sc[ML_];
    __shared__ float attn[ML_];
    if (t < ML_) sc[t] = 0.f;
    __syncthreads();
    #pragma unroll
    for (int m = 0; m < ML_; m++){
        mv[m] = mb[m*256 + t];
        if (m >= 1) mh[m*256 + t] = __float2half_rn(mv[m]);
        float v = qk * mv[m];
        #pragma unroll
        for (int off = 16; off; off >>= 1) v += __shfl_xor_sync(0xffffffffu, v, off);
        if ((t & 31) == 0) atomicAdd(&sc[m], v);
    }
    __syncthreads();
    if (t == 0){
        float mx = -1e30f;
        #pragma unroll
        for (int m = 0; m < ML_; m++){ sc[m] *= 0.0625f; mx = fmaxf(mx, sc[m]); }
        float e[ML_], s = 0.f;
        #pragma unroll
        for (int m = 0; m < ML_; m++){ e[m] = expf(sc[m] - mx); s += e[m]; }
        float inv = 1.f / s;
        #pragma unroll
        for (int m = 0; m < ML_; m++) attn[m] = e[m] * inv;
    }
    __syncthreads();
    float wm = 0.f;
    #pragma unroll
    for (int m = 0; m < ML_; m++) wm += attn[m] * mv[m];
    g_WM[(size_t)b*256 + t] = __float2half_rn(wm);
}

// ---------------- launcher ----------------
extern "C" void kernel_launch(void* const* d_in, const int* in_sizes, int n_in,
                              void* d_out, int out_size)
{
    const float* O_t     = (const float*)d_in[0];
    const float* O_prev  = (const float*)d_in[1];
    const float* memory  = (const float*)d_in[2];
    const float* w_mlp_W = (const float*)d_in[3];
    const float* w_mlp_b = (const float*)d_in[4];
    const float* lstm_Wih= (const float*)d_in[5];
    const float* lstm_bih= (const float*)d_in[7];
    const float* lstm_bhh= (const float*)d_in[8];
    const float* q_W = (const float*)d_in[9];   const float* q_b = (const float*)d_in[10];
    const float* k_W = (const float*)d_in[11];  // k_b cancels in softmax
    const float* v_W = (const float*)d_in[13];  const float* v_b = (const float*)d_in[14];
    const float* z_W = (const float*)d_in[15];  const float* z_b = (const float*)d_in[16];
    const float* r_W = (const float*)d_in[17];  const float* r_b = (const float*)d_in[18];
    const float* h_W = (const float*)d_in[19];  const float* h_b = (const float*)d_in[20];

    float* out      = (float*)d_out;
    float* out0     = out;
    float* out_mem  = out0 + (size_t)B_*D_;
    float* out2     = out_mem + (size_t)B_*ML_*D_;
    float* out3     = out2 + (size_t)B_*D_;

    cudaFuncSetAttribute(k_mma<5>, cudaFuncAttributeMaxDynamicSharedMemorySize, SMEM_TOTAL);
    cudaFuncSetAttribute(k_mma<2>, cudaFuncAttributeMaxDynamicSharedMemorySize, SMEM_TOTAL);
    cudaFuncSetAttribute(k_gru,    cudaFuncAttributeMaxDynamicSharedMemorySize, GRU_SMEM);

    float *pbigo,*pbozh,*pbqk;
    h16 *pQK,*pGates,*pOZH,*pX,*pOTP,*pWM,*pOUP,*pMEMh;
    h16 *pWigo,*pWqk,*pWv,*pWzrm,*pWhm,*pWozh;
    cudaGetSymbolAddress((void**)&pQK,    g_QK);
    cudaGetSymbolAddress((void**)&pbigo,  g_bigo);
    cudaGetSymbolAddress((void**)&pbozh,  g_bozh);
    cudaGetSymbolAddress((void**)&pbqk,   g_bqk);
    cudaGetSymbolAddress((void**)&pGates, g_gates);
    cudaGetSymbolAddress((void**)&pOZH,   g_OZH);
    cudaGetSymbolAddress((void**)&pX,     g_X);
    cudaGetSymbolAddress((void**)&pOTP,   g_OTP);
    cudaGetSymbolAddress((void**)&pWM,    g_WM);
    cudaGetSymbolAddress((void**)&pOUP,   g_OUP);
    cudaGetSymbolAddress((void**)&pMEMh,  g_MEMh);
    cudaGetSymbolAddress((void**)&pWigo,  g_Wigo);
    cudaGetSymbolAddress((void**)&pWqk,   g_Wqk);
    cudaGetSymbolAddress((void**)&pWv,    g_Wv);
    cudaGetSymbolAddress((void**)&pWzrm,  g_Wzrm);
    cudaGetSymbolAddress((void**)&pWhm,   g_Whm);
    cudaGetSymbolAddress((void**)&pWozh,  g_Wozh);

    // 1: prep (fp16 weights, Wqk, biases)
    k_prep<<<PB_TOTAL, 256>>>(q_W, k_W, q_b, lstm_Wih, lstm_bih, lstm_bhh,
                              v_W, z_W, r_W, h_W, z_b, r_b, h_b);
    // 2: frame weighting -> X (fp16) + W_t out
    k_frame<<<B_, 256>>>(O_t, O_prev, w_mlp_W, w_mlp_b, out3);
    // 3: LSTM gates [B,768] fp16, K=512
    k_mma<5><<<dim3(6, B_/128), 256, SMEM_TOTAL>>>(
        pX, pWigo, pbigo, pGates, nullptr, nullptr, nullptr,
        B_, 768, 512);
    // 4: LSTM activations -> OTP (fp16), half2-vectorized
    k_lstm_act<<<(B_*128)/256, 256>>>();
    // 5: QK = OTP @ Wqk^T + bqk  [B,256] fp16
    k_mma<5><<<dim3(2, B_/128), 256, SMEM_TOTAL>>>(
        pOTP, pWqk, pbqk, pQK, nullptr, nullptr, nullptr,
        B_, 256, 256);
    // 6: attention -> WM (fp16) + MEMh (fp16 memory copy)
    k_attn<<<B_, 256>>>(memory);
    // 7: V GEMM -> OUP (fp16) + out0/out2/mem slot 9 (fp32)
    k_mma<2><<<dim3(2, B_/128), 256, SMEM_TOTAL>>>(
        pWM, pWv, v_b, pOUP, out0, out_mem, out2,
        B_, 256, 256);
    // 8: OZH = O_up @ Wozh^T + bozh  [B,768] fp16
    k_mma<5><<<dim3(6, B_/128), 256, SMEM_TOTAL>>>(
        pOUP, pWozh, pbozh, pOZH, nullptr, nullptr, nullptr,
        B_, 768, 256);
    // 9: fused GRU v3 (64-row CTAs, 2 CTAs/SM)
    k_gru<<<M2_/64, 256, GRU_SMEM>>>(pMEMh, pWzrm, pWhm, pOZH, out_mem);
}

// round 14
// speedup vs baseline: 6.5922x; 1.0477x over previous
#include <cuda_runtime.h>
#include <cuda_fp16.h>
#include <math.h>
#include <stdint.h>

#define B_   16384
#define D_   256
#define ML_  10
#define M2_  (B_*9)

typedef __half h16;

// ---------------- fp16 scratch ----------------
__device__ __align__(256) h16 g_QK   [(size_t)B_*256];
__device__ __align__(256) h16 g_gates[(size_t)B_*768];
__device__ __align__(256) h16 g_OZH  [(size_t)B_*768];
__device__ __align__(256) h16 g_X   [(size_t)B_*512];
__device__ __align__(256) h16 g_OTP [(size_t)B_*256];
__device__ __align__(256) h16 g_WM  [(size_t)B_*256];
__device__ __align__(256) h16 g_OUP [(size_t)B_*256];
__device__ __align__(256) h16 g_MEMh[(size_t)B_*ML_*256];
// ---------------- fp16 weights ----------------
__device__ __align__(256) h16 g_Wigo [768*512];
__device__ __align__(256) h16 g_Wqk  [65536];
__device__ __align__(256) h16 g_Wv   [65536];
__device__ __align__(256) h16 g_Wzrm [512*256];
__device__ __align__(256) h16 g_Whm  [256*256];
__device__ __align__(256) h16 g_Wozh [768*256];
__device__ __align__(256) float g_bigo[768];
__device__ __align__(256) float g_bozh[768];
__device__ __align__(256) float g_bqk [256];

__device__ __forceinline__ float sigf(float x){ return 1.f/(1.f+expf(-x)); }

// ---------------- PTX helpers (base ISA only) ----------------
__device__ __forceinline__ uint32_t smem_u32(const void* p){
    uint32_t a; asm("{ .reg .u64 t; cvta.to.shared.u64 t, %1; cvt.u32.u64 %0, t; }" : "=r"(a) : "l"(p));
    return a;
}
__device__ __forceinline__ void ldsm4(uint32_t* r, uint32_t addr){
    asm volatile("ldmatrix.sync.aligned.m8n8.x4.shared.b16 {%0,%1,%2,%3}, [%4];"
        : "=r"(r[0]),"=r"(r[1]),"=r"(r[2]),"=r"(r[3]) : "r"(addr));
}
__device__ __forceinline__ void mma_f16(float* c, const uint32_t* a, const uint32_t* b){
    asm volatile("mma.sync.aligned.m16n8k16.row.col.f32.f16.f16.f32 "
        "{%0,%1,%2,%3}, {%4,%5,%6,%7}, {%8,%9}, {%0,%1,%2,%3};"
        : "+f"(c[0]),"+f"(c[1]),"+f"(c[2]),"+f"(c[3])
        : "r"(a[0]),"r"(a[1]),"r"(a[2]),"r"(a[3]), "r"(b[0]),"r"(b[1]));
}
__device__ __forceinline__ void cpa16(uint32_t dst, const void* src){
    asm volatile("cp.async.cg.shared.global [%0], [%1], 16;" :: "r"(dst), "l"(src));
}
#define CP_COMMIT() asm volatile("cp.async.commit_group;" ::: "memory")
#define CP_WAIT1()  asm volatile("cp.async.wait_group 1;"  ::: "memory")
#define CP_WAIT0()  asm volatile("cp.async.wait_group 0;"  ::: "memory")

#define ROWB     144
#define STAGE_SZ 36864
#define SMEM_TOTAL (3*STAGE_SZ)

// ================== fp16 HMMA GEMM: C[M,N] = A[M,K] @ W[N,K]^T ==================
// CTA 128x128, 8 warps (2x4), warp tile 64x32, K-chunk 64, 3-stage cp.async, 2 CTAs/SM.
// EPI 5: C16 fp16 = v + bias[col]
// EPI 2: V-mode: v+=bias; fp16(v) -> C16(=OUP); v -> out0, out2, out_mem slot 9
template<int EPI>
__global__ void __launch_bounds__(256,2) k_mma(
    const h16* __restrict__ A,
    const h16* __restrict__ W,
    const float* __restrict__ bias,
    h16* __restrict__ C16,
    float* __restrict__ out0, float* __restrict__ out_mem, float* __restrict__ out2,
    int M, int N, int K)
{
    extern __shared__ char smem[];
    uint32_t sb = smem_u32(smem);
    const int tid = threadIdx.x, lane = tid & 31, w = tid >> 5;
    const int wm = w >> 2, wn = w & 3;
    const int m0 = blockIdx.y * 128, n0 = blockIdx.x * 128;
    const int nch = K >> 6;

    float acc[4][4][4];
    #pragma unroll
    for (int i=0;i<4;i++)
        #pragma unroll
        for (int j=0;j<4;j++)
            #pragma unroll
            for (int k=0;k<4;k++) acc[i][j][k]=0.f;

    auto load_chunk = [&](int c, int s){
        uint32_t st = sb + s*STAGE_SZ;
        #pragma unroll
        for (int t=0;t<4;t++){
            int u = tid + t*256;
            int row = u >> 3, q = u & 7;
            cpa16(st + row*ROWB + q*16, A + (size_t)(m0+row)*K + c*64 + q*8);
        }
        #pragma unroll
        for (int t=0;t<4;t++){
            int u = tid + t*256;
            int row = u >> 3, q = u & 7;
            cpa16(st + 18432 + row*ROWB + q*16, W + (size_t)(n0+row)*K + c*64 + q*8);
        }
        CP_COMMIT();
    };

    load_chunk(0, 0);
    load_chunk(1, 1);

    for (int c = 0; c < nch; c++){
        if (c == nch - 1) CP_WAIT0(); else CP_WAIT1();
        __syncthreads();
        if (c + 2 < nch) load_chunk(c + 2, (c + 2) % 3);

        uint32_t sA = sb + (c % 3)*STAGE_SZ;
        uint32_t sW = sA + 18432;
        #pragma unroll
        for (int kk = 0; kk < 4; kk++){
            uint32_t a[4][4];
            #pragma unroll
            for (int i = 0; i < 4; i++){
                int rl = wm*64 + i*16 + (lane & 7) + ((lane & 8) ? 8 : 0);
                uint32_t colb = kk*32 + ((lane & 16) ? 16 : 0);
                ldsm4(a[i], sA + rl*ROWB + colb);
            }
            uint32_t bf[4][2];
            #pragma unroll
            for (int jp = 0; jp < 2; jp++){
                int nl = wn*32 + jp*16 + (lane & 7) + ((lane & 16) ? 8 : 0);
                uint32_t colb = kk*32 + ((lane & 8) ? 16 : 0);
                uint32_t t4[4];
                ldsm4(t4, sW + nl*ROWB + colb);
                bf[2*jp][0]=t4[0]; bf[2*jp][1]=t4[1]; bf[2*jp+1][0]=t4[2]; bf[2*jp+1][1]=t4[3];
            }
            #pragma unroll
            for (int i=0;i<4;i++)
                #pragma unroll
                for (int j=0;j<4;j++) mma_f16(acc[i][j], a[i], bf[j]);
        }
        __syncthreads();
    }

    #pragma unroll
    for (int j = 0; j < 4; j++){
        int col = n0 + wn*32 + j*8 + (lane & 3)*2;
        float b0 = bias ? bias[col]   : 0.f;
        float b1 = bias ? bias[col+1] : 0.f;
        #pragma unroll
        for (int i = 0; i < 4; i++){
            int row = m0 + wm*64 + i*16 + (lane >> 2);
            #pragma unroll
            for (int h = 0; h < 2; h++){
                int rr = row + h*8;
                float v0 = acc[i][j][2*h+0] + b0;
                float v1 = acc[i][j][2*h+1] + b1;
                if (EPI == 5){
                    *reinterpret_cast<__half2*>(C16 + (size_t)rr*N + col) = __floats2half2_rn(v0, v1);
                } else {  // EPI 2
                    size_t o = (size_t)rr*256 + col;
                    float2 fv = make_float2(v0, v1);
                    *reinterpret_cast<__half2*>(C16 + o) = __floats2half2_rn(v0, v1);
                    *reinterpret_cast<float2*>(out0 + o) = fv;
                    *reinterpret_cast<float2*>(out2 + o) = fv;
                    *reinterpret_cast<float2*>(out_mem + (size_t)rr*(ML_*256) + 9*256 + col) = fv;
                }
            }
        }
    }
}

// ================== fused GRU v3: 64-row CTAs, 2 CTAs/SM ==================
#define GRU_ROWSTR 528
#define GRU_A_OFF  0
#define GRU_RM_OFF 33792
#define GRU_ZS_OFF 67584
#define GRU_W_OFF  83968
#define GRU_WSTG   10240
#define GRU_SMEM   104448

__device__ __forceinline__ uint32_t zswz(int rl, int ccl){
    return (uint32_t)((rl*256 + ccl*2) ^ ((rl & 7) << 4));
}

__global__ void __launch_bounds__(256,2) k_gru(
    const h16* __restrict__ memh,
    const h16* __restrict__ Wzrm, const h16* __restrict__ Whm,
    const h16* __restrict__ ozh,
    float* __restrict__ out_mem)
{
    extern __shared__ char smem[];
    uint32_t sb = smem_u32(smem);
    const int tid = threadIdx.x, lane = tid & 31, w = tid >> 5;
    const int wm = w >> 2, wn = w & 3;
    const int m0 = blockIdx.x * 64;

    #pragma unroll
    for (int t = 0; t < 8; t++){
        int u = tid + t*256;
        int row = u >> 5, q = u & 31;
        int rr = m0 + row, b = rr/9, m = rr - b*9 + 1;
        cpa16(sb + GRU_A_OFF + row*GRU_ROWSTR + q*16,
              memh + ((size_t)b*10 + m)*256 + q*8);
    }
    CP_COMMIT(); CP_WAIT0(); __syncthreads();

    auto wptr = [&](int p)->const h16*{
        switch(p){
            case 0: return Wzrm;
            case 1: return Wzrm + 256*256;
            case 2: return Wzrm + 384*256;
            case 3: return Whm;
            case 4: return Wzrm + 128*256;
            default:return Whm + 128*256;
        }
    };
    auto wload = [&](const h16* Wg, int c, int s){
        #pragma unroll
        for (int t = 0; t < 2; t++){
            int u = tid + t*256;
            int row = u >> 2, q = u & 3;
            cpa16(sb + GRU_W_OFF + s*GRU_WSTG + row*80 + q*16,
                  Wg + (size_t)row*256 + c*32 + q*8);
        }
        CP_COMMIT();
    };

    wload(wptr(0), 0, 0);
    wload(wptr(0), 1, 1);

    for (int pass = 0; pass < 6; pass++){
        const h16* Wg;
        uint32_t aOff; int colOff, mode;
        switch(pass){
            case 0: Wg=wptr(0); aOff=GRU_A_OFF;  colOff=0;   mode=0; break;
            case 1: Wg=wptr(1); aOff=GRU_A_OFF;  colOff=0;   mode=1; break;
            case 2: Wg=wptr(2); aOff=GRU_A_OFF;  colOff=128; mode=1; break;
            case 3: Wg=wptr(3); aOff=GRU_RM_OFF; colOff=0;   mode=2; break;
            case 4: Wg=wptr(4); aOff=GRU_A_OFF;  colOff=128; mode=0; break;
            default:Wg=wptr(5); aOff=GRU_RM_OFF; colOff=128; mode=2; break;
        }
        uint32_t aBase = sb + aOff;

        float acc[2][4][4];
        #pragma unroll
        for (int i=0;i<2;i++)
            #pragma unroll
            for (int j=0;j<4;j++)
                #pragma unroll
                for (int k=0;k<4;k++) acc[i][j][k]=0.f;

        for (int c = 0; c < 8; c++){
            if (c == 7) CP_WAIT0(); else CP_WAIT1();
            __syncthreads();
            uint32_t sW = sb + GRU_W_OFF + (c & 1)*GRU_WSTG;
            #pragma unroll
            for (int s = 0; s < 2; s++){
                int kg = c*2 + s;
                uint32_t a[2][4];
                #pragma unroll
                for (int i = 0; i < 2; i++){
                    int rl = wm*32 + i*16 + (lane & 7) + ((lane & 8) ? 8 : 0);
                    uint32_t colb = kg*32 + ((lane & 16) ? 16 : 0);
                    ldsm4(a[i], aBase + rl*GRU_ROWSTR + colb);
                }
                uint32_t bf[4][2];
                #pragma unroll
                for (int jp = 0; jp < 2; jp++){
                    int nl = wn*32 + jp*16 + (lane & 7) + ((lane & 16) ? 8 : 0);
                    uint32_t colb = s*32 + ((lane & 8) ? 16 : 0);
                    uint32_t t4[4];
                    ldsm4(t4, sW + nl*80 + colb);
                    bf[2*jp][0]=t4[0]; bf[2*jp][1]=t4[1]; bf[2*jp+1][0]=t4[2]; bf[2*jp+1][1]=t4[3];
                }
                #pragma unroll
                for (int i=0;i<2;i++)
                    #pragma unroll
                    for (int j=0;j<4;j++) mma_f16(acc[i][j], a[i], bf[j]);
            }
            __syncthreads();
            if (c + 2 < 8) wload(Wg, c + 2, c & 1);
        }

        if (pass < 5){
            const h16* Wn = wptr(pass + 1);
            wload(Wn, 0, 0);
            wload(Wn, 1, 1);
        }

        #pragma unroll
        for (int j = 0; j < 4; j++){
            int ccl = wn*32 + j*8 + (lane & 3)*2;
            int cc  = colOff + ccl;
            #pragma unroll
            for (int i = 0; i < 2; i++){
                #pragma unroll
                for (int h = 0; h < 2; h++){
                    int rl = wm*32 + i*16 + (lane >> 2) + h*8;
                    int rr = m0 + rl, b = rr/9;
                    float v0 = acc[i][j][2*h], v1 = acc[i][j][2*h+1];
                    if (mode == 0){
                        float2 oz = __half22float2(*reinterpret_cast<const __half2*>(ozh + (size_t)b*768 + cc));
                        *reinterpret_cast<__half2*>(smem + GRU_ZS_OFF + zswz(rl, ccl)) =
                            __floats2half2_rn(sigf(v0+oz.x), sigf(v1+oz.y));
                    } else if (mode == 1){
                        float2 oz = __half22float2(*reinterpret_cast<const __half2*>(ozh + (size_t)b*768 + 256 + cc));
                        float2 mv = __half22float2(*reinterpret_cast<const __half2*>(smem + GRU_A_OFF + rl*GRU_ROWSTR + cc*2));
                        *reinterpret_cast<__half2*>(smem + GRU_RM_OFF + rl*GRU_ROWSTR + cc*2) =
                            __floats2half2_rn(sigf(v0+oz.x)*mv.x, sigf(v1+oz.y)*mv.y);
                    } else {
                        int m = rr - b*9 + 1;
                        float2 oz = __half22float2(*reinterpret_cast<const __half2*>(ozh + (size_t)b*768 + 512 + cc));
                        float mt0 = tanhf(v0+oz.x), mt1 = tanhf(v1+oz.y);
                        float2 zv = __half22float2(*reinterpret_cast<const __half2*>(smem + GRU_ZS_OFF + zswz(rl, ccl)));
                        float2 mv = __half22float2(*reinterpret_cast<const __half2*>(smem + GRU_A_OFF + rl*GRU_ROWSTR + cc*2));
                        *reinterpret_cast<float2*>(out_mem + (size_t)b*(ML_*256) + (size_t)(m-1)*256 + cc) =
                            make_float2(zv.x*mv.x + (1.f-zv.x)*mt0, zv.y*mv.y + (1.f-zv.y)*mt1);
                    }
                }
            }
        }
        __syncthreads();
    }
}

// ---------------- fused front launch: weights + Wqk + biases + frame + memconvert ----------------
#define PB_QK    256
#define PB_BIAS  6
#define PB_WIGO  1536
#define PB_WZRM  512
#define PB_WHM   256
#define PB_WOZH  768
#define PB_WV    256
#define PB_MEMC  20480
#define PB_FRAME 16384
#define PB_TOTAL (PB_QK+PB_BIAS+PB_WIGO+PB_WZRM+PB_WHM+PB_WOZH+PB_WV+PB_MEMC+PB_FRAME)

__global__ void k_prep_all(const float* __restrict__ qW, const float* __restrict__ kW,
                           const float* __restrict__ qb,
                           const float* __restrict__ Wih,
                           const float* __restrict__ bih, const float* __restrict__ bhh,
                           const float* __restrict__ vW,
                           const float* __restrict__ zW, const float* __restrict__ rW,
                           const float* __restrict__ hW,
                           const float* __restrict__ zb, const float* __restrict__ rb,
                           const float* __restrict__ hb,
                           const float* __restrict__ memory,
                           const float* __restrict__ O_t, const float* __restrict__ O_prev,
                           const float* __restrict__ wW, const float* __restrict__ wb,
                           float* __restrict__ out_Wt)
{
    int blk = blockIdx.x;
    if (blk < PB_QK){
        int j = blk, e = threadIdx.x;
        float s = 0.f;
        for (int d = 0; d < 256; d++) s = fmaf(qW[d*256 + e], kW[d*256 + j], s);
        g_Wqk[j*256 + e] = __float2half_rn(s);
        if (e == 0){
            float bq = 0.f;
            for (int d = 0; d < 256; d++) bq = fmaf(qb[d], kW[d*256 + j], bq);
            g_bqk[j] = bq;
        }
        return;
    } blk -= PB_QK;
    if (blk < PB_BIAS){
        int i = blk*256 + threadIdx.x;
        if (i < 768){
            int src = (i < 256) ? i : i + 256;
            g_bigo[i] = bih[src] + bhh[src];
        } else if (i < 1536){
            int n = i - 768;
            g_bozh[n] = (n < 256) ? zb[n] : (n < 512) ? rb[n-256] : hb[n-512];
        }
        return;
    } blk -= PB_BIAS;
    if (blk < PB_WIGO){
        int i = blk*256 + threadIdx.x;
        int n = i >> 9, k = i & 511;
        int src = (n < 256) ? n : n + 256;
        g_Wigo[i] = __float2half_rn(Wih[(size_t)src*512 + k]);
        return;
    } blk -= PB_WIGO;
    if (blk < PB_WZRM){
        int i = blk*256 + threadIdx.x;
        int n = i >> 8, k = i & 255;
        float v = (n < 256) ? zW[(size_t)n*512 + k] : rW[(size_t)(n-256)*512 + k];
        g_Wzrm[i] = __float2half_rn(v);
        return;
    } blk -= PB_WZRM;
    if (blk < PB_WHM){
        int i = blk*256 + threadIdx.x;
        int n = i >> 8, k = i & 255;
        g_Whm[i] = __float2half_rn(hW[(size_t)n*512 + k]);
        return;
    } blk -= PB_WHM;
    if (blk < PB_WOZH){
        int i = blk*256 + threadIdx.x;
        int n = i >> 8, k = i & 255;
        float v = (n < 256) ? zW[(size_t)n*512 + 256 + k]
                : (n < 512) ? rW[(size_t)(n-256)*512 + 256 + k]
                            : hW[(size_t)(n-512)*512 + 256 + k];
        g_Wozh[i] = __float2half_rn(v);
        return;
    } blk -= PB_WOZH;
    if (blk < PB_WV){
        int i = blk*256 + threadIdx.x;
        g_Wv[i] = __float2half_rn(vW[i]);
        return;
    } blk -= PB_WV;
    if (blk < PB_MEMC){
        // convert all 10 slots of memory to fp16 (8 elems/thread)
        size_t base = ((size_t)blk*256 + threadIdx.x) * 8;
        float4 a = *reinterpret_cast<const float4*>(memory + base);
        float4 bq = *reinterpret_cast<const float4*>(memory + base + 4);
        __half2 o0 = __floats2half2_rn(a.x, a.y);
        __half2 o1 = __floats2half2_rn(a.z, a.w);
        __half2 o2 = __floats2half2_rn(bq.x, bq.y);
        __half2 o3 = __floats2half2_rn(bq.z, bq.w);
        uint4 pk;
        pk.x = *reinterpret_cast<uint32_t*>(&o0);
        pk.y = *reinterpret_cast<uint32_t*>(&o1);
        pk.z = *reinterpret_cast<uint32_t*>(&o2);
        pk.w = *reinterpret_cast<uint32_t*>(&o3);
        *reinterpret_cast<uint4*>(g_MEMh + base) = pk;
        return;
    } blk -= PB_MEMC;
    {
        // frame weighting
        int b = blk, t = threadIdx.x;
        float ot = O_t[(size_t)b*256 + t];
        float op = O_prev[(size_t)b*256 + t];
        float dl = ot - op;
        float s0 = ot*ot, s1 = op*op, s2 = dl*dl, s3 = ot*op;
        #pragma unroll
        for (int off = 16; off; off >>= 1){
            s0 += __shfl_xor_sync(0xffffffffu, s0, off);
            s1 += __shfl_xor_sync(0xffffffffu, s1, off);
            s2 += __shfl_xor_sync(0xffffffffu, s2, off);
            s3 += __shfl_xor_sync(0xffffffffu, s3, off);
        }
        __shared__ float4 ws[8];
        __shared__ float4 tot;
        int w = t >> 5;
        if ((t & 31) == 0) ws[w] = make_float4(s0, s1, s2, s3);
        __syncthreads();
        if (t == 0){
            float4 r = ws[0];
            #pragma unroll
            for (int i = 1; i < 8; i++){ r.x += ws[i].x; r.y += ws[i].y; r.z += ws[i].z; r.w += ws[i].w; }
            tot = r;
        }
        __syncthreads();
        float n_t = sqrtf(tot.x), n_p = sqrtf(tot.y), rd = sqrtf(tot.z);
        float ra  = tot.w / (n_t*n_p + 1e-6f);
        float wt  = 0.5f*(tanhf(n_t*wW[t*3+0] + rd*wW[t*3+1] + ra*wW[t*3+2] + wb[t]) + 1.f);
        out_Wt[(size_t)b*256 + t] = wt;
        g_X[(size_t)b*512 + t]       = __float2half_rn(op);
        g_X[(size_t)b*512 + 256 + t] = __float2half_rn(ot * wt);
    }
}

// ---------------- LSTM activations (half2-vectorized) ----------------
__global__ void k_lstm_act(){
    int i = blockIdx.x*256 + threadIdx.x;
    const __half2* G = reinterpret_cast<const __half2*>(g_gates);
    int b = i >> 7, d2 = i & 127;
    float2 ig = __half22float2(G[(size_t)b*384 + d2]);
    float2 gg = __half22float2(G[(size_t)b*384 + 128 + d2]);
    float2 og = __half22float2(G[(size_t)b*384 + 256 + d2]);
    float c0 = sigf(ig.x) * tanhf(gg.x);
    float c1 = sigf(ig.y) * tanhf(gg.y);
    reinterpret_cast<__half2*>(g_OTP)[i] =
        __floats2half2_rn(sigf(og.x)*tanhf(c0), sigf(og.y)*tanhf(c1));
}

// ---------------- attention v2: 1 warp per batch row, fp16 memory, no smem ----------------
__global__ void __launch_bounds__(256) k_attn(){
    int b = blockIdx.x*8 + (threadIdx.x >> 5);
    int lane = threadIdx.x & 31;

    // load this lane's 8 QK values
    uint4 qv = *reinterpret_cast<const uint4*>(g_QK + (size_t)b*256 + lane*8);
    float qf[8];
    {
        float2 t;
        t = __half22float2(*reinterpret_cast<__half2*>(&qv.x)); qf[0]=t.x; qf[1]=t.y;
        t = __half22float2(*reinterpret_cast<__half2*>(&qv.y)); qf[2]=t.x; qf[3]=t.y;
        t = __half22float2(*reinterpret_cast<__half2*>(&qv.z)); qf[4]=t.x; qf[5]=t.y;
        t = __half22float2(*reinterpret_cast<__half2*>(&qv.w)); qf[6]=t.x; qf[7]=t.y;
    }

    uint4 mv[ML_];
    float sc[ML_];
    const h16* mb = g_MEMh + (size_t)b*ML_*256;
    #pragma unroll
    for (int m = 0; m < ML_; m++){
        mv[m] = *reinterpret_cast<const uint4*>(mb + m*256 + lane*8);
        float s = 0.f;
        const __half2* hp = reinterpret_cast<const __half2*>(&mv[m]);
        #pragma unroll
        for (int q = 0; q < 4; q++){
            float2 f = __half22float2(hp[q]);
            s = fmaf(qf[2*q], f.x, s);
            s = fmaf(qf[2*q+1], f.y, s);
        }
        #pragma unroll
        for (int off = 16; off; off >>= 1) s += __shfl_xor_sync(0xffffffffu, s, off);
        sc[m] = s * 0.0625f;
    }
    // softmax (redundant per lane)
    float mx = sc[0];
    #pragma unroll
    for (int m = 1; m < ML_; m++) mx = fmaxf(mx, sc[m]);
    float e[ML_], ssum = 0.f;
    #pragma unroll
    for (int m = 0; m < ML_; m++){ e[m] = expf(sc[m] - mx); ssum += e[m]; }
    float inv = 1.f / ssum;

    float wm[8];
    #pragma unroll
    for (int q = 0; q < 8; q++) wm[q] = 0.f;
    #pragma unroll
    for (int m = 0; m < ML_; m++){
        float am = e[m] * inv;
        const __half2* hp = reinterpret_cast<const __half2*>(&mv[m]);
        #pragma unroll
        for (int q = 0; q < 4; q++){
            float2 f = __half22float2(hp[q]);
            wm[2*q]   = fmaf(am, f.x, wm[2*q]);
            wm[2*q+1] = fmaf(am, f.y, wm[2*q+1]);
        }
    }
    __half2 o0 = __floats2half2_rn(wm[0], wm[1]);
    __half2 o1 = __floats2half2_rn(wm[2], wm[3]);
    __half2 o2 = __floats2half2_rn(wm[4], wm[5]);
    __half2 o3 = __floats2half2_rn(wm[6], wm[7]);
    uint4 pk;
    pk.x = *reinterpret_cast<uint32_t*>(&o0);
    pk.y = *reinterpret_cast<uint32_t*>(&o1);
    pk.z = *reinterpret_cast<uint32_t*>(&o2);
    pk.w = *reinterpret_cast<uint32_t*>(&o3);
    *reinterpret_cast<uint4*>(g_WM + (size_t)b*256 + lane*8) = pk;
}

// ---------------- launcher ----------------
extern "C" void kernel_launch(void* const* d_in, const int* in_sizes, int n_in,
                              void* d_out, int out_size)
{
    const float* O_t     = (const float*)d_in[0];
    const float* O_prev  = (const float*)d_in[1];
    const float* memory  = (const float*)d_in[2];
    const float* w_mlp_W = (const float*)d_in[3];
    const float* w_mlp_b = (const float*)d_in[4];
    const float* lstm_Wih= (const float*)d_in[5];
    const float* lstm_bih= (const float*)d_in[7];
    const float* lstm_bhh= (const float*)d_in[8];
    const float* q_W = (const float*)d_in[9];   const float* q_b = (const float*)d_in[10];
    const float* k_W = (const float*)d_in[11];  // k_b cancels in softmax
    const float* v_W = (const float*)d_in[13];  const float* v_b = (const float*)d_in[14];
    const float* z_W = (const float*)d_in[15];  const float* z_b = (const float*)d_in[16];
    const float* r_W = (const float*)d_in[17];  const float* r_b = (const float*)d_in[18];
    const float* h_W = (const float*)d_in[19];  const float* h_b = (const float*)d_in[20];

    float* out      = (float*)d_out;
    float* out0     = out;
    float* out_mem  = out0 + (size_t)B_*D_;
    float* out2     = out_mem + (size_t)B_*ML_*D_;
    float* out3     = out2 + (size_t)B_*D_;

    cudaFuncSetAttribute(k_mma<5>, cudaFuncAttributeMaxDynamicSharedMemorySize, SMEM_TOTAL);
    cudaFuncSetAttribute(k_mma<2>, cudaFuncAttributeMaxDynamicSharedMemorySize, SMEM_TOTAL);
    cudaFuncSetAttribute(k_gru,    cudaFuncAttributeMaxDynamicSharedMemorySize, GRU_SMEM);

    float *pbigo,*pbozh,*pbqk;
    h16 *pQK,*pGates,*pOZH,*pX,*pOTP,*pWM,*pOUP,*pMEMh;
    h16 *pWigo,*pWqk,*pWv,*pWzrm,*pWhm,*pWozh;
    cudaGetSymbolAddress((void**)&pQK,    g_QK);
    cudaGetSymbolAddress((void**)&pbigo,  g_bigo);
    cudaGetSymbolAddress((void**)&pbozh,  g_bozh);
    cudaGetSymbolAddress((void**)&pbqk,   g_bqk);
    cudaGetSymbolAddress((void**)&pGates, g_gates);
    cudaGetSymbolAddress((void**)&pOZH,   g_OZH);
    cudaGetSymbolAddress((void**)&pX,     g_X);
    cudaGetSymbolAddress((void**)&pOTP,   g_OTP);
    cudaGetSymbolAddress((void**)&pWM,    g_WM);
    cudaGetSymbolAddress((void**)&pOUP,   g_OUP);
    cudaGetSymbolAddress((void**)&pMEMh,  g_MEMh);
    cudaGetSymbolAddress((void**)&pWigo,  g_Wigo);
    cudaGetSymbolAddress((void**)&pWqk,   g_Wqk);
    cudaGetSymbolAddress((void**)&pWv,    g_Wv);
    cudaGetSymbolAddress((void**)&pWzrm,  g_Wzrm);
    cudaGetSymbolAddress((void**)&pWhm,   g_Whm);
    cudaGetSymbolAddress((void**)&pWozh,  g_Wozh);

    // 1: fused front (weights + Wqk + biases + frame + mem->fp16)
    k_prep_all<<<PB_TOTAL, 256>>>(q_W, k_W, q_b, lstm_Wih, lstm_bih, lstm_bhh,
                                  v_W, z_W, r_W, h_W, z_b, r_b, h_b,
                                  memory, O_t, O_prev, w_mlp_W, w_mlp_b, out3);
    // 2: LSTM gates [B,768] fp16, K=512
    k_mma<5><<<dim3(6, B_/128), 256, SMEM_TOTAL>>>(
        pX, pWigo, pbigo, pGates, nullptr, nullptr, nullptr,
        B_, 768, 512);
    // 3: LSTM activations -> OTP (fp16)
    k_lstm_act<<<(B_*128)/256, 256>>>();
    // 4: QK = OTP @ Wqk^T + bqk  [B,256] fp16   <-- ncu capture slot
    k_mma<5><<<dim3(2, B_/128), 256, SMEM_TOTAL>>>(
        pOTP, pWqk, pbqk, pQK, nullptr, nullptr, nullptr,
        B_, 256, 256);
    // 5: attention v2 (fp16 memory, warp per row) -> WM
    k_attn<<<B_/8, 256>>>();
    // 6: V GEMM -> OUP (fp16) + out0/out2/mem slot 9 (fp32)
    k_mma<2><<<dim3(2, B_/128), 256, SMEM_TOTAL>>>(
        pWM, pWv, v_b, pOUP, out0, out_mem, out2,
        B_, 256, 256);
    // 7: OZH = O_up @ Wozh^T + bozh  [B,768] fp16
    k_mma<5><<<dim3(6, B_/128), 256, SMEM_TOTAL>>>(
        pOUP, pWozh, pbozh, pOZH, nullptr, nullptr, nullptr,
        B_, 768, 256);
    // 8: fused GRU v3
    k_gru<<<M2_/64, 256, GRU_SMEM>>>(pMEMh, pWzrm, pWhm, pOZH, out_mem);
}